// round 1
// baseline (speedup 1.0000x reference)
#include <cuda_runtime.h>
#include <math.h>

#define BB   32
#define SEQ  257
#define DIM  1024
#define NH   16
#define HD   64
#define NEXP 8
#define RNK  16
#define GHID 256
#define BSQ  (BB*SEQ)          /* 8224 tokens */
#define QSCALE 0.125f

/* ---------------- scratch (device globals; no allocations) ---------------- */
static __device__ float g_q  [(size_t)BSQ*DIM];
static __device__ float g_k  [(size_t)BSQ*DIM];
static __device__ float g_v  [(size_t)BSQ*DIM];
static __device__ float g_ctx[(size_t)BSQ*DIM];
static __device__ float g_sc [(size_t)BB*NH*SEQ*SEQ];   /* attention scores */
static __device__ float g_xv [(size_t)BSQ*32];
static __device__ float g_gates[BB*2];
static __device__ int   g_idx  [BB*2];

/* ---------------- gating: pooled mean -> MLP -> top2 -> softmax ----------- */
__global__ void gating_kernel(const float* __restrict__ x,
                              const float* __restrict__ gw1, const float* __restrict__ gb1,
                              const float* __restrict__ gw2, const float* __restrict__ gb2)
{
    int b = blockIdx.x;
    __shared__ float pooled[DIM];
    __shared__ float h[GHID];
    __shared__ float logits[NEXP];
    int tid = threadIdx.x;                 /* 256 threads */
    for (int d = tid; d < DIM; d += 256) {
        float s = 0.f;
        const float* xp = x + (size_t)b*SEQ*DIM + d;
        for (int t = 0; t < SEQ; t++) s += xp[(size_t)t*DIM];
        pooled[d] = s * (1.0f/SEQ);
    }
    __syncthreads();
    {
        float a = gb1[tid];
        const float* w = gw1 + (size_t)tid*DIM;
        #pragma unroll 4
        for (int d = 0; d < DIM; d++) a += pooled[d]*w[d];
        h[tid] = fmaxf(a, 0.f);
    }
    __syncthreads();
    if (tid < NEXP) {
        float a = gb2[tid];
        const float* w = gw2 + tid*GHID;
        for (int d = 0; d < GHID; d++) a += h[d]*w[d];
        logits[tid] = a;
    }
    __syncthreads();
    if (tid == 0) {
        int i0 = 0;
        for (int e = 1; e < NEXP; e++) if (logits[e] > logits[i0]) i0 = e;
        int i1 = -1;
        for (int e = 0; e < NEXP; e++) {
            if (e == i0) continue;
            if (i1 < 0 || logits[e] > logits[i1]) i1 = e;
        }
        float v0 = logits[i0], v1 = logits[i1];
        float e0 = expf(v0 - v0), e1 = expf(v1 - v0);
        float inv = 1.f/(e0 + e1);
        g_gates[b*2]   = e0*inv;
        g_gates[b*2+1] = e1*inv;
        g_idx[b*2]   = i0;
        g_idx[b*2+1] = i1;
    }
}

/* ---------------- main GEMM: Y = X @ W^T + bias (NT, fp32) ---------------- */
/* 128x128 tile, BK=16, 256 threads, 8x8 micro-tile.
   out_code: 0->g_q 1->g_k 2->g_v 3->Yout.  Xin==nullptr -> g_ctx           */
__global__ void gemm_kernel(const float* __restrict__ Xin, const float* __restrict__ W,
                            const float* __restrict__ bias, float* __restrict__ Yout,
                            int out_code)
{
    const float* X = Xin ? Xin : g_ctx;
    float* Y = (out_code==0) ? g_q : (out_code==1) ? g_k : (out_code==2) ? g_v : Yout;

    __shared__ float As[16][128];
    __shared__ float Bs[16][128];

    int tid = threadIdx.x;
    int m0 = blockIdx.y * 128, n0 = blockIdx.x * 128;
    int tx = tid & 15, ty = tid >> 4;
    int arow = tid >> 2;
    int ac4  = (tid & 3) * 4;

    float acc[8][8];
    #pragma unroll
    for (int i = 0; i < 8; i++)
        #pragma unroll
        for (int j = 0; j < 8; j++) acc[i][j] = 0.f;

    for (int k0 = 0; k0 < DIM; k0 += 16) {
        #pragma unroll
        for (int half = 0; half < 2; half++) {
            int row = arow + half*64;
            int m = m0 + row;
            float4 va = make_float4(0.f,0.f,0.f,0.f);
            if (m < BSQ) va = *(const float4*)(X + (size_t)m*DIM + k0 + ac4);
            As[ac4+0][row]=va.x; As[ac4+1][row]=va.y; As[ac4+2][row]=va.z; As[ac4+3][row]=va.w;
            int n = n0 + row;
            float4 vb = *(const float4*)(W + (size_t)n*DIM + k0 + ac4);
            Bs[ac4+0][row]=vb.x; Bs[ac4+1][row]=vb.y; Bs[ac4+2][row]=vb.z; Bs[ac4+3][row]=vb.w;
        }
        __syncthreads();
        #pragma unroll
        for (int kk = 0; kk < 16; kk++) {
            float4 a0 = *(float4*)&As[kk][ty*8];
            float4 a1 = *(float4*)&As[kk][ty*8+4];
            float4 b0 = *(float4*)&Bs[kk][tx*8];
            float4 b1 = *(float4*)&Bs[kk][tx*8+4];
            float a[8] = {a0.x,a0.y,a0.z,a0.w,a1.x,a1.y,a1.z,a1.w};
            float bb[8]= {b0.x,b0.y,b0.z,b0.w,b1.x,b1.y,b1.z,b1.w};
            #pragma unroll
            for (int i = 0; i < 8; i++)
                #pragma unroll
                for (int j = 0; j < 8; j++)
                    acc[i][j] += a[i]*bb[j];
        }
        __syncthreads();
    }

    float bj[8];
    #pragma unroll
    for (int j = 0; j < 8; j++) bj[j] = bias[n0 + tx*8 + j];
    #pragma unroll
    for (int i = 0; i < 8; i++) {
        int m = m0 + ty*8 + i;
        if (m >= BSQ) break;
        float4 o0 = make_float4(acc[i][0]+bj[0], acc[i][1]+bj[1], acc[i][2]+bj[2], acc[i][3]+bj[3]);
        float4 o1 = make_float4(acc[i][4]+bj[4], acc[i][5]+bj[5], acc[i][6]+bj[6], acc[i][7]+bj[7]);
        *(float4*)(Y + (size_t)m*DIM + n0 + tx*8)     = o0;
        *(float4*)(Y + (size_t)m*DIM + n0 + tx*8 + 4) = o1;
    }
}

/* ---------------- xv: rank-32 projection with gate*S folded in ------------ */
/* grid (ceil(S/16), B), 256 threads (8 warps). warp computes 2 tokens x 32 j */
__global__ void xv_kernel(const float* __restrict__ Xin,
                          const float* __restrict__ Vm, const float* __restrict__ Sm)
{
    const float* X = Xin ? Xin : g_ctx;
    int b = blockIdx.y;
    int s0 = blockIdx.x * 16;
    int warp = threadIdx.x >> 5, lane = threadIdx.x & 31;
    int i0 = g_idx[b*2], i1 = g_idx[b*2+1];
    float gg0 = g_gates[b*2], gg1 = g_gates[b*2+1];

    for (int p = 0; p < 64; p++) {
        int pid = warp*64 + p;
        int tl  = pid >> 5;
        int j   = pid & 31;
        int t   = s0 + tl;
        if (t >= SEQ) continue;               /* warp-uniform */
        int e   = (j < 16) ? i0 : i1;
        float g = (j < 16) ? gg0 : gg1;
        int r   = j & 15;
        const float* vrow = Vm + ((size_t)e*RNK + r)*DIM;
        const float* xrow = X + (size_t)(b*SEQ + t)*DIM;
        float acc = 0.f;
        #pragma unroll 8
        for (int d = lane; d < DIM; d += 32) acc += xrow[d]*vrow[d];
        #pragma unroll
        for (int off = 16; off > 0; off >>= 1)
            acc += __shfl_xor_sync(0xffffffffu, acc, off);
        if (lane == 0)
            g_xv[(size_t)(b*SEQ + t)*32 + j] = acc * g * Sm[e*RNK + r];
    }
}

/* ---------------- add rank-32 expansion:  Y = (Y + xv@Uc^T) * scale ------- */
/* grid (ceil(S/64), B), 256 threads.  code: 0..2 -> g_q/g_k/g_v, 3 -> Yext  */
__global__ void add_kernel(float* __restrict__ Yext, const float* __restrict__ U,
                           float scale, int code)
{
    float* Y = (code==0) ? g_q : (code==1) ? g_k : (code==2) ? g_v : Yext;
    int b = blockIdx.y;
    int s0 = blockIdx.x * 64;
    __shared__ float xvs[64*32];
    int tid = threadIdx.x;
    int i0 = g_idx[b*2], i1 = g_idx[b*2+1];

    #pragma unroll
    for (int i = 0; i < 2; i++) {
        int f = tid + 256*i;          /* float4 index 0..511 */
        int t = f >> 3;
        int j4 = (f & 7) * 4;
        float4 v = make_float4(0.f,0.f,0.f,0.f);
        if (s0 + t < SEQ) v = *(const float4*)&g_xv[(size_t)(b*SEQ + s0 + t)*32 + j4];
        *(float4*)&xvs[t*32 + j4] = v;
    }
    __syncthreads();

    int nt = SEQ - s0; if (nt > 64) nt = 64;
    for (int gblk = 0; gblk < 4; gblk++) {
        int o = tid + gblk*256;
        float u[32];
        const float* u0 = U + ((size_t)i0*DIM + o)*RNK;
        const float* u1 = U + ((size_t)i1*DIM + o)*RNK;
        #pragma unroll
        for (int r = 0; r < 16; r++) { u[r] = u0[r]; u[16+r] = u1[r]; }
        for (int t = 0; t < nt; t++) {
            float a = 0.f;
            #pragma unroll
            for (int j = 0; j < 32; j++) a += xvs[t*32 + j]*u[j];
            size_t yi = (size_t)(b*SEQ + s0 + t)*DIM + o;
            Y[yi] = (Y[yi] + a) * scale;
        }
    }
}

/* ---------------- attention pass 1: scores = Q @ K^T ---------------------- */
/* grid (B*H, 5, 5), 64 threads, 64x64 tile, 8x8 micro                       */
__global__ void qk_kernel()
{
    int bh = blockIdx.x;
    int mt = blockIdx.y, nt = blockIdx.z;
    int b = bh >> 4, h = bh & 15;
    __shared__ float Qs[64][68];    /* [d][m] */
    __shared__ float Ks[64][68];    /* [d][n] */
    int tid = threadIdx.x;

    #pragma unroll
    for (int i = 0; i < 16; i++) {
        int f = tid + 64*i;            /* 0..1023 float4 slots */
        int row = f >> 4;
        int d4 = (f & 15) * 4;
        int sm = mt*64 + row;
        float4 vq = make_float4(0.f,0.f,0.f,0.f);
        if (sm < SEQ) vq = *(const float4*)(g_q + (size_t)(b*SEQ+sm)*DIM + h*HD + d4);
        Qs[d4+0][row]=vq.x; Qs[d4+1][row]=vq.y; Qs[d4+2][row]=vq.z; Qs[d4+3][row]=vq.w;
        int sn = nt*64 + row;
        float4 vk = make_float4(0.f,0.f,0.f,0.f);
        if (sn < SEQ) vk = *(const float4*)(g_k + (size_t)(b*SEQ+sn)*DIM + h*HD + d4);
        Ks[d4+0][row]=vk.x; Ks[d4+1][row]=vk.y; Ks[d4+2][row]=vk.z; Ks[d4+3][row]=vk.w;
    }
    __syncthreads();

    int tx = tid & 7, ty = tid >> 3;
    float acc[8][8];
    #pragma unroll
    for (int i = 0; i < 8; i++)
        #pragma unroll
        for (int j = 0; j < 8; j++) acc[i][j] = 0.f;

    #pragma unroll 4
    for (int d = 0; d < HD; d++) {
        float4 a0 = *(float4*)&Qs[d][ty*8];
        float4 a1 = *(float4*)&Qs[d][ty*8+4];
        float4 b0 = *(float4*)&Ks[d][tx*8];
        float4 b1 = *(float4*)&Ks[d][tx*8+4];
        float a[8] = {a0.x,a0.y,a0.z,a0.w,a1.x,a1.y,a1.z,a1.w};
        float bb[8]= {b0.x,b0.y,b0.z,b0.w,b1.x,b1.y,b1.z,b1.w};
        #pragma unroll
        for (int i = 0; i < 8; i++)
            #pragma unroll
            for (int j = 0; j < 8; j++)
                acc[i][j] += a[i]*bb[j];
    }

    size_t base = (size_t)bh*SEQ*SEQ;
    #pragma unroll
    for (int i = 0; i < 8; i++) {
        int m = mt*64 + ty*8 + i;
        if (m >= SEQ) break;
        #pragma unroll
        for (int j = 0; j < 8; j++) {
            int n = nt*64 + tx*8 + j;
            if (n < SEQ) g_sc[base + (size_t)m*SEQ + n] = acc[i][j];
        }
    }
}

/* ---------------- attention pass 2: row softmax --------------------------- */
__global__ void softmax_kernel()
{
    int row = blockIdx.x*8 + (threadIdx.x >> 5);
    int lane = threadIdx.x & 31;
    if (row >= BB*NH*SEQ) return;
    int bh = row / SEQ, m = row % SEQ;
    float* p = g_sc + (size_t)bh*SEQ*SEQ + (size_t)m*SEQ;

    float v[9];
    float mx = -1e30f;
    #pragma unroll
    for (int i = 0; i < 9; i++) {
        int t = lane + 32*i;
        v[i] = (t < SEQ) ? p[t] : -1e30f;
        mx = fmaxf(mx, v[i]);
    }
    #pragma unroll
    for (int off = 16; off > 0; off >>= 1)
        mx = fmaxf(mx, __shfl_xor_sync(0xffffffffu, mx, off));
    float sum = 0.f;
    #pragma unroll
    for (int i = 0; i < 9; i++) {
        int t = lane + 32*i;
        v[i] = (t < SEQ) ? expf(v[i]-mx) : 0.f;
        sum += v[i];
    }
    #pragma unroll
    for (int off = 16; off > 0; off >>= 1)
        sum += __shfl_xor_sync(0xffffffffu, sum, off);
    float inv = 1.f/sum;
    #pragma unroll
    for (int i = 0; i < 9; i++) {
        int t = lane + 32*i;
        if (t < SEQ) p[t] = v[i]*inv;
    }
}

/* ---------------- attention pass 3: ctx = P @ V --------------------------- */
/* grid (5, B*H), 64 threads, 64(m) x 64(n=HD) tile, K loop over t in 32s    */
__global__ void pv_kernel()
{
    int mt = blockIdx.x;
    int bh = blockIdx.y;
    int b = bh >> 4, h = bh & 15;
    __shared__ float Ps[32][68];   /* [k][m] */
    __shared__ float Vs[32][64];   /* [k][n] */
    int tid = threadIdx.x;
    int tx = tid & 7, ty = tid >> 3;

    float acc[8][8];
    #pragma unroll
    for (int i = 0; i < 8; i++)
        #pragma unroll
        for (int j = 0; j < 8; j++) acc[i][j] = 0.f;

    for (int t0 = 0; t0 < SEQ; t0 += 32) {
        #pragma unroll
        for (int i = 0; i < 8; i++) {
            int f = tid + 64*i;          /* 0..511 */
            int row = f >> 3;            /* m 0..63 */
            int k4 = (f & 7) * 4;
            int m = mt*64 + row;
            float e0=0.f, e1=0.f, e2=0.f, e3=0.f;
            if (m < SEQ) {
                const float* pr = g_sc + (size_t)bh*SEQ*SEQ + (size_t)m*SEQ;
                int t = t0 + k4;
                if (t+3 < SEQ) { e0=pr[t]; e1=pr[t+1]; e2=pr[t+2]; e3=pr[t+3]; }
                else {
                    if (t   < SEQ) e0 = pr[t];
                    if (t+1 < SEQ) e1 = pr[t+1];
                    if (t+2 < SEQ) e2 = pr[t+2];
                    if (t+3 < SEQ) e3 = pr[t+3];
                }
            }
            Ps[k4+0][row]=e0; Ps[k4+1][row]=e1; Ps[k4+2][row]=e2; Ps[k4+3][row]=e3;
        }
        #pragma unroll
        for (int i = 0; i < 8; i++) {
            int f = tid + 64*i;
            int k = f >> 4;
            int n4 = (f & 15) * 4;
            int t = t0 + k;
            float4 v = make_float4(0.f,0.f,0.f,0.f);
            if (t < SEQ) v = *(const float4*)(g_v + (size_t)(b*SEQ+t)*DIM + h*HD + n4);
            *(float4*)&Vs[k][n4] = v;
        }
        __syncthreads();
        #pragma unroll 4
        for (int k = 0; k < 32; k++) {
            float4 a0 = *(float4*)&Ps[k][ty*8];
            float4 a1 = *(float4*)&Ps[k][ty*8+4];
            float4 b0 = *(float4*)&Vs[k][tx*8];
            float4 b1 = *(float4*)&Vs[k][tx*8+4];
            float a[8] = {a0.x,a0.y,a0.z,a0.w,a1.x,a1.y,a1.z,a1.w};
            float bb[8]= {b0.x,b0.y,b0.z,b0.w,b1.x,b1.y,b1.z,b1.w};
            #pragma unroll
            for (int i = 0; i < 8; i++)
                #pragma unroll
                for (int j = 0; j < 8; j++)
                    acc[i][j] += a[i]*bb[j];
        }
        __syncthreads();
    }

    #pragma unroll
    for (int i = 0; i < 8; i++) {
        int m = mt*64 + ty*8 + i;
        if (m >= SEQ) break;
        float* cp = g_ctx + (size_t)(b*SEQ+m)*DIM + h*HD + tx*8;
        *(float4*)cp       = make_float4(acc[i][0],acc[i][1],acc[i][2],acc[i][3]);
        *(float4*)(cp + 4) = make_float4(acc[i][4],acc[i][5],acc[i][6],acc[i][7]);
    }
}

/* ---------------- launch ---------------- */
extern "C" void kernel_launch(void* const* d_in, const int* in_sizes, int n_in,
                              void* d_out, int out_size)
{
    const float* x   = (const float*)d_in[0];
    const float* gw1 = (const float*)d_in[1];
    const float* gb1 = (const float*)d_in[2];
    const float* gw2 = (const float*)d_in[3];
    const float* gb2 = (const float*)d_in[4];
    const float* Wm[4] = {(const float*)d_in[5],  (const float*)d_in[10],
                          (const float*)d_in[15], (const float*)d_in[20]};
    const float* Uu[4] = {(const float*)d_in[6],  (const float*)d_in[11],
                          (const float*)d_in[16], (const float*)d_in[21]};
    const float* Ss[4] = {(const float*)d_in[7],  (const float*)d_in[12],
                          (const float*)d_in[17], (const float*)d_in[22]};
    const float* Vv[4] = {(const float*)d_in[8],  (const float*)d_in[13],
                          (const float*)d_in[18], (const float*)d_in[23]};
    const float* bb[4] = {(const float*)d_in[9],  (const float*)d_in[14],
                          (const float*)d_in[19], (const float*)d_in[24]};
    float* out = (float*)d_out;

    gating_kernel<<<BB, 256>>>(x, gw1, gb1, gw2, gb2);

    dim3 gg(8, 65);       /* N/128, ceil(8224/128) */
    dim3 gxv(17, BB);     /* ceil(257/16) */
    dim3 gadd(5, BB);     /* ceil(257/64) */

    for (int p = 0; p < 3; p++) {
        gemm_kernel<<<gg, 256>>>(x, Wm[p], bb[p], nullptr, p);
        xv_kernel<<<gxv, 256>>>(x, Vv[p], Ss[p]);
        add_kernel<<<gadd, 256>>>(nullptr, Uu[p], (p == 0) ? QSCALE : 1.0f, p);
    }

    qk_kernel<<<dim3(BB*NH, 5, 5), 64>>>();
    softmax_kernel<<<(BB*NH*SEQ + 7)/8, 256>>>();
    pv_kernel<<<dim3(5, BB*NH), 64>>>();

    gemm_kernel<<<gg, 256>>>(nullptr, Wm[3], bb[3], out, 3);
    xv_kernel<<<gxv, 256>>>(nullptr, Vv[3], Ss[3]);
    add_kernel<<<gadd, 256>>>(out, Uu[3], 1.0f, 3);
}

// round 3
// speedup vs baseline: 2.2196x; 2.2196x over previous
#include <cuda_runtime.h>
#include <cuda_bf16.h>
#include <cstdint>
#include <math.h>

#define BB   32
#define SEQ  257
#define DIM  1024
#define NH   16
#define HD   64
#define NEXP 8
#define RNK  16
#define GHID 256
#define BSQ  (BB*SEQ)          /* 8224 tokens */
#define QSCALE 0.125f

/* ---------------- scratch (device globals; no allocations) ---------------- */
static __device__ float g_q  [(size_t)BSQ*DIM];
static __device__ float g_k  [(size_t)BSQ*DIM];
static __device__ float g_v  [(size_t)BSQ*DIM];
static __device__ float g_ctx[(size_t)BSQ*DIM];
static __device__ float g_sc [(size_t)BB*NH*SEQ*SEQ];
static __device__ float g_xv [(size_t)BSQ*32];
static __device__ float g_gates[BB*2];
static __device__ int   g_idx  [BB*2];
static __device__ __nv_bfloat16 g_xh[(size_t)BSQ*DIM];
static __device__ __nv_bfloat16 g_xl[(size_t)BSQ*DIM];
static __device__ __nv_bfloat16 g_wh[(size_t)4*DIM*DIM];
static __device__ __nv_bfloat16 g_wl[(size_t)4*DIM*DIM];

/* ---------------- small PTX helpers ---------------- */
__device__ __forceinline__ uint32_t smem_u32(const void* p) {
    uint32_t a;
    asm("{ .reg .u64 t; cvta.to.shared.u64 t, %1; cvt.u32.u64 %0, t; }" : "=r"(a) : "l"(p));
    return a;
}
__device__ __forceinline__ void cp16(uint32_t dst, const void* src, int srcBytes) {
    asm volatile("cp.async.cg.shared.global [%0], [%1], 16, %2;"
                 :: "r"(dst), "l"(src), "r"(srcBytes) : "memory");
}
#define CP_COMMIT() asm volatile("cp.async.commit_group;" ::: "memory")
#define CP_WAIT0()  asm volatile("cp.async.wait_group 0;" ::: "memory")
#define CP_WAIT1()  asm volatile("cp.async.wait_group 1;" ::: "memory")

__device__ __forceinline__ void ldsm_x4(uint32_t& r0, uint32_t& r1, uint32_t& r2, uint32_t& r3,
                                        uint32_t addr) {
    asm volatile("ldmatrix.sync.aligned.m8n8.x4.shared.b16 {%0,%1,%2,%3}, [%4];"
                 : "=r"(r0), "=r"(r1), "=r"(r2), "=r"(r3) : "r"(addr));
}
__device__ __forceinline__ void mma_bf16(float* c, const uint32_t* a, uint32_t b0, uint32_t b1) {
    asm volatile("mma.sync.aligned.m16n8k16.row.col.f32.bf16.bf16.f32 "
                 "{%0,%1,%2,%3}, {%4,%5,%6,%7}, {%8,%9}, {%0,%1,%2,%3};"
                 : "+f"(c[0]), "+f"(c[1]), "+f"(c[2]), "+f"(c[3])
                 : "r"(a[0]), "r"(a[1]), "r"(a[2]), "r"(a[3]), "r"(b0), "r"(b1));
}

/* ---------------- gating ---------------- */
__global__ void gating_kernel(const float* __restrict__ x,
                              const float* __restrict__ gw1, const float* __restrict__ gb1,
                              const float* __restrict__ gw2, const float* __restrict__ gb2)
{
    int b = blockIdx.x;
    __shared__ float pooled[DIM];
    __shared__ float h[GHID];
    __shared__ float logits[NEXP];
    int tid = threadIdx.x;
    for (int d = tid; d < DIM; d += 256) {
        float s = 0.f;
        const float* xp = x + (size_t)b*SEQ*DIM + d;
        for (int t = 0; t < SEQ; t++) s += xp[(size_t)t*DIM];
        pooled[d] = s * (1.0f/SEQ);
    }
    __syncthreads();
    {
        float a = gb1[tid];
        const float* w = gw1 + (size_t)tid*DIM;
        #pragma unroll 4
        for (int d = 0; d < DIM; d++) a += pooled[d]*w[d];
        h[tid] = fmaxf(a, 0.f);
    }
    __syncthreads();
    if (tid < NEXP) {
        float a = gb2[tid];
        const float* w = gw2 + tid*GHID;
        for (int d = 0; d < GHID; d++) a += h[d]*w[d];
        logits[tid] = a;
    }
    __syncthreads();
    if (tid == 0) {
        int i0 = 0;
        for (int e = 1; e < NEXP; e++) if (logits[e] > logits[i0]) i0 = e;
        int i1 = -1;
        for (int e = 0; e < NEXP; e++) {
            if (e == i0) continue;
            if (i1 < 0 || logits[e] > logits[i1]) i1 = e;
        }
        float v0 = logits[i0], v1 = logits[i1];
        float e0 = expf(v0 - v0), e1 = expf(v1 - v0);
        float inv = 1.f/(e0 + e1);
        g_gates[b*2]   = e0*inv;
        g_gates[b*2+1] = e1*inv;
        g_idx[b*2]   = i0;
        g_idx[b*2+1] = i1;
    }
}

/* ---------------- fp32 -> (bf16 hi, bf16 lo) ---------------- */
__global__ void conv_kernel(const float* __restrict__ srcExt, int which, int n4)
{
    const float* s;
    __nv_bfloat16 *H, *L;
    if (which == 0)      { s = srcExt; H = g_xh; L = g_xl; }
    else if (which <= 4) { s = srcExt;
                           H = g_wh + (size_t)(which-1)*DIM*DIM;
                           L = g_wl + (size_t)(which-1)*DIM*DIM; }
    else                 { s = g_ctx; H = g_xh; L = g_xl; }
    int i = blockIdx.x*256 + threadIdx.x;
    if (i >= n4) return;
    float4 v = ((const float4*)s)[i];
    ushort4 hh, ll;
    __nv_bfloat16 t;
    t = __float2bfloat16(v.x); hh.x = __bfloat16_as_ushort(t);
    ll.x = __bfloat16_as_ushort(__float2bfloat16(v.x - __bfloat162float(t)));
    t = __float2bfloat16(v.y); hh.y = __bfloat16_as_ushort(t);
    ll.y = __bfloat16_as_ushort(__float2bfloat16(v.y - __bfloat162float(t)));
    t = __float2bfloat16(v.z); hh.z = __bfloat16_as_ushort(t);
    ll.z = __bfloat16_as_ushort(__float2bfloat16(v.z - __bfloat162float(t)));
    t = __float2bfloat16(v.w); hh.w = __bfloat16_as_ushort(t);
    ll.w = __bfloat16_as_ushort(__float2bfloat16(v.w - __bfloat162float(t)));
    ((ushort4*)H)[i] = hh;
    ((ushort4*)L)[i] = ll;
}

/* ---------------- HMMA split-bf16 GEMM: Y = X @ W^T + bias ---------------- */
/* 128x128 tile, BK=32, 256 threads (8 warps, 2x4), warp tile 64x32.
   smem per stage: 4 matrices (Ah,Al,Bh,Bl), each 128 rows x 32 bf16,
   row stride 40 bf16 (80 B) -> conflict-free ldmatrix. Double buffered.    */
#define MAT_BYTES (128*40*2)            /* 10240 */
#define STG_BYTES (4*MAT_BYTES)         /* 40960 */
#define MM_SMEM   (2*STG_BYTES)         /* 81920 */

__device__ __forceinline__ void mm_load_stage(uint32_t sb, int buf, int k0,
    const __nv_bfloat16* Ah, const __nv_bfloat16* Al,
    const __nv_bfloat16* Bh, const __nv_bfloat16* Bl,
    int m0, int n0, int tid)
{
    uint32_t base = sb + buf*STG_BYTES;
    const __nv_bfloat16* srcs[4] = {Ah, Al, Bh, Bl};
    #pragma unroll
    for (int i = 0; i < 8; i++) {
        int c = tid + 256*i;            /* 0..2047 */
        int mat = c >> 9;
        int cc  = c & 511;
        int row = cc >> 2;
        int col = (cc & 3) * 8;
        const __nv_bfloat16* p = srcs[mat];
        int grow = ((mat < 2) ? m0 : n0) + row;
        int ok = (mat >= 2) || (grow < BSQ);
        const void* src = p + ((size_t)(ok ? grow : 0))*DIM + k0 + col;
        uint32_t dst = base + mat*MAT_BYTES + (uint32_t)(row*40 + col)*2;
        cp16(dst, src, ok ? 16 : 0);
    }
}

__global__ void __launch_bounds__(256, 1) mm_kernel(int wcode, const float* __restrict__ bias,
                                                    float* __restrict__ Yext, int ycode)
{
    extern __shared__ __align__(128) char smem[];
    const __nv_bfloat16* Ah = g_xh;
    const __nv_bfloat16* Al = g_xl;
    const __nv_bfloat16* Bh = g_wh + (size_t)wcode*DIM*DIM;
    const __nv_bfloat16* Bl = g_wl + (size_t)wcode*DIM*DIM;
    float* Y = (ycode==0)?g_q:(ycode==1)?g_k:(ycode==2)?g_v:Yext;

    uint32_t sb = smem_u32(smem);
    int tid = threadIdx.x;
    int lane = tid & 31;
    int wid = tid >> 5;
    int warp_m = wid >> 2;              /* 0..1 */
    int warp_n = wid & 3;               /* 0..3 */
    int n0 = blockIdx.x*128, m0 = blockIdx.y*128;

    float acc[4][4][4];
    #pragma unroll
    for (int i = 0; i < 4; i++)
        #pragma unroll
        for (int j = 0; j < 4; j++)
            #pragma unroll
            for (int q = 0; q < 4; q++) acc[i][j][q] = 0.f;

    /* per-lane ldmatrix source addressing (within a matrix) */
    uint32_t aRow = (uint32_t)(warp_m*64 + (lane & 15));
    uint32_t aCol = (uint32_t)((lane >> 4) * 8);
    uint32_t bRowBase = (uint32_t)(warp_n*32 + (lane & 7) + ((lane >> 4) << 3));
    uint32_t bCol = (uint32_t)(((lane >> 3) & 1) * 8);

    mm_load_stage(sb, 0, 0, Ah, Al, Bh, Bl, m0, n0, tid);
    CP_COMMIT();

    const int NK = DIM/32;              /* 32 stages */
    for (int s = 0; s < NK; s++) {
        if (s + 1 < NK) {
            mm_load_stage(sb, (s+1)&1, (s+1)*32, Ah, Al, Bh, Bl, m0, n0, tid);
            CP_COMMIT();
            CP_WAIT1();
        } else {
            CP_WAIT0();
        }
        __syncthreads();

        uint32_t stg = sb + (s&1)*STG_BYTES;
        #pragma unroll
        for (int kk = 0; kk < 32; kk += 16) {
            uint32_t ah[4][4], al[4][4], bh[8], bl[8];
            #pragma unroll
            for (int i = 0; i < 4; i++) {
                uint32_t off = ((aRow + i*16)*40 + kk + aCol)*2;
                ldsm_x4(ah[i][0], ah[i][1], ah[i][2], ah[i][3], stg + 0*MAT_BYTES + off);
                ldsm_x4(al[i][0], al[i][1], al[i][2], al[i][3], stg + 1*MAT_BYTES + off);
            }
            #pragma unroll
            for (int g = 0; g < 2; g++) {
                uint32_t off = ((bRowBase + g*16)*40 + kk + bCol)*2;
                ldsm_x4(bh[g*4+0], bh[g*4+1], bh[g*4+2], bh[g*4+3], stg + 2*MAT_BYTES + off);
                ldsm_x4(bl[g*4+0], bl[g*4+1], bl[g*4+2], bl[g*4+3], stg + 3*MAT_BYTES + off);
            }
            #pragma unroll
            for (int i = 0; i < 4; i++) {
                #pragma unroll
                for (int j = 0; j < 4; j++) {
                    mma_bf16(acc[i][j], ah[i], bh[j*2], bh[j*2+1]);
                    mma_bf16(acc[i][j], ah[i], bl[j*2], bl[j*2+1]);
                    mma_bf16(acc[i][j], al[i], bh[j*2], bh[j*2+1]);
                }
            }
        }
        __syncthreads();
    }

    /* epilogue: add bias, store fp32 */
    #pragma unroll
    for (int j = 0; j < 4; j++) {
        int col = n0 + warp_n*32 + j*8 + (lane & 3)*2;
        float b0 = bias[col], b1 = bias[col+1];
        #pragma unroll
        for (int i = 0; i < 4; i++) {
            int r0 = m0 + warp_m*64 + i*16 + (lane >> 2);
            if (r0 < BSQ) {
                float2 o = make_float2(acc[i][j][0] + b0, acc[i][j][1] + b1);
                *(float2*)(Y + (size_t)r0*DIM + col) = o;
            }
            int r1 = r0 + 8;
            if (r1 < BSQ) {
                float2 o = make_float2(acc[i][j][2] + b0, acc[i][j][3] + b1);
                *(float2*)(Y + (size_t)r1*DIM + col) = o;
            }
        }
    }
}

/* ---------------- xv: rank-32 projection (gate*S folded at store) --------- */
__global__ void xv_kernel(const float* __restrict__ Xin,
                          const float* __restrict__ Vm, const float* __restrict__ Sm)
{
    const float* X = Xin ? Xin : g_ctx;
    int b = blockIdx.y;
    int t0 = blockIdx.x * 32;
    __shared__ float Xs[32][132];
    __shared__ float Vs[128][33];
    int tid = threadIdx.x;
    int i0 = g_idx[b*2], i1 = g_idx[b*2+1];

    int tj = (tid & 7) * 4;
    int tt = tid >> 3;
    float a0 = 0.f, a1 = 0.f, a2 = 0.f, a3 = 0.f;

    for (int kc = 0; kc < 8; kc++) {
        int k0 = kc * 128;
        #pragma unroll
        for (int i = 0; i < 4; i++) {
            int c = tid + 256*i;
            int row = c >> 5, k4 = (c & 31) * 4;
            float4 v = make_float4(0.f,0.f,0.f,0.f);
            if (t0 + row < SEQ)
                v = *(const float4*)(X + (size_t)(b*SEQ + t0 + row)*DIM + k0 + k4);
            *(float4*)&Xs[row][k4] = v;
        }
        #pragma unroll
        for (int i = 0; i < 4; i++) {
            int c = tid + 256*i;
            int j = c >> 5, k4 = (c & 31) * 4;
            int e = (j < 16) ? i0 : i1;
            int r = j & 15;
            float4 v = *(const float4*)(Vm + ((size_t)e*RNK + r)*DIM + k0 + k4);
            Vs[k4+0][j] = v.x; Vs[k4+1][j] = v.y; Vs[k4+2][j] = v.z; Vs[k4+3][j] = v.w;
        }
        __syncthreads();
        #pragma unroll 4
        for (int k = 0; k < 128; k++) {
            float x = Xs[tt][k];
            a0 += x * Vs[k][tj+0];
            a1 += x * Vs[k][tj+1];
            a2 += x * Vs[k][tj+2];
            a3 += x * Vs[k][tj+3];
        }
        __syncthreads();
    }
    int t = t0 + tt;
    if (t < SEQ) {
        float g0 = g_gates[b*2], g1 = g_gates[b*2+1];
        float accs[4] = {a0, a1, a2, a3};
        #pragma unroll
        for (int q = 0; q < 4; q++) {
            int j = tj + q;
            int e = (j < 16) ? i0 : i1;
            int r = j & 15;
            float sc = ((j < 16) ? g0 : g1) * Sm[e*RNK + r];
            g_xv[(size_t)(b*SEQ + t)*32 + j] = accs[q] * sc;
        }
    }
}

/* ---------------- add rank-32 expansion:  Y = (Y + xv@Uc^T) * scale ------- */
__global__ void add_kernel(float* __restrict__ Yext, const float* __restrict__ U,
                           float scale, int code)
{
    float* Y = (code==0)?g_q:(code==1)?g_k:(code==2)?g_v:Yext;
    int b = blockIdx.z;
    int t0 = blockIdx.x * 64;
    int o0 = blockIdx.y * 256;
    __shared__ float xvs[64][33];
    __shared__ float Us[32][260];
    int tid = threadIdx.x;
    int i0 = g_idx[b*2], i1 = g_idx[b*2+1];

    #pragma unroll
    for (int i = 0; i < 8; i++) {
        int c = tid + 256*i;
        int t = c >> 5, j = c & 31;
        float v = 0.f;
        if (t0 + t < SEQ) v = g_xv[(size_t)(b*SEQ + t0 + t)*32 + j];
        xvs[t][j] = v;
    }
    {
        int o = tid;
        #pragma unroll
        for (int hh = 0; hh < 2; hh++) {
            int e = hh ? i1 : i0;
            const float* up = U + ((size_t)e*DIM + o0 + o)*RNK;
            #pragma unroll
            for (int r = 0; r < 16; r++) Us[hh*16 + r][o] = up[r];
        }
    }
    __syncthreads();

    int tx = tid & 31, ty = tid >> 5;
    float acc[8][8];
    #pragma unroll
    for (int i = 0; i < 8; i++)
        #pragma unroll
        for (int j = 0; j < 8; j++) acc[i][j] = 0.f;

    #pragma unroll 4
    for (int j = 0; j < 32; j++) {
        float a[8];
        #pragma unroll
        for (int i = 0; i < 8; i++) a[i] = xvs[ty*8 + i][j];
        float4 b0 = *(float4*)&Us[j][tx*8];
        float4 b1 = *(float4*)&Us[j][tx*8 + 4];
        float bv[8] = {b0.x,b0.y,b0.z,b0.w,b1.x,b1.y,b1.z,b1.w};
        #pragma unroll
        for (int i = 0; i < 8; i++)
            #pragma unroll
            for (int q = 0; q < 8; q++)
                acc[i][q] += a[i]*bv[q];
    }

    #pragma unroll
    for (int i = 0; i < 8; i++) {
        int t = t0 + ty*8 + i;
        if (t >= SEQ) break;
        float* yp = Y + (size_t)(b*SEQ + t)*DIM + o0 + tx*8;
        float4 y0 = *(float4*)yp;
        float4 y1 = *(float4*)(yp + 4);
        y0.x = (y0.x + acc[i][0])*scale; y0.y = (y0.y + acc[i][1])*scale;
        y0.z = (y0.z + acc[i][2])*scale; y0.w = (y0.w + acc[i][3])*scale;
        y1.x = (y1.x + acc[i][4])*scale; y1.y = (y1.y + acc[i][5])*scale;
        y1.z = (y1.z + acc[i][6])*scale; y1.w = (y1.w + acc[i][7])*scale;
        *(float4*)yp = y0;
        *(float4*)(yp + 4) = y1;
    }
}

/* ---------------- attention pass 1: scores = Q @ K^T ---------------------- */
__global__ void qk_kernel()
{
    int bh = blockIdx.x;
    int mt = blockIdx.y, nt = blockIdx.z;
    int b = bh >> 4, h = bh & 15;
    __shared__ float Qs[64][68];
    __shared__ float Ks[64][68];
    int tid = threadIdx.x;

    #pragma unroll
    for (int i = 0; i < 16; i++) {
        int f = tid + 64*i;
        int row = f >> 4;
        int d4 = (f & 15) * 4;
        int sm = mt*64 + row;
        float4 vq = make_float4(0.f,0.f,0.f,0.f);
        if (sm < SEQ) vq = *(const float4*)(g_q + (size_t)(b*SEQ+sm)*DIM + h*HD + d4);
        Qs[d4+0][row]=vq.x; Qs[d4+1][row]=vq.y; Qs[d4+2][row]=vq.z; Qs[d4+3][row]=vq.w;
        int sn = nt*64 + row;
        float4 vk = make_float4(0.f,0.f,0.f,0.f);
        if (sn < SEQ) vk = *(const float4*)(g_k + (size_t)(b*SEQ+sn)*DIM + h*HD + d4);
        Ks[d4+0][row]=vk.x; Ks[d4+1][row]=vk.y; Ks[d4+2][row]=vk.z; Ks[d4+3][row]=vk.w;
    }
    __syncthreads();

    int tx = tid & 7, ty = tid >> 3;
    float acc[8][8];
    #pragma unroll
    for (int i = 0; i < 8; i++)
        #pragma unroll
        for (int j = 0; j < 8; j++) acc[i][j] = 0.f;

    #pragma unroll 4
    for (int d = 0; d < HD; d++) {
        float4 a0 = *(float4*)&Qs[d][ty*8];
        float4 a1 = *(float4*)&Qs[d][ty*8+4];
        float4 b0 = *(float4*)&Ks[d][tx*8];
        float4 b1 = *(float4*)&Ks[d][tx*8+4];
        float a[8] = {a0.x,a0.y,a0.z,a0.w,a1.x,a1.y,a1.z,a1.w};
        float bb[8]= {b0.x,b0.y,b0.z,b0.w,b1.x,b1.y,b1.z,b1.w};
        #pragma unroll
        for (int i = 0; i < 8; i++)
            #pragma unroll
            for (int j = 0; j < 8; j++)
                acc[i][j] += a[i]*bb[j];
    }

    size_t base = (size_t)bh*SEQ*SEQ;
    #pragma unroll
    for (int i = 0; i < 8; i++) {
        int m = mt*64 + ty*8 + i;
        if (m >= SEQ) break;
        #pragma unroll
        for (int j = 0; j < 8; j++) {
            int n = nt*64 + tx*8 + j;
            if (n < SEQ) g_sc[base + (size_t)m*SEQ + n] = acc[i][j];
        }
    }
}

/* ---------------- attention pass 2: row softmax --------------------------- */
__global__ void softmax_kernel()
{
    int row = blockIdx.x*8 + (threadIdx.x >> 5);
    int lane = threadIdx.x & 31;
    if (row >= BB*NH*SEQ) return;
    int bh = row / SEQ, m = row % SEQ;
    float* p = g_sc + (size_t)bh*SEQ*SEQ + (size_t)m*SEQ;

    float v[9];
    float mx = -1e30f;
    #pragma unroll
    for (int i = 0; i < 9; i++) {
        int t = lane + 32*i;
        v[i] = (t < SEQ) ? p[t] : -1e30f;
        mx = fmaxf(mx, v[i]);
    }
    #pragma unroll
    for (int off = 16; off > 0; off >>= 1)
        mx = fmaxf(mx, __shfl_xor_sync(0xffffffffu, mx, off));
    float sum = 0.f;
    #pragma unroll
    for (int i = 0; i < 9; i++) {
        int t = lane + 32*i;
        v[i] = (t < SEQ) ? expf(v[i]-mx) : 0.f;
        sum += v[i];
    }
    #pragma unroll
    for (int off = 16; off > 0; off >>= 1)
        sum += __shfl_xor_sync(0xffffffffu, sum, off);
    float inv = 1.f/sum;
    #pragma unroll
    for (int i = 0; i < 9; i++) {
        int t = lane + 32*i;
        if (t < SEQ) p[t] = v[i]*inv;
    }
}

/* ---------------- attention pass 3: ctx = P @ V --------------------------- */
__global__ void pv_kernel()
{
    int mt = blockIdx.x;
    int bh = blockIdx.y;
    int b = bh >> 4, h = bh & 15;
    __shared__ float Ps[32][68];
    __shared__ float Vsh[32][64];
    int tid = threadIdx.x;
    int tx = tid & 7, ty = tid >> 3;

    float acc[8][8];
    #pragma unroll
    for (int i = 0; i < 8; i++)
        #pragma unroll
        for (int j = 0; j < 8; j++) acc[i][j] = 0.f;

    for (int t0 = 0; t0 < SEQ; t0 += 32) {
        #pragma unroll
        for (int i = 0; i < 8; i++) {
            int f = tid + 64*i;
            int row = f >> 3;
            int k4 = (f & 7) * 4;
            int m = mt*64 + row;
            float e0=0.f, e1=0.f, e2=0.f, e3=0.f;
            if (m < SEQ) {
                const float* pr = g_sc + (size_t)bh*SEQ*SEQ + (size_t)m*SEQ;
                int t = t0 + k4;
                if (t+3 < SEQ) { e0=pr[t]; e1=pr[t+1]; e2=pr[t+2]; e3=pr[t+3]; }
                else {
                    if (t   < SEQ) e0 = pr[t];
                    if (t+1 < SEQ) e1 = pr[t+1];
                    if (t+2 < SEQ) e2 = pr[t+2];
                    if (t+3 < SEQ) e3 = pr[t+3];
                }
            }
            Ps[k4+0][row]=e0; Ps[k4+1][row]=e1; Ps[k4+2][row]=e2; Ps[k4+3][row]=e3;
        }
        #pragma unroll
        for (int i = 0; i < 8; i++) {
            int f = tid + 64*i;
            int k = f >> 4;
            int n4 = (f & 15) * 4;
            int t = t0 + k;
            float4 v = make_float4(0.f,0.f,0.f,0.f);
            if (t < SEQ) v = *(const float4*)(g_v + (size_t)(b*SEQ+t)*DIM + h*HD + n4);
            *(float4*)&Vsh[k][n4] = v;
        }
        __syncthreads();
        #pragma unroll 4
        for (int k = 0; k < 32; k++) {
            float4 a0 = *(float4*)&Ps[k][ty*8];
            float4 a1 = *(float4*)&Ps[k][ty*8+4];
            float4 b0 = *(float4*)&Vsh[k][tx*8];
            float4 b1 = *(float4*)&Vsh[k][tx*8+4];
            float a[8] = {a0.x,a0.y,a0.z,a0.w,a1.x,a1.y,a1.z,a1.w};
            float bb[8]= {b0.x,b0.y,b0.z,b0.w,b1.x,b1.y,b1.z,b1.w};
            #pragma unroll
            for (int i = 0; i < 8; i++)
                #pragma unroll
                for (int j = 0; j < 8; j++)
                    acc[i][j] += a[i]*bb[j];
        }
        __syncthreads();
    }

    #pragma unroll
    for (int i = 0; i < 8; i++) {
        int m = mt*64 + ty*8 + i;
        if (m >= SEQ) break;
        float* cp = g_ctx + (size_t)(b*SEQ+m)*DIM + h*HD + tx*8;
        *(float4*)cp       = make_float4(acc[i][0],acc[i][1],acc[i][2],acc[i][3]);
        *(float4*)(cp + 4) = make_float4(acc[i][4],acc[i][5],acc[i][6],acc[i][7]);
    }
}

/* ---------------- launch ---------------- */
extern "C" void kernel_launch(void* const* d_in, const int* in_sizes, int n_in,
                              void* d_out, int out_size)
{
    const float* x   = (const float*)d_in[0];
    const float* gw1 = (const float*)d_in[1];
    const float* gb1 = (const float*)d_in[2];
    const float* gw2 = (const float*)d_in[3];
    const float* gb2 = (const float*)d_in[4];
    const float* Wm[4] = {(const float*)d_in[5],  (const float*)d_in[10],
                          (const float*)d_in[15], (const float*)d_in[20]};
    const float* Uu[4] = {(const float*)d_in[6],  (const float*)d_in[11],
                          (const float*)d_in[16], (const float*)d_in[21]};
    const float* Ss[4] = {(const float*)d_in[7],  (const float*)d_in[12],
                          (const float*)d_in[17], (const float*)d_in[22]};
    const float* Vv[4] = {(const float*)d_in[8],  (const float*)d_in[13],
                          (const float*)d_in[18], (const float*)d_in[23]};
    const float* bbv[4] = {(const float*)d_in[9],  (const float*)d_in[14],
                           (const float*)d_in[19], (const float*)d_in[24]};
    float* out = (float*)d_out;

    cudaFuncSetAttribute(mm_kernel, cudaFuncAttributeMaxDynamicSharedMemorySize, MM_SMEM);

    gating_kernel<<<BB, 256>>>(x, gw1, gb1, gw2, gb2);

    int nx4 = BSQ*DIM/4;
    int nw4 = DIM*DIM/4;
    conv_kernel<<<(nx4 + 255)/256, 256>>>(x, 0, nx4);
    for (int p = 0; p < 4; p++)
        conv_kernel<<<(nw4 + 255)/256, 256>>>(Wm[p], p + 1, nw4);

    dim3 gmm(8, 65);
    dim3 gxv(9, BB);
    dim3 gadd(5, 4, BB);

    for (int p = 0; p < 3; p++) {
        mm_kernel<<<gmm, 256, MM_SMEM>>>(p, bbv[p], nullptr, p);
        xv_kernel<<<gxv, 256>>>(x, Vv[p], Ss[p]);
        add_kernel<<<gadd, 256>>>(nullptr, Uu[p], (p == 0) ? QSCALE : 1.0f, p);
    }

    qk_kernel<<<dim3(BB*NH, 5, 5), 64>>>();
    softmax_kernel<<<(BB*NH*SEQ + 7)/8, 256>>>();
    pv_kernel<<<dim3(5, BB*NH), 64>>>();

    conv_kernel<<<(nx4 + 255)/256, 256>>>(nullptr, 5, nx4);
    mm_kernel<<<gmm, 256, MM_SMEM>>>(3, bbv[3], out, 3);
    xv_kernel<<<gxv, 256>>>(nullptr, Vv[3], Ss[3]);
    add_kernel<<<gadd, 256>>>(out, Uu[3], 1.0f, 3);
}

// round 5
// speedup vs baseline: 2.7172x; 1.2242x over previous
#include <cuda_runtime.h>
#include <cuda_bf16.h>
#include <cstdint>
#include <math.h>

#define BB   32
#define SEQ  257
#define SEQP 320
#define DIM  1024
#define NH   16
#define HD   64
#define NEXP 8
#define RNK  16
#define GHID 256
#define BSQ  (BB*SEQ)          /* 8224 tokens */
#define QSCALE 0.125f

/* ---------------- scratch (device globals; no allocations) ---------------- */
static __device__ float g_q  [(size_t)BSQ*DIM];
static __device__ float g_k  [(size_t)BSQ*DIM];
static __device__ float g_v  [(size_t)BSQ*DIM];
static __device__ float g_ctx[(size_t)BSQ*DIM];
static __device__ float g_sc [(size_t)BB*NH*SEQ*SEQP];   /* padded row stride */
static __device__ float g_xv [(size_t)BSQ*32];
static __device__ float g_gates[BB*2];
static __device__ int   g_idx  [BB*2];
static __device__ __align__(16) __nv_bfloat16 g_xh[(size_t)BSQ*DIM];
static __device__ __align__(16) __nv_bfloat16 g_xl[(size_t)BSQ*DIM];
static __device__ __align__(16) __nv_bfloat16 g_wh[(size_t)4*DIM*DIM];
static __device__ __align__(16) __nv_bfloat16 g_wl[(size_t)4*DIM*DIM];
/* attention bf16 operands: [bh][s(0..SEQP)][64]; pad rows stay .bss-zero */
static __device__ __align__(16) __nv_bfloat16 g_aqh[(size_t)BB*NH*SEQP*HD];
static __device__ __align__(16) __nv_bfloat16 g_aql[(size_t)BB*NH*SEQP*HD];
static __device__ __align__(16) __nv_bfloat16 g_akh[(size_t)BB*NH*SEQP*HD];
static __device__ __align__(16) __nv_bfloat16 g_akl[(size_t)BB*NH*SEQP*HD];
static __device__ __align__(16) __nv_bfloat16 g_avh[(size_t)BB*NH*SEQP*HD];
static __device__ __align__(16) __nv_bfloat16 g_avl[(size_t)BB*NH*SEQP*HD];
/* probabilities hi/lo: [bh][m<257][t<SEQP] */
static __device__ __align__(16) __nv_bfloat16 g_ph[(size_t)BB*NH*SEQ*SEQP];
static __device__ __align__(16) __nv_bfloat16 g_pl[(size_t)BB*NH*SEQ*SEQP];

/* ---------------- small PTX helpers ---------------- */
__device__ __forceinline__ uint32_t smem_u32(const void* p) {
    uint32_t a;
    asm("{ .reg .u64 t; cvta.to.shared.u64 t, %1; cvt.u32.u64 %0, t; }" : "=r"(a) : "l"(p));
    return a;
}
__device__ __forceinline__ void cp16(uint32_t dst, const void* src, int srcBytes) {
    asm volatile("cp.async.cg.shared.global [%0], [%1], 16, %2;"
                 :: "r"(dst), "l"(src), "r"(srcBytes) : "memory");
}
#define CP_COMMIT() asm volatile("cp.async.commit_group;" ::: "memory")
#define CP_WAIT0()  asm volatile("cp.async.wait_group 0;" ::: "memory")
#define CP_WAIT1()  asm volatile("cp.async.wait_group 1;" ::: "memory")

__device__ __forceinline__ void ldsm_x4(uint32_t& r0, uint32_t& r1, uint32_t& r2, uint32_t& r3,
                                        uint32_t addr) {
    asm volatile("ldmatrix.sync.aligned.m8n8.x4.shared.b16 {%0,%1,%2,%3}, [%4];"
                 : "=r"(r0), "=r"(r1), "=r"(r2), "=r"(r3) : "r"(addr));
}
__device__ __forceinline__ void ldsm_x4_t(uint32_t& r0, uint32_t& r1, uint32_t& r2, uint32_t& r3,
                                          uint32_t addr) {
    asm volatile("ldmatrix.sync.aligned.m8n8.x4.trans.shared.b16 {%0,%1,%2,%3}, [%4];"
                 : "=r"(r0), "=r"(r1), "=r"(r2), "=r"(r3) : "r"(addr));
}
__device__ __forceinline__ void mma_bf16(float* c, const uint32_t* a, uint32_t b0, uint32_t b1) {
    asm volatile("mma.sync.aligned.m16n8k16.row.col.f32.bf16.bf16.f32 "
                 "{%0,%1,%2,%3}, {%4,%5,%6,%7}, {%8,%9}, {%0,%1,%2,%3};"
                 : "+f"(c[0]), "+f"(c[1]), "+f"(c[2]), "+f"(c[3])
                 : "r"(a[0]), "r"(a[1]), "r"(a[2]), "r"(a[3]), "r"(b0), "r"(b1));
}

/* ---------------- gating ---------------- */
__global__ void gating_kernel(const float* __restrict__ x,
                              const float* __restrict__ gw1, const float* __restrict__ gb1,
                              const float* __restrict__ gw2, const float* __restrict__ gb2)
{
    int b = blockIdx.x;
    __shared__ float pooled[DIM];
    __shared__ float h[GHID];
    __shared__ float logits[NEXP];
    int tid = threadIdx.x;
    for (int d = tid; d < DIM; d += 256) {
        float s = 0.f;
        const float* xp = x + (size_t)b*SEQ*DIM + d;
        for (int t = 0; t < SEQ; t++) s += xp[(size_t)t*DIM];
        pooled[d] = s * (1.0f/SEQ);
    }
    __syncthreads();
    {
        float a = gb1[tid];
        const float* w = gw1 + (size_t)tid*DIM;
        #pragma unroll 4
        for (int d = 0; d < DIM; d++) a += pooled[d]*w[d];
        h[tid] = fmaxf(a, 0.f);
    }
    __syncthreads();
    if (tid < NEXP) {
        float a = gb2[tid];
        const float* w = gw2 + tid*GHID;
        for (int d = 0; d < GHID; d++) a += h[d]*w[d];
        logits[tid] = a;
    }
    __syncthreads();
    if (tid == 0) {
        int i0 = 0;
        for (int e = 1; e < NEXP; e++) if (logits[e] > logits[i0]) i0 = e;
        int i1 = -1;
        for (int e = 0; e < NEXP; e++) {
            if (e == i0) continue;
            if (i1 < 0 || logits[e] > logits[i1]) i1 = e;
        }
        float v0 = logits[i0], v1 = logits[i1];
        float e0 = expf(v0 - v0), e1 = expf(v1 - v0);
        float inv = 1.f/(e0 + e1);
        g_gates[b*2]   = e0*inv;
        g_gates[b*2+1] = e1*inv;
        g_idx[b*2]   = i0;
        g_idx[b*2+1] = i1;
    }
}

/* ---------------- fp32 -> (bf16 hi, bf16 lo) ---------------- */
__global__ void conv_kernel(const float* __restrict__ srcExt, int which, int n4)
{
    const float* s;
    __nv_bfloat16 *H, *L;
    if (which == 0)      { s = srcExt; H = g_xh; L = g_xl; }
    else if (which <= 4) { s = srcExt;
                           H = g_wh + (size_t)(which-1)*DIM*DIM;
                           L = g_wl + (size_t)(which-1)*DIM*DIM; }
    else                 { s = g_ctx; H = g_xh; L = g_xl; }
    int i = blockIdx.x*256 + threadIdx.x;
    if (i >= n4) return;
    float4 v = ((const float4*)s)[i];
    ushort4 hh, ll;
    __nv_bfloat16 t;
    t = __float2bfloat16(v.x); hh.x = __bfloat16_as_ushort(t);
    ll.x = __bfloat16_as_ushort(__float2bfloat16(v.x - __bfloat162float(t)));
    t = __float2bfloat16(v.y); hh.y = __bfloat16_as_ushort(t);
    ll.y = __bfloat16_as_ushort(__float2bfloat16(v.y - __bfloat162float(t)));
    t = __float2bfloat16(v.z); hh.z = __bfloat16_as_ushort(t);
    ll.z = __bfloat16_as_ushort(__float2bfloat16(v.z - __bfloat162float(t)));
    t = __float2bfloat16(v.w); hh.w = __bfloat16_as_ushort(t);
    ll.w = __bfloat16_as_ushort(__float2bfloat16(v.w - __bfloat162float(t)));
    ((ushort4*)H)[i] = hh;
    ((ushort4*)L)[i] = ll;
}

/* ---------------- HMMA split-bf16 GEMM: Y = X @ W^T + bias ---------------- */
#define MAT_BYTES (128*40*2)            /* 10240 */
#define STG_BYTES (4*MAT_BYTES)         /* 40960 */
#define MM_SMEM   (2*STG_BYTES)         /* 81920 */

__device__ __forceinline__ void mm_load_stage(uint32_t sb, int buf, int k0,
    const __nv_bfloat16* Ah, const __nv_bfloat16* Al,
    const __nv_bfloat16* Bh, const __nv_bfloat16* Bl,
    int m0, int n0, int tid)
{
    uint32_t base = sb + buf*STG_BYTES;
    const __nv_bfloat16* srcs[4] = {Ah, Al, Bh, Bl};
    #pragma unroll
    for (int i = 0; i < 8; i++) {
        int c = tid + 256*i;
        int mat = c >> 9;
        int cc  = c & 511;
        int row = cc >> 2;
        int col = (cc & 3) * 8;
        const __nv_bfloat16* p = srcs[mat];
        int grow = ((mat < 2) ? m0 : n0) + row;
        int ok = (mat >= 2) || (grow < BSQ);
        const void* src = p + ((size_t)(ok ? grow : 0))*DIM + k0 + col;
        uint32_t dst = base + mat*MAT_BYTES + (uint32_t)(row*40 + col)*2;
        cp16(dst, src, ok ? 16 : 0);
    }
}

__global__ void __launch_bounds__(256, 1) mm_kernel(int wcode, const float* __restrict__ bias,
                                                    float* __restrict__ Yext, int ycode)
{
    extern __shared__ __align__(128) char smem[];
    const __nv_bfloat16* Ah = g_xh;
    const __nv_bfloat16* Al = g_xl;
    const __nv_bfloat16* Bh = g_wh + (size_t)wcode*DIM*DIM;
    const __nv_bfloat16* Bl = g_wl + (size_t)wcode*DIM*DIM;
    float* Y = (ycode==0)?g_q:(ycode==1)?g_k:(ycode==2)?g_v:Yext;

    uint32_t sb = smem_u32(smem);
    int tid = threadIdx.x;
    int lane = tid & 31;
    int wid = tid >> 5;
    int warp_m = wid >> 2;
    int warp_n = wid & 3;
    int n0 = blockIdx.x*128, m0 = blockIdx.y*128;

    float acc[4][4][4];
    #pragma unroll
    for (int i = 0; i < 4; i++)
        #pragma unroll
        for (int j = 0; j < 4; j++)
            #pragma unroll
            for (int q = 0; q < 4; q++) acc[i][j][q] = 0.f;

    uint32_t aRow = (uint32_t)(warp_m*64 + (lane & 15));
    uint32_t aCol = (uint32_t)((lane >> 4) * 8);
    uint32_t bRowBase = (uint32_t)(warp_n*32 + (lane & 7) + ((lane >> 4) << 3));
    uint32_t bCol = (uint32_t)(((lane >> 3) & 1) * 8);

    mm_load_stage(sb, 0, 0, Ah, Al, Bh, Bl, m0, n0, tid);
    CP_COMMIT();

    const int NK = DIM/32;
    for (int s = 0; s < NK; s++) {
        if (s + 1 < NK) {
            mm_load_stage(sb, (s+1)&1, (s+1)*32, Ah, Al, Bh, Bl, m0, n0, tid);
            CP_COMMIT();
            CP_WAIT1();
        } else {
            CP_WAIT0();
        }
        __syncthreads();

        uint32_t stg = sb + (s&1)*STG_BYTES;
        #pragma unroll
        for (int kk = 0; kk < 32; kk += 16) {
            uint32_t ah[4][4], al[4][4], bh[8], bl[8];
            #pragma unroll
            for (int i = 0; i < 4; i++) {
                uint32_t off = ((aRow + i*16)*40 + kk + aCol)*2;
                ldsm_x4(ah[i][0], ah[i][1], ah[i][2], ah[i][3], stg + 0*MAT_BYTES + off);
                ldsm_x4(al[i][0], al[i][1], al[i][2], al[i][3], stg + 1*MAT_BYTES + off);
            }
            #pragma unroll
            for (int g = 0; g < 2; g++) {
                uint32_t off = ((bRowBase + g*16)*40 + kk + bCol)*2;
                ldsm_x4(bh[g*4+0], bh[g*4+1], bh[g*4+2], bh[g*4+3], stg + 2*MAT_BYTES + off);
                ldsm_x4(bl[g*4+0], bl[g*4+1], bl[g*4+2], bl[g*4+3], stg + 3*MAT_BYTES + off);
            }
            #pragma unroll
            for (int i = 0; i < 4; i++) {
                #pragma unroll
                for (int j = 0; j < 4; j++) {
                    mma_bf16(acc[i][j], ah[i], bh[j*2], bh[j*2+1]);
                    mma_bf16(acc[i][j], ah[i], bl[j*2], bl[j*2+1]);
                    mma_bf16(acc[i][j], al[i], bh[j*2], bh[j*2+1]);
                }
            }
        }
        __syncthreads();
    }

    #pragma unroll
    for (int j = 0; j < 4; j++) {
        int col = n0 + warp_n*32 + j*8 + (lane & 3)*2;
        float b0 = bias[col], b1 = bias[col+1];
        #pragma unroll
        for (int i = 0; i < 4; i++) {
            int r0 = m0 + warp_m*64 + i*16 + (lane >> 2);
            if (r0 < BSQ) {
                float2 o = make_float2(acc[i][j][0] + b0, acc[i][j][1] + b1);
                *(float2*)(Y + (size_t)r0*DIM + col) = o;
            }
            int r1 = r0 + 8;
            if (r1 < BSQ) {
                float2 o = make_float2(acc[i][j][2] + b0, acc[i][j][3] + b1);
                *(float2*)(Y + (size_t)r1*DIM + col) = o;
            }
        }
    }
}

/* ---------------- xv: rank-32 projection (gate*S folded at store) --------- */
__global__ void xv_kernel(const float* __restrict__ Xin,
                          const float* __restrict__ Vm, const float* __restrict__ Sm)
{
    const float* X = Xin ? Xin : g_ctx;
    int b = blockIdx.y;
    int t0 = blockIdx.x * 32;
    __shared__ float Xs[32][132];
    __shared__ float Vs[128][33];
    int tid = threadIdx.x;
    int i0 = g_idx[b*2], i1 = g_idx[b*2+1];

    int tj = (tid & 7) * 4;
    int tt = tid >> 3;
    float a0 = 0.f, a1 = 0.f, a2 = 0.f, a3 = 0.f;

    for (int kc = 0; kc < 8; kc++) {
        int k0 = kc * 128;
        #pragma unroll
        for (int i = 0; i < 4; i++) {
            int c = tid + 256*i;
            int row = c >> 5, k4 = (c & 31) * 4;
            float4 v = make_float4(0.f,0.f,0.f,0.f);
            if (t0 + row < SEQ)
                v = *(const float4*)(X + (size_t)(b*SEQ + t0 + row)*DIM + k0 + k4);
            *(float4*)&Xs[row][k4] = v;
        }
        #pragma unroll
        for (int i = 0; i < 4; i++) {
            int c = tid + 256*i;
            int j = c >> 5, k4 = (c & 31) * 4;
            int e = (j < 16) ? i0 : i1;
            int r = j & 15;
            float4 v = *(const float4*)(Vm + ((size_t)e*RNK + r)*DIM + k0 + k4);
            Vs[k4+0][j] = v.x; Vs[k4+1][j] = v.y; Vs[k4+2][j] = v.z; Vs[k4+3][j] = v.w;
        }
        __syncthreads();
        #pragma unroll 4
        for (int k = 0; k < 128; k++) {
            float x = Xs[tt][k];
            a0 += x * Vs[k][tj+0];
            a1 += x * Vs[k][tj+1];
            a2 += x * Vs[k][tj+2];
            a3 += x * Vs[k][tj+3];
        }
        __syncthreads();
    }
    int t = t0 + tt;
    if (t < SEQ) {
        float g0 = g_gates[b*2], g1 = g_gates[b*2+1];
        float accs[4] = {a0, a1, a2, a3};
        #pragma unroll
        for (int q = 0; q < 4; q++) {
            int j = tj + q;
            int e = (j < 16) ? i0 : i1;
            int r = j & 15;
            float sc = ((j < 16) ? g0 : g1) * Sm[e*RNK + r];
            g_xv[(size_t)(b*SEQ + t)*32 + j] = accs[q] * sc;
        }
    }
}

/* ---------------- add: Y = (Ymm + xv@U^T)*scale; emit bf16 hi/lo for qkv -- */
__global__ void add_kernel(float* __restrict__ Yext, const float* __restrict__ U,
                           float scale, int code)
{
    const float* Yin = (code==0)?g_q:(code==1)?g_k:(code==2)?g_v:Yext;
    __nv_bfloat16* Hd = (code==0)?g_aqh:(code==1)?g_akh:g_avh;
    __nv_bfloat16* Ld = (code==0)?g_aql:(code==1)?g_akl:g_avl;
    int b = blockIdx.z;
    int t0 = blockIdx.x * 64;
    int o0 = blockIdx.y * 256;
    __shared__ float xvs[64][33];
    __shared__ float Us[32][260];
    int tid = threadIdx.x;
    int i0 = g_idx[b*2], i1 = g_idx[b*2+1];

    #pragma unroll
    for (int i = 0; i < 8; i++) {
        int c = tid + 256*i;
        int t = c >> 5, j = c & 31;
        float v = 0.f;
        if (t0 + t < SEQ) v = g_xv[(size_t)(b*SEQ + t0 + t)*32 + j];
        xvs[t][j] = v;
    }
    {
        int o = tid;
        #pragma unroll
        for (int hh = 0; hh < 2; hh++) {
            int e = hh ? i1 : i0;
            const float* up = U + ((size_t)e*DIM + o0 + o)*RNK;
            #pragma unroll
            for (int r = 0; r < 16; r++) Us[hh*16 + r][o] = up[r];
        }
    }
    __syncthreads();

    int tx = tid & 31, ty = tid >> 5;
    float acc[8][8];
    #pragma unroll
    for (int i = 0; i < 8; i++)
        #pragma unroll
        for (int j = 0; j < 8; j++) acc[i][j] = 0.f;

    #pragma unroll 4
    for (int j = 0; j < 32; j++) {
        float a[8];
        #pragma unroll
        for (int i = 0; i < 8; i++) a[i] = xvs[ty*8 + i][j];
        float4 b0 = *(float4*)&Us[j][tx*8];
        float4 b1 = *(float4*)&Us[j][tx*8 + 4];
        float bv[8] = {b0.x,b0.y,b0.z,b0.w,b1.x,b1.y,b1.z,b1.w};
        #pragma unroll
        for (int i = 0; i < 8; i++)
            #pragma unroll
            for (int q = 0; q < 8; q++)
                acc[i][q] += a[i]*bv[q];
    }

    int o = o0 + tx*8;
    int hh = o >> 6;             /* head */
    int d0 = o & 63;
    #pragma unroll
    for (int i = 0; i < 8; i++) {
        int t = t0 + ty*8 + i;
        if (t >= SEQ) break;
        const float* yp = Yin + (size_t)(b*SEQ + t)*DIM + o;
        float4 y0 = *(const float4*)yp;
        float4 y1 = *(const float4*)(yp + 4);
        float yv[8];
        yv[0]=(y0.x+acc[i][0])*scale; yv[1]=(y0.y+acc[i][1])*scale;
        yv[2]=(y0.z+acc[i][2])*scale; yv[3]=(y0.w+acc[i][3])*scale;
        yv[4]=(y1.x+acc[i][4])*scale; yv[5]=(y1.y+acc[i][5])*scale;
        yv[6]=(y1.z+acc[i][6])*scale; yv[7]=(y1.w+acc[i][7])*scale;
        if (code == 3) {
            float* wp = Yext + (size_t)(b*SEQ + t)*DIM + o;
            *(float4*)wp     = make_float4(yv[0],yv[1],yv[2],yv[3]);
            *(float4*)(wp+4) = make_float4(yv[4],yv[5],yv[6],yv[7]);
        } else {
            ushort hu[8], lu[8];
            #pragma unroll
            for (int q = 0; q < 8; q++) {
                __nv_bfloat16 hbf = __float2bfloat16(yv[q]);
                hu[q] = __bfloat16_as_ushort(hbf);
                lu[q] = __bfloat16_as_ushort(__float2bfloat16(yv[q] - __bfloat162float(hbf)));
            }
            size_t bidx = ((size_t)((b*NH + hh)*SEQP + t))*HD + d0;
            *(uint4*)(Hd + bidx) = *(uint4*)hu;
            *(uint4*)(Ld + bidx) = *(uint4*)lu;
        }
    }
}

/* ---------------- qk: scores = Q @ K^T (HMMA split bf16) ------------------ */
/* grid (3,3,512), 192 threads (6 warps: 2m x 3n), CTA tile 96x96, k=64      */
#define QK_SMEM (4*96*72*2)
__global__ void __launch_bounds__(192, 1) qk_kernel()
{
    extern __shared__ __align__(16) char qsm[];
    uint32_t sb = smem_u32(qsm);
    int tid = threadIdx.x, lane = tid & 31, wid = tid >> 5;
    int wm = wid & 1, wn = wid >> 1;
    int mt = blockIdx.x, nt = blockIdx.y, bh = blockIdx.z;

    const __nv_bfloat16* mats[4] = {g_aqh, g_aql, g_akh, g_akl};
    #pragma unroll
    for (int mat = 0; mat < 4; mat++) {
        const __nv_bfloat16* src = mats[mat] +
            ((size_t)bh*SEQP + ((mat < 2) ? mt : nt)*96)*HD;
        #pragma unroll
        for (int it = 0; it < 4; it++) {
            int c = tid + 192*it;           /* 0..767 */
            int row = c >> 3, col8 = (c & 7)*8;
            uint4 v = *(const uint4*)(src + (size_t)row*HD + col8);
            *(uint4*)(qsm + mat*13824 + (row*72 + col8)*2) = v;
        }
    }
    __syncthreads();

    float acc[3][4][4];
    #pragma unroll
    for (int i = 0; i < 3; i++)
        #pragma unroll
        for (int j = 0; j < 4; j++)
            #pragma unroll
            for (int q = 0; q < 4; q++) acc[i][j][q] = 0.f;

    uint32_t aRow = (uint32_t)(wm*48 + (lane & 15));
    uint32_t aCol = (uint32_t)((lane >> 4)*8);
    uint32_t bRow = (uint32_t)(wn*32 + (lane & 7) + ((lane >> 4) << 3));
    uint32_t bCol = (uint32_t)(((lane >> 3) & 1)*8);

    #pragma unroll
    for (int kk = 0; kk < 64; kk += 16) {
        uint32_t qh[3][4], ql[3][4], kh[8], kl[8];
        #pragma unroll
        for (int i = 0; i < 3; i++) {
            uint32_t off = ((aRow + i*16)*72 + kk + aCol)*2;
            ldsm_x4(qh[i][0], qh[i][1], qh[i][2], qh[i][3], sb + 0*13824 + off);
            ldsm_x4(ql[i][0], ql[i][1], ql[i][2], ql[i][3], sb + 1*13824 + off);
        }
        #pragma unroll
        for (int g = 0; g < 2; g++) {
            uint32_t off = ((bRow + g*16)*72 + kk + bCol)*2;
            ldsm_x4(kh[g*4+0], kh[g*4+1], kh[g*4+2], kh[g*4+3], sb + 2*13824 + off);
            ldsm_x4(kl[g*4+0], kl[g*4+1], kl[g*4+2], kl[g*4+3], sb + 3*13824 + off);
        }
        #pragma unroll
        for (int i = 0; i < 3; i++)
            #pragma unroll
            for (int j = 0; j < 4; j++) {
                mma_bf16(acc[i][j], qh[i], kh[j*2], kh[j*2+1]);
                mma_bf16(acc[i][j], qh[i], kl[j*2], kl[j*2+1]);
                mma_bf16(acc[i][j], ql[i], kh[j*2], kh[j*2+1]);
            }
    }

    size_t base = (size_t)bh*SEQ*SEQP;
    #pragma unroll
    for (int i = 0; i < 3; i++) {
        #pragma unroll
        for (int j = 0; j < 4; j++) {
            int n = nt*96 + wn*32 + j*8 + (lane & 3)*2;   /* < 288 <= SEQP, even */
            int m = mt*96 + wm*48 + i*16 + (lane >> 2);
            if (m < SEQ)
                *(float2*)(g_sc + base + (size_t)m*SEQP + n) = make_float2(acc[i][j][0], acc[i][j][1]);
            int m2 = m + 8;
            if (m2 < SEQ)
                *(float2*)(g_sc + base + (size_t)m2*SEQP + n) = make_float2(acc[i][j][2], acc[i][j][3]);
        }
    }
}

/* ---------------- softmax: row softmax -> P (bf16 hi/lo) ------------------ */
__global__ void softmax_kernel()
{
    int row = blockIdx.x*8 + (threadIdx.x >> 5);
    int lane = threadIdx.x & 31;
    if (row >= BB*NH*SEQ) return;
    int bh = row / SEQ, m = row % SEQ;
    const float* p = g_sc + (size_t)bh*SEQ*SEQP + (size_t)m*SEQP;

    float v[9];
    float mx = -1e30f;
    #pragma unroll
    for (int i = 0; i < 9; i++) {
        int t = lane + 32*i;
        v[i] = (t < SEQ) ? p[t] : -1e30f;
        mx = fmaxf(mx, v[i]);
    }
    #pragma unroll
    for (int off = 16; off > 0; off >>= 1)
        mx = fmaxf(mx, __shfl_xor_sync(0xffffffffu, mx, off));
    float sum = 0.f;
    #pragma unroll
    for (int i = 0; i < 9; i++) {
        int t = lane + 32*i;
        v[i] = (t < SEQ) ? expf(v[i]-mx) : 0.f;
        sum += v[i];
    }
    #pragma unroll
    for (int off = 16; off > 0; off >>= 1)
        sum += __shfl_xor_sync(0xffffffffu, sum, off);
    float inv = 1.f/sum;

    size_t pbase = ((size_t)bh*SEQ + m)*SEQP;
    #pragma unroll
    for (int i = 0; i < 10; i++) {
        int t = lane + 32*i;
        if (t >= SEQP) break;
        float pv = (i < 9 && t < SEQ) ? v[i]*inv : 0.f;
        __nv_bfloat16 hbf = __float2bfloat16(pv);
        g_ph[pbase + t] = hbf;
        g_pl[pbase + t] = __float2bfloat16(pv - __bfloat162float(hbf));
    }
}

/* ---------------- pv: ctx = P @ V (HMMA split, trans-B ldmatrix) ---------- */
/* grid (3, 512), 128 threads (4 warps: 2m x 2n), CTA tile 96(m) x 64(d)     */
__global__ void __launch_bounds__(128, 1) pv_kernel()
{
    __shared__ __align__(16) __nv_bfloat16 Ph[96*72], Pl[96*72], Vh[64*72], Vl[64*72];
    uint32_t sPh = smem_u32(Ph), sPl = smem_u32(Pl);
    uint32_t sVh = smem_u32(Vh), sVl = smem_u32(Vl);
    int tid = threadIdx.x, lane = tid & 31, wid = tid >> 5;
    int wm = wid & 1, wn = wid >> 1;
    int mt = blockIdx.x, bh = blockIdx.y;
    int b = bh >> 4, hh = bh & 15;

    float acc[3][4][4];
    #pragma unroll
    for (int i = 0; i < 3; i++)
        #pragma unroll
        for (int j = 0; j < 4; j++)
            #pragma unroll
            for (int q = 0; q < 4; q++) acc[i][j][q] = 0.f;

    uint32_t aRow = (uint32_t)(wm*48 + (lane & 15));
    uint32_t aCol = (uint32_t)((lane >> 4)*8);
    /* trans-B: row = k (t), col = n (d) — same index math as A, plus .trans */
    uint32_t bRow = (uint32_t)(lane & 15);
    uint32_t bColBase = (uint32_t)(wn*32 + ((lane >> 4) << 3));

    for (int c = 0; c < 5; c++) {
        int t0 = c*64;
        /* load P tiles 96 x 64 (hi, lo) */
        #pragma unroll
        for (int mat = 0; mat < 2; mat++) {
            const __nv_bfloat16* src = (mat ? g_pl : g_ph) + (size_t)bh*SEQ*SEQP;
            __nv_bfloat16* dst = mat ? Pl : Ph;
            #pragma unroll
            for (int it = 0; it < 6; it++) {
                int cc = tid + 128*it;      /* 0..767 */
                int row = cc >> 3, col8 = (cc & 7)*8;
                int m = mt*96 + row;
                uint4 v = make_uint4(0u,0u,0u,0u);
                if (m < SEQ) v = *(const uint4*)(src + (size_t)m*SEQP + t0 + col8);
                *(uint4*)((char*)dst + (row*72 + col8)*2) = v;
            }
        }
        /* load V tiles [t][d] 64 x 64 (hi, lo) — natural layout, no transpose */
        #pragma unroll
        for (int mat = 0; mat < 2; mat++) {
            const __nv_bfloat16* src = (mat ? g_avl : g_avh) + (size_t)bh*SEQP*HD;
            __nv_bfloat16* dst = mat ? Vl : Vh;
            #pragma unroll
            for (int it = 0; it < 4; it++) {
                int cc = tid + 128*it;      /* 0..511 */
                int row = cc >> 3, col8 = (cc & 7)*8;
                uint4 v = *(const uint4*)(src + (size_t)(t0 + row)*HD + col8);
                *(uint4*)((char*)dst + (row*72 + col8)*2) = v;
            }
        }
        __syncthreads();

        #pragma unroll
        for (int kk = 0; kk < 64; kk += 16) {
            uint32_t ph[3][4], pl[3][4], vh[8], vl[8];
            #pragma unroll
            for (int i = 0; i < 3; i++) {
                uint32_t off = ((aRow + i*16)*72 + kk + aCol)*2;
                ldsm_x4(ph[i][0], ph[i][1], ph[i][2], ph[i][3], sPh + off);
                ldsm_x4(pl[i][0], pl[i][1], pl[i][2], pl[i][3], sPl + off);
            }
            #pragma unroll
            for (int g = 0; g < 2; g++) {
                uint32_t off = ((kk + bRow)*72 + bColBase + g*16)*2;
                ldsm_x4_t(vh[g*4+0], vh[g*4+1], vh[g*4+2], vh[g*4+3], sVh + off);
                ldsm_x4_t(vl[g*4+0], vl[g*4+1], vl[g*4+2], vl[g*4+3], sVl + off);
            }
            #pragma unroll
            for (int i = 0; i < 3; i++)
                #pragma unroll
                for (int j = 0; j < 4; j++) {
                    mma_bf16(acc[i][j], ph[i], vh[j*2], vh[j*2+1]);
                    mma_bf16(acc[i][j], ph[i], vl[j*2], vl[j*2+1]);
                    mma_bf16(acc[i][j], pl[i], vh[j*2], vh[j*2+1]);
                }
        }
        __syncthreads();
    }

    #pragma unroll
    for (int i = 0; i < 3; i++) {
        #pragma unroll
        for (int j = 0; j < 4; j++) {
            int d = wn*32 + j*8 + (lane & 3)*2;
            int m = mt*96 + wm*48 + i*16 + (lane >> 2);
            if (m < SEQ)
                *(float2*)(g_ctx + (size_t)(b*SEQ + m)*DIM + hh*HD + d) =
                    make_float2(acc[i][j][0], acc[i][j][1]);
            int m2 = m + 8;
            if (m2 < SEQ)
                *(float2*)(g_ctx + (size_t)(b*SEQ + m2)*DIM + hh*HD + d) =
                    make_float2(acc[i][j][2], acc[i][j][3]);
        }
    }
}

/* ---------------- launch ---------------- */
extern "C" void kernel_launch(void* const* d_in, const int* in_sizes, int n_in,
                              void* d_out, int out_size)
{
    const float* x   = (const float*)d_in[0];
    const float* gw1 = (const float*)d_in[1];
    const float* gb1 = (const float*)d_in[2];
    const float* gw2 = (const float*)d_in[3];
    const float* gb2 = (const float*)d_in[4];
    const float* Wm[4] = {(const float*)d_in[5],  (const float*)d_in[10],
                          (const float*)d_in[15], (const float*)d_in[20]};
    const float* Uu[4] = {(const float*)d_in[6],  (const float*)d_in[11],
                          (const float*)d_in[16], (const float*)d_in[21]};
    const float* Ss[4] = {(const float*)d_in[7],  (const float*)d_in[12],
                          (const float*)d_in[17], (const float*)d_in[22]};
    const float* Vv[4] = {(const float*)d_in[8],  (const float*)d_in[13],
                          (const float*)d_in[18], (const float*)d_in[23]};
    const float* bbv[4] = {(const float*)d_in[9],  (const float*)d_in[14],
                           (const float*)d_in[19], (const float*)d_in[24]};
    float* out = (float*)d_out;

    cudaFuncSetAttribute(mm_kernel, cudaFuncAttributeMaxDynamicSharedMemorySize, MM_SMEM);
    cudaFuncSetAttribute(qk_kernel, cudaFuncAttributeMaxDynamicSharedMemorySize, QK_SMEM);

    gating_kernel<<<BB, 256>>>(x, gw1, gb1, gw2, gb2);

    int nx4 = BSQ*DIM/4;
    int nw4 = DIM*DIM/4;
    conv_kernel<<<(nx4 + 255)/256, 256>>>(x, 0, nx4);
    for (int p = 0; p < 4; p++)
        conv_kernel<<<(nw4 + 255)/256, 256>>>(Wm[p], p + 1, nw4);

    dim3 gmm(8, 65);
    dim3 gxv(9, BB);
    dim3 gadd(5, 4, BB);

    for (int p = 0; p < 3; p++) {
        mm_kernel<<<gmm, 256, MM_SMEM>>>(p, bbv[p], nullptr, p);
        xv_kernel<<<gxv, 256>>>(x, Vv[p], Ss[p]);
        add_kernel<<<gadd, 256>>>(nullptr, Uu[p], (p == 0) ? QSCALE : 1.0f, p);
    }

    qk_kernel<<<dim3(3, 3, BB*NH), 192, QK_SMEM>>>();
    softmax_kernel<<<(BB*NH*SEQ + 7)/8, 256>>>();
    pv_kernel<<<dim3(3, BB*NH), 128>>>();

    conv_kernel<<<(nx4 + 255)/256, 256>>>(nullptr, 5, nx4);
    mm_kernel<<<gmm, 256, MM_SMEM>>>(3, bbv[3], out, 3);
    xv_kernel<<<gxv, 256>>>(nullptr, Vv[3], Ss[3]);
    add_kernel<<<gadd, 256>>>(out, Uu[3], 1.0f, 3);
}

// round 6
// speedup vs baseline: 2.7563x; 1.0144x over previous
#include <cuda_runtime.h>
#include <cuda_bf16.h>
#include <cstdint>
#include <math.h>

#define BB   32
#define SEQ  257
#define SEQP 320
#define DIM  1024
#define NH   16
#define HD   64
#define NEXP 8
#define RNK  16
#define GHID 256
#define BSQ  (BB*SEQ)          /* 8224 tokens */
#define QSCALE 0.125f

/* ---------------- scratch (device globals; no allocations) ---------------- */
static __device__ float g_q  [(size_t)BSQ*DIM];
static __device__ float g_k  [(size_t)BSQ*DIM];
static __device__ float g_v  [(size_t)BSQ*DIM];
static __device__ float g_ctx[(size_t)BSQ*DIM];
static __device__ float g_xv [(size_t)BSQ*32];
static __device__ float g_gates[BB*2];
static __device__ int   g_idx  [BB*2];
static __device__ __align__(16) __nv_bfloat16 g_xh[(size_t)BSQ*DIM];
static __device__ __align__(16) __nv_bfloat16 g_xl[(size_t)BSQ*DIM];
static __device__ __align__(16) __nv_bfloat16 g_wh[(size_t)4*DIM*DIM];
static __device__ __align__(16) __nv_bfloat16 g_wl[(size_t)4*DIM*DIM];
/* attention bf16 operands: [bh][s(0..SEQP)][64]; pad rows stay .bss-zero */
static __device__ __align__(16) __nv_bfloat16 g_aqh[(size_t)BB*NH*SEQP*HD];
static __device__ __align__(16) __nv_bfloat16 g_aql[(size_t)BB*NH*SEQP*HD];
static __device__ __align__(16) __nv_bfloat16 g_akh[(size_t)BB*NH*SEQP*HD];
static __device__ __align__(16) __nv_bfloat16 g_akl[(size_t)BB*NH*SEQP*HD];
static __device__ __align__(16) __nv_bfloat16 g_avh[(size_t)BB*NH*SEQP*HD];
static __device__ __align__(16) __nv_bfloat16 g_avl[(size_t)BB*NH*SEQP*HD];

/* ---------------- small PTX helpers ---------------- */
__device__ __forceinline__ uint32_t smem_u32(const void* p) {
    uint32_t a;
    asm("{ .reg .u64 t; cvta.to.shared.u64 t, %1; cvt.u32.u64 %0, t; }" : "=r"(a) : "l"(p));
    return a;
}
__device__ __forceinline__ void cp16(uint32_t dst, const void* src, int srcBytes) {
    asm volatile("cp.async.cg.shared.global [%0], [%1], 16, %2;"
                 :: "r"(dst), "l"(src), "r"(srcBytes) : "memory");
}
#define CP_COMMIT() asm volatile("cp.async.commit_group;" ::: "memory")
#define CP_WAIT0()  asm volatile("cp.async.wait_group 0;" ::: "memory")
#define CP_WAIT1()  asm volatile("cp.async.wait_group 1;" ::: "memory")

__device__ __forceinline__ void ldsm_x4(uint32_t& r0, uint32_t& r1, uint32_t& r2, uint32_t& r3,
                                        uint32_t addr) {
    asm volatile("ldmatrix.sync.aligned.m8n8.x4.shared.b16 {%0,%1,%2,%3}, [%4];"
                 : "=r"(r0), "=r"(r1), "=r"(r2), "=r"(r3) : "r"(addr));
}
__device__ __forceinline__ void ldsm_x4_t(uint32_t& r0, uint32_t& r1, uint32_t& r2, uint32_t& r3,
                                          uint32_t addr) {
    asm volatile("ldmatrix.sync.aligned.m8n8.x4.trans.shared.b16 {%0,%1,%2,%3}, [%4];"
                 : "=r"(r0), "=r"(r1), "=r"(r2), "=r"(r3) : "r"(addr));
}
__device__ __forceinline__ void mma_bf16(float* c, const uint32_t* a, uint32_t b0, uint32_t b1) {
    asm volatile("mma.sync.aligned.m16n8k16.row.col.f32.bf16.bf16.f32 "
                 "{%0,%1,%2,%3}, {%4,%5,%6,%7}, {%8,%9}, {%0,%1,%2,%3};"
                 : "+f"(c[0]), "+f"(c[1]), "+f"(c[2]), "+f"(c[3])
                 : "r"(a[0]), "r"(a[1]), "r"(a[2]), "r"(a[3]), "r"(b0), "r"(b1));
}
__device__ __forceinline__ uint32_t pack_bf2(float lo, float hi) {
    __nv_bfloat16 l = __float2bfloat16(lo), h = __float2bfloat16(hi);
    return ((uint32_t)__bfloat16_as_ushort(h) << 16) | (uint32_t)__bfloat16_as_ushort(l);
}

/* ---------------- gating ---------------- */
__global__ void gating_kernel(const float* __restrict__ x,
                              const float* __restrict__ gw1, const float* __restrict__ gb1,
                              const float* __restrict__ gw2, const float* __restrict__ gb2)
{
    int b = blockIdx.x;
    __shared__ float pooled[DIM];
    __shared__ float h[GHID];
    __shared__ float logits[NEXP];
    int tid = threadIdx.x;
    for (int d = tid; d < DIM; d += 256) {
        float s = 0.f;
        const float* xp = x + (size_t)b*SEQ*DIM + d;
        for (int t = 0; t < SEQ; t++) s += xp[(size_t)t*DIM];
        pooled[d] = s * (1.0f/SEQ);
    }
    __syncthreads();
    {
        float a = gb1[tid];
        const float* w = gw1 + (size_t)tid*DIM;
        #pragma unroll 4
        for (int d = 0; d < DIM; d++) a += pooled[d]*w[d];
        h[tid] = fmaxf(a, 0.f);
    }
    __syncthreads();
    if (tid < NEXP) {
        float a = gb2[tid];
        const float* w = gw2 + tid*GHID;
        for (int d = 0; d < GHID; d++) a += h[d]*w[d];
        logits[tid] = a;
    }
    __syncthreads();
    if (tid == 0) {
        int i0 = 0;
        for (int e = 1; e < NEXP; e++) if (logits[e] > logits[i0]) i0 = e;
        int i1 = -1;
        for (int e = 0; e < NEXP; e++) {
            if (e == i0) continue;
            if (i1 < 0 || logits[e] > logits[i1]) i1 = e;
        }
        float v0 = logits[i0], v1 = logits[i1];
        float e0 = expf(v0 - v0), e1 = expf(v1 - v0);
        float inv = 1.f/(e0 + e1);
        g_gates[b*2]   = e0*inv;
        g_gates[b*2+1] = e1*inv;
        g_idx[b*2]   = i0;
        g_idx[b*2+1] = i1;
    }
}

/* ---------------- fp32 -> (bf16 hi, bf16 lo) ---------------- */
__global__ void conv_kernel(const float* __restrict__ srcExt, int which, int n4)
{
    const float* s;
    __nv_bfloat16 *H, *L;
    if (which == 0)      { s = srcExt; H = g_xh; L = g_xl; }
    else if (which <= 4) { s = srcExt;
                           H = g_wh + (size_t)(which-1)*DIM*DIM;
                           L = g_wl + (size_t)(which-1)*DIM*DIM; }
    else                 { s = g_ctx; H = g_xh; L = g_xl; }
    int i = blockIdx.x*256 + threadIdx.x;
    if (i >= n4) return;
    float4 v = ((const float4*)s)[i];
    ushort4 hh, ll;
    __nv_bfloat16 t;
    t = __float2bfloat16(v.x); hh.x = __bfloat16_as_ushort(t);
    ll.x = __bfloat16_as_ushort(__float2bfloat16(v.x - __bfloat162float(t)));
    t = __float2bfloat16(v.y); hh.y = __bfloat16_as_ushort(t);
    ll.y = __bfloat16_as_ushort(__float2bfloat16(v.y - __bfloat162float(t)));
    t = __float2bfloat16(v.z); hh.z = __bfloat16_as_ushort(t);
    ll.z = __bfloat16_as_ushort(__float2bfloat16(v.z - __bfloat162float(t)));
    t = __float2bfloat16(v.w); hh.w = __bfloat16_as_ushort(t);
    ll.w = __bfloat16_as_ushort(__float2bfloat16(v.w - __bfloat162float(t)));
    ((ushort4*)H)[i] = hh;
    ((ushort4*)L)[i] = ll;
}

/* ---------------- HMMA split-bf16 GEMM: Y = X @ W^T + bias ---------------- */
#define MAT_BYTES (128*40*2)            /* 10240 */
#define STG_BYTES (4*MAT_BYTES)         /* 40960 */
#define MM_SMEM   (2*STG_BYTES)         /* 81920 */

__device__ __forceinline__ void mm_load_stage(uint32_t sb, int buf, int k0,
    const __nv_bfloat16* Ah, const __nv_bfloat16* Al,
    const __nv_bfloat16* Bh, const __nv_bfloat16* Bl,
    int m0, int n0, int tid)
{
    uint32_t base = sb + buf*STG_BYTES;
    const __nv_bfloat16* srcs[4] = {Ah, Al, Bh, Bl};
    #pragma unroll
    for (int i = 0; i < 8; i++) {
        int c = tid + 256*i;
        int mat = c >> 9;
        int cc  = c & 511;
        int row = cc >> 2;
        int col = (cc & 3) * 8;
        const __nv_bfloat16* p = srcs[mat];
        int grow = ((mat < 2) ? m0 : n0) + row;
        int ok = (mat >= 2) || (grow < BSQ);
        const void* src = p + ((size_t)(ok ? grow : 0))*DIM + k0 + col;
        uint32_t dst = base + mat*MAT_BYTES + (uint32_t)(row*40 + col)*2;
        cp16(dst, src, ok ? 16 : 0);
    }
}

__global__ void __launch_bounds__(256, 1) mm_kernel(int wcode, const float* __restrict__ bias,
                                                    float* __restrict__ Yext, int ycode)
{
    extern __shared__ __align__(128) char smem[];
    const __nv_bfloat16* Ah = g_xh;
    const __nv_bfloat16* Al = g_xl;
    const __nv_bfloat16* Bh = g_wh + (size_t)wcode*DIM*DIM;
    const __nv_bfloat16* Bl = g_wl + (size_t)wcode*DIM*DIM;
    float* Y = (ycode==0)?g_q:(ycode==1)?g_k:(ycode==2)?g_v:Yext;

    uint32_t sb = smem_u32(smem);
    int tid = threadIdx.x;
    int lane = tid & 31;
    int wid = tid >> 5;
    int warp_m = wid >> 2;
    int warp_n = wid & 3;
    int n0 = blockIdx.x*128, m0 = blockIdx.y*128;

    float acc[4][4][4];
    #pragma unroll
    for (int i = 0; i < 4; i++)
        #pragma unroll
        for (int j = 0; j < 4; j++)
            #pragma unroll
            for (int q = 0; q < 4; q++) acc[i][j][q] = 0.f;

    uint32_t aRow = (uint32_t)(warp_m*64 + (lane & 15));
    uint32_t aCol = (uint32_t)((lane >> 4) * 8);
    uint32_t bRowBase = (uint32_t)(warp_n*32 + (lane & 7) + ((lane >> 4) << 3));
    uint32_t bCol = (uint32_t)(((lane >> 3) & 1) * 8);

    mm_load_stage(sb, 0, 0, Ah, Al, Bh, Bl, m0, n0, tid);
    CP_COMMIT();

    const int NK = DIM/32;
    for (int s = 0; s < NK; s++) {
        if (s + 1 < NK) {
            mm_load_stage(sb, (s+1)&1, (s+1)*32, Ah, Al, Bh, Bl, m0, n0, tid);
            CP_COMMIT();
            CP_WAIT1();
        } else {
            CP_WAIT0();
        }
        __syncthreads();

        uint32_t stg = sb + (s&1)*STG_BYTES;
        #pragma unroll
        for (int kk = 0; kk < 32; kk += 16) {
            uint32_t ah[4][4], al[4][4], bh[8], bl[8];
            #pragma unroll
            for (int i = 0; i < 4; i++) {
                uint32_t off = ((aRow + i*16)*40 + kk + aCol)*2;
                ldsm_x4(ah[i][0], ah[i][1], ah[i][2], ah[i][3], stg + 0*MAT_BYTES + off);
                ldsm_x4(al[i][0], al[i][1], al[i][2], al[i][3], stg + 1*MAT_BYTES + off);
            }
            #pragma unroll
            for (int g = 0; g < 2; g++) {
                uint32_t off = ((bRowBase + g*16)*40 + kk + bCol)*2;
                ldsm_x4(bh[g*4+0], bh[g*4+1], bh[g*4+2], bh[g*4+3], stg + 2*MAT_BYTES + off);
                ldsm_x4(bl[g*4+0], bl[g*4+1], bl[g*4+2], bl[g*4+3], stg + 3*MAT_BYTES + off);
            }
            #pragma unroll
            for (int i = 0; i < 4; i++) {
                #pragma unroll
                for (int j = 0; j < 4; j++) {
                    mma_bf16(acc[i][j], ah[i], bh[j*2], bh[j*2+1]);
                    mma_bf16(acc[i][j], ah[i], bl[j*2], bl[j*2+1]);
                    mma_bf16(acc[i][j], al[i], bh[j*2], bh[j*2+1]);
                }
            }
        }
        __syncthreads();
    }

    #pragma unroll
    for (int j = 0; j < 4; j++) {
        int col = n0 + warp_n*32 + j*8 + (lane & 3)*2;
        float b0 = bias[col], b1 = bias[col+1];
        #pragma unroll
        for (int i = 0; i < 4; i++) {
            int r0 = m0 + warp_m*64 + i*16 + (lane >> 2);
            if (r0 < BSQ) {
                float2 o = make_float2(acc[i][j][0] + b0, acc[i][j][1] + b1);
                *(float2*)(Y + (size_t)r0*DIM + col) = o;
            }
            int r1 = r0 + 8;
            if (r1 < BSQ) {
                float2 o = make_float2(acc[i][j][2] + b0, acc[i][j][3] + b1);
                *(float2*)(Y + (size_t)r1*DIM + col) = o;
            }
        }
    }
}

/* ---------------- xv: rank-32 projection (gate*S folded at store) --------- */
__global__ void xv_kernel(const float* __restrict__ Xin,
                          const float* __restrict__ Vm, const float* __restrict__ Sm)
{
    const float* X = Xin ? Xin : g_ctx;
    int b = blockIdx.y;
    int t0 = blockIdx.x * 32;
    __shared__ float Xs[32][132];
    __shared__ float Vs[128][33];
    int tid = threadIdx.x;
    int i0 = g_idx[b*2], i1 = g_idx[b*2+1];

    int tj = (tid & 7) * 4;
    int tt = tid >> 3;
    float a0 = 0.f, a1 = 0.f, a2 = 0.f, a3 = 0.f;

    for (int kc = 0; kc < 8; kc++) {
        int k0 = kc * 128;
        #pragma unroll
        for (int i = 0; i < 4; i++) {
            int c = tid + 256*i;
            int row = c >> 5, k4 = (c & 31) * 4;
            float4 v = make_float4(0.f,0.f,0.f,0.f);
            if (t0 + row < SEQ)
                v = *(const float4*)(X + (size_t)(b*SEQ + t0 + row)*DIM + k0 + k4);
            *(float4*)&Xs[row][k4] = v;
        }
        #pragma unroll
        for (int i = 0; i < 4; i++) {
            int c = tid + 256*i;
            int j = c >> 5, k4 = (c & 31) * 4;
            int e = (j < 16) ? i0 : i1;
            int r = j & 15;
            float4 v = *(const float4*)(Vm + ((size_t)e*RNK + r)*DIM + k0 + k4);
            Vs[k4+0][j] = v.x; Vs[k4+1][j] = v.y; Vs[k4+2][j] = v.z; Vs[k4+3][j] = v.w;
        }
        __syncthreads();
        #pragma unroll 4
        for (int k = 0; k < 128; k++) {
            float x = Xs[tt][k];
            a0 += x * Vs[k][tj+0];
            a1 += x * Vs[k][tj+1];
            a2 += x * Vs[k][tj+2];
            a3 += x * Vs[k][tj+3];
        }
        __syncthreads();
    }
    int t = t0 + tt;
    if (t < SEQ) {
        float g0 = g_gates[b*2], g1 = g_gates[b*2+1];
        float accs[4] = {a0, a1, a2, a3};
        #pragma unroll
        for (int q = 0; q < 4; q++) {
            int j = tj + q;
            int e = (j < 16) ? i0 : i1;
            int r = j & 15;
            float sc = ((j < 16) ? g0 : g1) * Sm[e*RNK + r];
            g_xv[(size_t)(b*SEQ + t)*32 + j] = accs[q] * sc;
        }
    }
}

/* ---------------- add: Y = (Ymm + xv@U^T)*scale; emit bf16 hi/lo for qkv -- */
__global__ void add_kernel(float* __restrict__ Yext, const float* __restrict__ U,
                           float scale, int code)
{
    const float* Yin = (code==0)?g_q:(code==1)?g_k:(code==2)?g_v:Yext;
    __nv_bfloat16* Hd = (code==0)?g_aqh:(code==1)?g_akh:g_avh;
    __nv_bfloat16* Ld = (code==0)?g_aql:(code==1)?g_akl:g_avl;
    int b = blockIdx.z;
    int t0 = blockIdx.x * 64;
    int o0 = blockIdx.y * 256;
    __shared__ float xvs[64][33];
    __shared__ float Us[32][260];
    int tid = threadIdx.x;
    int i0 = g_idx[b*2], i1 = g_idx[b*2+1];

    #pragma unroll
    for (int i = 0; i < 8; i++) {
        int c = tid + 256*i;
        int t = c >> 5, j = c & 31;
        float v = 0.f;
        if (t0 + t < SEQ) v = g_xv[(size_t)(b*SEQ + t0 + t)*32 + j];
        xvs[t][j] = v;
    }
    {
        int o = tid;
        #pragma unroll
        for (int hh = 0; hh < 2; hh++) {
            int e = hh ? i1 : i0;
            const float* up = U + ((size_t)e*DIM + o0 + o)*RNK;
            #pragma unroll
            for (int r = 0; r < 16; r++) Us[hh*16 + r][o] = up[r];
        }
    }
    __syncthreads();

    int tx = tid & 31, ty = tid >> 5;
    float acc[8][8];
    #pragma unroll
    for (int i = 0; i < 8; i++)
        #pragma unroll
        for (int j = 0; j < 8; j++) acc[i][j] = 0.f;

    #pragma unroll 4
    for (int j = 0; j < 32; j++) {
        float a[8];
        #pragma unroll
        for (int i = 0; i < 8; i++) a[i] = xvs[ty*8 + i][j];
        float4 b0 = *(float4*)&Us[j][tx*8];
        float4 b1 = *(float4*)&Us[j][tx*8 + 4];
        float bv[8] = {b0.x,b0.y,b0.z,b0.w,b1.x,b1.y,b1.z,b1.w};
        #pragma unroll
        for (int i = 0; i < 8; i++)
            #pragma unroll
            for (int q = 0; q < 8; q++)
                acc[i][q] += a[i]*bv[q];
    }

    int o = o0 + tx*8;
    int hh = o >> 6;             /* head */
    int d0 = o & 63;
    #pragma unroll
    for (int i = 0; i < 8; i++) {
        int t = t0 + ty*8 + i;
        if (t >= SEQ) break;
        const float* yp = Yin + (size_t)(b*SEQ + t)*DIM + o;
        float4 y0 = *(const float4*)yp;
        float4 y1 = *(const float4*)(yp + 4);
        float yv[8];
        yv[0]=(y0.x+acc[i][0])*scale; yv[1]=(y0.y+acc[i][1])*scale;
        yv[2]=(y0.z+acc[i][2])*scale; yv[3]=(y0.w+acc[i][3])*scale;
        yv[4]=(y1.x+acc[i][4])*scale; yv[5]=(y1.y+acc[i][5])*scale;
        yv[6]=(y1.z+acc[i][6])*scale; yv[7]=(y1.w+acc[i][7])*scale;
        if (code == 3) {
            float* wp = Yext + (size_t)(b*SEQ + t)*DIM + o;
            *(float4*)wp     = make_float4(yv[0],yv[1],yv[2],yv[3]);
            *(float4*)(wp+4) = make_float4(yv[4],yv[5],yv[6],yv[7]);
        } else {
            ushort hu[8], lu[8];
            #pragma unroll
            for (int q = 0; q < 8; q++) {
                __nv_bfloat16 hbf = __float2bfloat16(yv[q]);
                hu[q] = __bfloat16_as_ushort(hbf);
                lu[q] = __bfloat16_as_ushort(__float2bfloat16(yv[q] - __bfloat162float(hbf)));
            }
            size_t bidx = ((size_t)((b*NH + hh)*SEQP + t))*HD + d0;
            *(uint4*)(Hd + bidx) = *(uint4*)hu;
            *(uint4*)(Ld + bidx) = *(uint4*)lu;
        }
    }
}

/* ---------------- fused flash attention: ctx = softmax(QK^T) V ------------ */
/* grid (3, 512), 192 threads (6 warps), warp = 16 q-rows x 64 d.
   smem: Q tile (hi,lo) 96x72 resident + double-buffered K/V chunks 64x72.   */
#define FA_QBYTES  13824            /* 96*72*2 */
#define FA_MATB    9216             /* 64*72*2 */
#define FA_STGB    (4*FA_MATB)      /* 36864: Kh,Kl,Vh,Vl */
#define FA_KVBASE  (2*FA_QBYTES)    /* 27648 */
#define FA_SMEM    (FA_KVBASE + 2*FA_STGB)   /* 101376 */

__device__ __forceinline__ void fa_load_kv(uint32_t sb, char* smem, int buf, int t0,
                                           int bh, int tid)
{
    uint32_t base = sb + FA_KVBASE + buf*FA_STGB;
    size_t goff = (size_t)bh*SEQP*HD + (size_t)t0*HD;
    const __nv_bfloat16* srcs[4] = {g_akh + goff, g_akl + goff, g_avh + goff, g_avl + goff};
    #pragma unroll
    for (int i = 0; i < 11; i++) {
        int c = tid + 192*i;
        if (c < 2048) {
            int mat = c >> 9, cc = c & 511;
            int row = cc >> 3, col8 = (cc & 7)*8;
            cp16(base + mat*FA_MATB + (uint32_t)(row*72 + col8)*2,
                 srcs[mat] + (size_t)row*HD + col8, 16);
        }
    }
}

__global__ void __launch_bounds__(192, 1) fa_kernel()
{
    extern __shared__ __align__(16) char fsm[];
    uint32_t sb = smem_u32(fsm);
    int tid = threadIdx.x, lane = tid & 31, w = tid >> 5;
    int mt = blockIdx.x, bh = blockIdx.y;
    int b = bh >> 4, hh = bh & 15;

    /* stage Q tile 96x64 (hi, lo) */
    {
        const __nv_bfloat16* qs[2] = {g_aqh, g_aql};
        #pragma unroll
        for (int mat = 0; mat < 2; mat++) {
            const __nv_bfloat16* src = qs[mat] + ((size_t)bh*SEQP + mt*96)*HD;
            #pragma unroll
            for (int it = 0; it < 4; it++) {
                int c = tid + 192*it;
                int row = c >> 3, col8 = (c & 7)*8;
                uint4 v = *(const uint4*)(src + (size_t)row*HD + col8);
                *(uint4*)(fsm + mat*FA_QBYTES + (row*72 + col8)*2) = v;
            }
        }
    }
    fa_load_kv(sb, fsm, 0, 0, bh, tid);
    CP_COMMIT();
    __syncthreads();

    /* Q fragments (resident) */
    uint32_t qh[4][4], ql[4][4];
    {
        uint32_t aRow = (uint32_t)(w*16 + (lane & 15));
        uint32_t aCol = (uint32_t)((lane >> 4)*8);
        #pragma unroll
        for (int kt = 0; kt < 4; kt++) {
            uint32_t off = (aRow*72 + kt*16 + aCol)*2;
            ldsm_x4(qh[kt][0], qh[kt][1], qh[kt][2], qh[kt][3], sb + off);
            ldsm_x4(ql[kt][0], ql[kt][1], ql[kt][2], ql[kt][3], sb + FA_QBYTES + off);
        }
    }

    float o[8][4];
    #pragma unroll
    for (int j = 0; j < 8; j++)
        #pragma unroll
        for (int q = 0; q < 4; q++) o[j][q] = 0.f;
    float mr0 = -1e30f, mr1 = -1e30f, l0 = 0.f, l1 = 0.f;

    uint32_t kRow = (uint32_t)((lane & 7) + ((lane >> 4) << 3));
    uint32_t kCol = (uint32_t)(((lane >> 3) & 1)*8);
    uint32_t vRow = (uint32_t)(lane & 15);
    uint32_t vCol = (uint32_t)((lane >> 4) << 3);

    for (int c = 0; c < 5; c++) {
        if (c + 1 < 5) {
            fa_load_kv(sb, fsm, (c+1)&1, (c+1)*64, bh, tid);
            CP_COMMIT();
            CP_WAIT1();
        } else {
            CP_WAIT0();
        }
        __syncthreads();
        uint32_t stg = sb + FA_KVBASE + (c&1)*FA_STGB;

        /* scores S (16 rows x 64 keys per warp) */
        float S[8][4];
        #pragma unroll
        for (int j = 0; j < 8; j++)
            #pragma unroll
            for (int q = 0; q < 4; q++) S[j][q] = 0.f;

        #pragma unroll
        for (int kt = 0; kt < 4; kt++) {
            #pragma unroll
            for (int g = 0; g < 4; g++) {
                uint32_t off = ((kRow + g*16)*72 + kt*16 + kCol)*2;
                uint32_t h0,h1,h2,h3, e0,e1,e2,e3;
                ldsm_x4(h0,h1,h2,h3, stg + 0*FA_MATB + off);
                ldsm_x4(e0,e1,e2,e3, stg + 1*FA_MATB + off);
                mma_bf16(S[2*g],   qh[kt], h0, h1);
                mma_bf16(S[2*g],   qh[kt], e0, e1);
                mma_bf16(S[2*g],   ql[kt], h0, h1);
                mma_bf16(S[2*g+1], qh[kt], h2, h3);
                mma_bf16(S[2*g+1], qh[kt], e2, e3);
                mma_bf16(S[2*g+1], ql[kt], h2, h3);
            }
        }

        /* mask pad key columns (only last chunk has t >= SEQ) */
        if (c == 4) {
            #pragma unroll
            for (int j = 0; j < 8; j++) {
                int tb = 256 + j*8 + (lane & 3)*2;
                if (tb     >= SEQ) { S[j][0] = -1e30f; S[j][2] = -1e30f; }
                if (tb + 1 >= SEQ) { S[j][1] = -1e30f; S[j][3] = -1e30f; }
            }
        }

        /* online softmax */
        float mx0 = -1e30f, mx1 = -1e30f;
        #pragma unroll
        for (int j = 0; j < 8; j++) {
            mx0 = fmaxf(mx0, fmaxf(S[j][0], S[j][1]));
            mx1 = fmaxf(mx1, fmaxf(S[j][2], S[j][3]));
        }
        mx0 = fmaxf(mx0, __shfl_xor_sync(0xffffffffu, mx0, 1));
        mx0 = fmaxf(mx0, __shfl_xor_sync(0xffffffffu, mx0, 2));
        mx1 = fmaxf(mx1, __shfl_xor_sync(0xffffffffu, mx1, 1));
        mx1 = fmaxf(mx1, __shfl_xor_sync(0xffffffffu, mx1, 2));
        float mn0 = fmaxf(mr0, mx0), mn1 = fmaxf(mr1, mx1);
        float sc0 = expf(mr0 - mn0), sc1 = expf(mr1 - mn1);
        mr0 = mn0; mr1 = mn1;

        uint32_t ph[4][4], pl[4][4];
        float rs0 = 0.f, rs1 = 0.f;
        #pragma unroll
        for (int j = 0; j < 8; j++) {
            float p0 = expf(S[j][0] - mn0), p1 = expf(S[j][1] - mn0);
            float p2 = expf(S[j][2] - mn1), p3 = expf(S[j][3] - mn1);
            rs0 += p0 + p1; rs1 += p2 + p3;
            float h0 = __bfloat162float(__float2bfloat16(p0));
            float h1 = __bfloat162float(__float2bfloat16(p1));
            float h2 = __bfloat162float(__float2bfloat16(p2));
            float h3 = __bfloat162float(__float2bfloat16(p3));
            int kt2 = j >> 1, hb = (j & 1)*2;
            ph[kt2][hb]   = pack_bf2(h0, h1);
            ph[kt2][hb+1] = pack_bf2(h2, h3);
            pl[kt2][hb]   = pack_bf2(p0 - h0, p1 - h1);
            pl[kt2][hb+1] = pack_bf2(p2 - h2, p3 - h3);
        }
        rs0 += __shfl_xor_sync(0xffffffffu, rs0, 1);
        rs0 += __shfl_xor_sync(0xffffffffu, rs0, 2);
        rs1 += __shfl_xor_sync(0xffffffffu, rs1, 1);
        rs1 += __shfl_xor_sync(0xffffffffu, rs1, 2);
        l0 = l0*sc0 + rs0;
        l1 = l1*sc1 + rs1;

        #pragma unroll
        for (int j = 0; j < 8; j++) {
            o[j][0] *= sc0; o[j][1] *= sc0;
            o[j][2] *= sc1; o[j][3] *= sc1;
        }

        /* P @ V */
        #pragma unroll
        for (int kt2 = 0; kt2 < 4; kt2++) {
            #pragma unroll
            for (int g = 0; g < 4; g++) {
                uint32_t off = ((kt2*16 + vRow)*72 + g*16 + vCol)*2;
                uint32_t h0,h1,h2,h3, e0,e1,e2,e3;
                ldsm_x4_t(h0,h1,h2,h3, stg + 2*FA_MATB + off);
                ldsm_x4_t(e0,e1,e2,e3, stg + 3*FA_MATB + off);
                mma_bf16(o[2*g],   ph[kt2], h0, h1);
                mma_bf16(o[2*g],   ph[kt2], e0, e1);
                mma_bf16(o[2*g],   pl[kt2], h0, h1);
                mma_bf16(o[2*g+1], ph[kt2], h2, h3);
                mma_bf16(o[2*g+1], ph[kt2], e2, e3);
                mma_bf16(o[2*g+1], pl[kt2], h2, h3);
            }
        }
        __syncthreads();
    }

    float inv0 = 1.f/l0, inv1 = 1.f/l1;
    int r0 = mt*96 + w*16 + (lane >> 2);
    int r1 = r0 + 8;
    #pragma unroll
    for (int j = 0; j < 8; j++) {
        int d = hh*HD + j*8 + (lane & 3)*2;
        if (r0 < SEQ)
            *(float2*)(g_ctx + (size_t)(b*SEQ + r0)*DIM + d) =
                make_float2(o[j][0]*inv0, o[j][1]*inv0);
        if (r1 < SEQ)
            *(float2*)(g_ctx + (size_t)(b*SEQ + r1)*DIM + d) =
                make_float2(o[j][2]*inv1, o[j][3]*inv1);
    }
}

/* ---------------- launch ---------------- */
extern "C" void kernel_launch(void* const* d_in, const int* in_sizes, int n_in,
                              void* d_out, int out_size)
{
    const float* x   = (const float*)d_in[0];
    const float* gw1 = (const float*)d_in[1];
    const float* gb1 = (const float*)d_in[2];
    const float* gw2 = (const float*)d_in[3];
    const float* gb2 = (const float*)d_in[4];
    const float* Wm[4] = {(const float*)d_in[5],  (const float*)d_in[10],
                          (const float*)d_in[15], (const float*)d_in[20]};
    const float* Uu[4] = {(const float*)d_in[6],  (const float*)d_in[11],
                          (const float*)d_in[16], (const float*)d_in[21]};
    const float* Ss[4] = {(const float*)d_in[7],  (const float*)d_in[12],
                          (const float*)d_in[17], (const float*)d_in[22]};
    const float* Vv[4] = {(const float*)d_in[8],  (const float*)d_in[13],
                          (const float*)d_in[18], (const float*)d_in[23]};
    const float* bbv[4] = {(const float*)d_in[9],  (const float*)d_in[14],
                           (const float*)d_in[19], (const float*)d_in[24]};
    float* out = (float*)d_out;

    cudaFuncSetAttribute(mm_kernel, cudaFuncAttributeMaxDynamicSharedMemorySize, MM_SMEM);
    cudaFuncSetAttribute(fa_kernel, cudaFuncAttributeMaxDynamicSharedMemorySize, FA_SMEM);

    gating_kernel<<<BB, 256>>>(x, gw1, gb1, gw2, gb2);

    int nx4 = BSQ*DIM/4;
    int nw4 = DIM*DIM/4;
    conv_kernel<<<(nx4 + 255)/256, 256>>>(x, 0, nx4);
    for (int p = 0; p < 4; p++)
        conv_kernel<<<(nw4 + 255)/256, 256>>>(Wm[p], p + 1, nw4);

    dim3 gmm(8, 65);
    dim3 gxv(9, BB);
    dim3 gadd(5, 4, BB);

    for (int p = 0; p < 3; p++) {
        mm_kernel<<<gmm, 256, MM_SMEM>>>(p, bbv[p], nullptr, p);
        xv_kernel<<<gxv, 256>>>(x, Vv[p], Ss[p]);
        add_kernel<<<gadd, 256>>>(nullptr, Uu[p], (p == 0) ? QSCALE : 1.0f, p);
    }

    fa_kernel<<<dim3(3, BB*NH), 192, FA_SMEM>>>();

    conv_kernel<<<(nx4 + 255)/256, 256>>>(nullptr, 5, nx4);
    mm_kernel<<<gmm, 256, MM_SMEM>>>(3, bbv[3], out, 3);
    xv_kernel<<<gxv, 256>>>(nullptr, Vv[3], Ss[3]);
    add_kernel<<<gadd, 256>>>(out, Uu[3], 1.0f, 3);
}

// round 7
// speedup vs baseline: 3.0077x; 1.0912x over previous
#include <cuda_runtime.h>
#include <cuda_bf16.h>
#include <cstdint>
#include <math.h>

#define BB   32
#define SEQ  257
#define SEQP 320
#define DIM  1024
#define NH   16
#define HD   64
#define NEXP 8
#define RNK  16
#define GHID 256
#define BSQ  (BB*SEQ)          /* 8224 tokens */
#define QSCALE 0.125f

/* ---------------- scratch (device globals; no allocations) ---------------- */
static __device__ float g_q  [(size_t)BSQ*DIM];
static __device__ float g_k  [(size_t)BSQ*DIM];
static __device__ float g_v  [(size_t)BSQ*DIM];
static __device__ float g_ctx[(size_t)BSQ*DIM];
static __device__ float g_gates[BB*2];
static __device__ int   g_idx  [BB*2];
static __device__ __align__(16) __nv_bfloat16 g_xh[(size_t)BSQ*DIM];
static __device__ __align__(16) __nv_bfloat16 g_xl[(size_t)BSQ*DIM];
static __device__ __align__(16) __nv_bfloat16 g_wh[(size_t)4*DIM*DIM];
static __device__ __align__(16) __nv_bfloat16 g_wl[(size_t)4*DIM*DIM];
/* combined expert V rows (gate*S folded), U cols; per-projection reuse */
static __device__ __align__(16) __nv_bfloat16 g_vbh[(size_t)BB*32*DIM];
static __device__ __align__(16) __nv_bfloat16 g_vbl[(size_t)BB*32*DIM];
static __device__ __align__(16) __nv_bfloat16 g_ubh[(size_t)BB*DIM*32];
static __device__ __align__(16) __nv_bfloat16 g_ubl[(size_t)BB*DIM*32];
/* xv: [b][t<SEQP][32] hi/lo; pad rows stay .bss-zero */
static __device__ __align__(16) __nv_bfloat16 g_xvh[(size_t)BB*SEQP*32];
static __device__ __align__(16) __nv_bfloat16 g_xvl[(size_t)BB*SEQP*32];
/* attention bf16 operands: [bh][s(0..SEQP)][64]; pad rows stay .bss-zero */
static __device__ __align__(16) __nv_bfloat16 g_aqh[(size_t)BB*NH*SEQP*HD];
static __device__ __align__(16) __nv_bfloat16 g_aql[(size_t)BB*NH*SEQP*HD];
static __device__ __align__(16) __nv_bfloat16 g_akh[(size_t)BB*NH*SEQP*HD];
static __device__ __align__(16) __nv_bfloat16 g_akl[(size_t)BB*NH*SEQP*HD];
static __device__ __align__(16) __nv_bfloat16 g_avh[(size_t)BB*NH*SEQP*HD];
static __device__ __align__(16) __nv_bfloat16 g_avl[(size_t)BB*NH*SEQP*HD];

/* ---------------- small PTX helpers ---------------- */
__device__ __forceinline__ uint32_t smem_u32(const void* p) {
    uint32_t a;
    asm("{ .reg .u64 t; cvta.to.shared.u64 t, %1; cvt.u32.u64 %0, t; }" : "=r"(a) : "l"(p));
    return a;
}
__device__ __forceinline__ void cp16(uint32_t dst, const void* src, int srcBytes) {
    asm volatile("cp.async.cg.shared.global [%0], [%1], 16, %2;"
                 :: "r"(dst), "l"(src), "r"(srcBytes) : "memory");
}
#define CP_COMMIT() asm volatile("cp.async.commit_group;" ::: "memory")
#define CP_WAIT0()  asm volatile("cp.async.wait_group 0;" ::: "memory")
#define CP_WAIT1()  asm volatile("cp.async.wait_group 1;" ::: "memory")

__device__ __forceinline__ void ldsm_x4(uint32_t& r0, uint32_t& r1, uint32_t& r2, uint32_t& r3,
                                        uint32_t addr) {
    asm volatile("ldmatrix.sync.aligned.m8n8.x4.shared.b16 {%0,%1,%2,%3}, [%4];"
                 : "=r"(r0), "=r"(r1), "=r"(r2), "=r"(r3) : "r"(addr));
}
__device__ __forceinline__ void ldsm_x4_t(uint32_t& r0, uint32_t& r1, uint32_t& r2, uint32_t& r3,
                                          uint32_t addr) {
    asm volatile("ldmatrix.sync.aligned.m8n8.x4.trans.shared.b16 {%0,%1,%2,%3}, [%4];"
                 : "=r"(r0), "=r"(r1), "=r"(r2), "=r"(r3) : "r"(addr));
}
__device__ __forceinline__ void mma_bf16(float* c, const uint32_t* a, uint32_t b0, uint32_t b1) {
    asm volatile("mma.sync.aligned.m16n8k16.row.col.f32.bf16.bf16.f32 "
                 "{%0,%1,%2,%3}, {%4,%5,%6,%7}, {%8,%9}, {%0,%1,%2,%3};"
                 : "+f"(c[0]), "+f"(c[1]), "+f"(c[2]), "+f"(c[3])
                 : "r"(a[0]), "r"(a[1]), "r"(a[2]), "r"(a[3]), "r"(b0), "r"(b1));
}
__device__ __forceinline__ uint32_t pack_bf2(float lo, float hi) {
    __nv_bfloat16 l = __float2bfloat16(lo), h = __float2bfloat16(hi);
    return ((uint32_t)__bfloat16_as_ushort(h) << 16) | (uint32_t)__bfloat16_as_ushort(l);
}

/* ---------------- gating ---------------- */
__global__ void gating_kernel(const float* __restrict__ x,
                              const float* __restrict__ gw1, const float* __restrict__ gb1,
                              const float* __restrict__ gw2, const float* __restrict__ gb2)
{
    int b = blockIdx.x;
    __shared__ float pooled[DIM];
    __shared__ float h[GHID];
    __shared__ float logits[NEXP];
    int tid = threadIdx.x;
    for (int d = tid; d < DIM; d += 256) {
        float s = 0.f;
        const float* xp = x + (size_t)b*SEQ*DIM + d;
        for (int t = 0; t < SEQ; t++) s += xp[(size_t)t*DIM];
        pooled[d] = s * (1.0f/SEQ);
    }
    __syncthreads();
    {
        float a = gb1[tid];
        const float* w = gw1 + (size_t)tid*DIM;
        #pragma unroll 4
        for (int d = 0; d < DIM; d++) a += pooled[d]*w[d];
        h[tid] = fmaxf(a, 0.f);
    }
    __syncthreads();
    if (tid < NEXP) {
        float a = gb2[tid];
        const float* w = gw2 + tid*GHID;
        for (int d = 0; d < GHID; d++) a += h[d]*w[d];
        logits[tid] = a;
    }
    __syncthreads();
    if (tid == 0) {
        int i0 = 0;
        for (int e = 1; e < NEXP; e++) if (logits[e] > logits[i0]) i0 = e;
        int i1 = -1;
        for (int e = 0; e < NEXP; e++) {
            if (e == i0) continue;
            if (i1 < 0 || logits[e] > logits[i1]) i1 = e;
        }
        float v0 = logits[i0], v1 = logits[i1];
        float e0 = expf(v0 - v0), e1 = expf(v1 - v0);
        float inv = 1.f/(e0 + e1);
        g_gates[b*2]   = e0*inv;
        g_gates[b*2+1] = e1*inv;
        g_idx[b*2]   = i0;
        g_idx[b*2+1] = i1;
    }
}

/* ---------------- fp32 -> (bf16 hi, bf16 lo) ---------------- */
__global__ void conv_kernel(const float* __restrict__ srcExt, int which, int n4)
{
    const float* s;
    __nv_bfloat16 *H, *L;
    if (which == 0)      { s = srcExt; H = g_xh; L = g_xl; }
    else if (which <= 4) { s = srcExt;
                           H = g_wh + (size_t)(which-1)*DIM*DIM;
                           L = g_wl + (size_t)(which-1)*DIM*DIM; }
    else                 { s = g_ctx; H = g_xh; L = g_xl; }
    int i = blockIdx.x*256 + threadIdx.x;
    if (i >= n4) return;
    float4 v = ((const float4*)s)[i];
    ushort4 hh, ll;
    __nv_bfloat16 t;
    t = __float2bfloat16(v.x); hh.x = __bfloat16_as_ushort(t);
    ll.x = __bfloat16_as_ushort(__float2bfloat16(v.x - __bfloat162float(t)));
    t = __float2bfloat16(v.y); hh.y = __bfloat16_as_ushort(t);
    ll.y = __bfloat16_as_ushort(__float2bfloat16(v.y - __bfloat162float(t)));
    t = __float2bfloat16(v.z); hh.z = __bfloat16_as_ushort(t);
    ll.z = __bfloat16_as_ushort(__float2bfloat16(v.z - __bfloat162float(t)));
    t = __float2bfloat16(v.w); hh.w = __bfloat16_as_ushort(t);
    ll.w = __bfloat16_as_ushort(__float2bfloat16(v.w - __bfloat162float(t)));
    ((ushort4*)H)[i] = hh;
    ((ushort4*)L)[i] = ll;
}

/* ---------------- vconv: gather+scale V rows, split bf16 ------------------ */
/* grid (BB, 32), 256 threads; row j of batch b = V[e_j][r_j] * gate_j*S     */
__global__ void vconv_kernel(const float* __restrict__ Vm, const float* __restrict__ Sm)
{
    int b = blockIdx.x, j = blockIdx.y;
    int half = j >> 4, r = j & 15;
    int e = g_idx[b*2 + half];
    float sc = g_gates[b*2 + half] * Sm[e*RNK + r];
    float4 v = ((const float4*)(Vm + ((size_t)e*RNK + r)*DIM))[threadIdx.x];
    v.x *= sc; v.y *= sc; v.z *= sc; v.w *= sc;
    ushort4 hh, ll;
    __nv_bfloat16 t;
    t = __float2bfloat16(v.x); hh.x = __bfloat16_as_ushort(t);
    ll.x = __bfloat16_as_ushort(__float2bfloat16(v.x - __bfloat162float(t)));
    t = __float2bfloat16(v.y); hh.y = __bfloat16_as_ushort(t);
    ll.y = __bfloat16_as_ushort(__float2bfloat16(v.y - __bfloat162float(t)));
    t = __float2bfloat16(v.z); hh.z = __bfloat16_as_ushort(t);
    ll.z = __bfloat16_as_ushort(__float2bfloat16(v.z - __bfloat162float(t)));
    t = __float2bfloat16(v.w); hh.w = __bfloat16_as_ushort(t);
    ll.w = __bfloat16_as_ushort(__float2bfloat16(v.w - __bfloat162float(t)));
    size_t o = ((size_t)b*32 + j)*DIM/4 + threadIdx.x;
    ((ushort4*)g_vbh)[o] = hh;
    ((ushort4*)g_vbl)[o] = ll;
}

/* ---------------- uconv: gather U cols per batch, split bf16 -------------- */
/* grid (BB, 4), 256 threads; Ub[b][n][j] = U[e_j][n][r_j]                   */
__global__ void uconv_kernel(const float* __restrict__ U)
{
    int b = blockIdx.x;
    int n = blockIdx.y*256 + threadIdx.x;
    int i0 = g_idx[b*2], i1 = g_idx[b*2+1];
    const float* u0 = U + ((size_t)i0*DIM + n)*RNK;
    const float* u1 = U + ((size_t)i1*DIM + n)*RNK;
    __nv_bfloat16* H = g_ubh + ((size_t)b*DIM + n)*32;
    __nv_bfloat16* L = g_ubl + ((size_t)b*DIM + n)*32;
    #pragma unroll
    for (int r = 0; r < 16; r++) {
        float v0 = u0[r], v1 = u1[r];
        __nv_bfloat16 h0 = __float2bfloat16(v0);
        H[r]      = h0;
        L[r]      = __float2bfloat16(v0 - __bfloat162float(h0));
        __nv_bfloat16 h1 = __float2bfloat16(v1);
        H[16 + r] = h1;
        L[16 + r] = __float2bfloat16(v1 - __bfloat162float(h1));
    }
}

/* ---------------- HMMA split-bf16 GEMM: Y = X @ W^T + bias ---------------- */
#define MAT_BYTES (128*40*2)            /* 10240 */
#define STG_BYTES (4*MAT_BYTES)         /* 40960 */
#define MM_SMEM   (2*STG_BYTES)         /* 81920 */

__device__ __forceinline__ void mm_load_stage(uint32_t sb, int buf, int k0,
    const __nv_bfloat16* Ah, const __nv_bfloat16* Al,
    const __nv_bfloat16* Bh, const __nv_bfloat16* Bl,
    int m0, int n0, int tid)
{
    uint32_t base = sb + buf*STG_BYTES;
    const __nv_bfloat16* srcs[4] = {Ah, Al, Bh, Bl};
    #pragma unroll
    for (int i = 0; i < 8; i++) {
        int c = tid + 256*i;
        int mat = c >> 9;
        int cc  = c & 511;
        int row = cc >> 2;
        int col = (cc & 3) * 8;
        const __nv_bfloat16* p = srcs[mat];
        int grow = ((mat < 2) ? m0 : n0) + row;
        int ok = (mat >= 2) || (grow < BSQ);
        const void* src = p + ((size_t)(ok ? grow : 0))*DIM + k0 + col;
        uint32_t dst = base + mat*MAT_BYTES + (uint32_t)(row*40 + col)*2;
        cp16(dst, src, ok ? 16 : 0);
    }
}

__global__ void __launch_bounds__(256, 1) mm_kernel(int wcode, const float* __restrict__ bias,
                                                    float* __restrict__ Yext, int ycode)
{
    extern __shared__ __align__(128) char smem[];
    const __nv_bfloat16* Ah = g_xh;
    const __nv_bfloat16* Al = g_xl;
    const __nv_bfloat16* Bh = g_wh + (size_t)wcode*DIM*DIM;
    const __nv_bfloat16* Bl = g_wl + (size_t)wcode*DIM*DIM;
    float* Y = (ycode==0)?g_q:(ycode==1)?g_k:(ycode==2)?g_v:Yext;

    uint32_t sb = smem_u32(smem);
    int tid = threadIdx.x;
    int lane = tid & 31;
    int wid = tid >> 5;
    int warp_m = wid >> 2;
    int warp_n = wid & 3;
    int n0 = blockIdx.x*128, m0 = blockIdx.y*128;

    float acc[4][4][4];
    #pragma unroll
    for (int i = 0; i < 4; i++)
        #pragma unroll
        for (int j = 0; j < 4; j++)
            #pragma unroll
            for (int q = 0; q < 4; q++) acc[i][j][q] = 0.f;

    uint32_t aRow = (uint32_t)(warp_m*64 + (lane & 15));
    uint32_t aCol = (uint32_t)((lane >> 4) * 8);
    uint32_t bRowBase = (uint32_t)(warp_n*32 + (lane & 7) + ((lane >> 4) << 3));
    uint32_t bCol = (uint32_t)(((lane >> 3) & 1) * 8);

    mm_load_stage(sb, 0, 0, Ah, Al, Bh, Bl, m0, n0, tid);
    CP_COMMIT();

    const int NK = DIM/32;
    for (int s = 0; s < NK; s++) {
        if (s + 1 < NK) {
            mm_load_stage(sb, (s+1)&1, (s+1)*32, Ah, Al, Bh, Bl, m0, n0, tid);
            CP_COMMIT();
            CP_WAIT1();
        } else {
            CP_WAIT0();
        }
        __syncthreads();

        uint32_t stg = sb + (s&1)*STG_BYTES;
        #pragma unroll
        for (int kk = 0; kk < 32; kk += 16) {
            uint32_t ah[4][4], al[4][4], bh[8], bl[8];
            #pragma unroll
            for (int i = 0; i < 4; i++) {
                uint32_t off = ((aRow + i*16)*40 + kk + aCol)*2;
                ldsm_x4(ah[i][0], ah[i][1], ah[i][2], ah[i][3], stg + 0*MAT_BYTES + off);
                ldsm_x4(al[i][0], al[i][1], al[i][2], al[i][3], stg + 1*MAT_BYTES + off);
            }
            #pragma unroll
            for (int g = 0; g < 2; g++) {
                uint32_t off = ((bRowBase + g*16)*40 + kk + bCol)*2;
                ldsm_x4(bh[g*4+0], bh[g*4+1], bh[g*4+2], bh[g*4+3], stg + 2*MAT_BYTES + off);
                ldsm_x4(bl[g*4+0], bl[g*4+1], bl[g*4+2], bl[g*4+3], stg + 3*MAT_BYTES + off);
            }
            #pragma unroll
            for (int i = 0; i < 4; i++) {
                #pragma unroll
                for (int j = 0; j < 4; j++) {
                    mma_bf16(acc[i][j], ah[i], bh[j*2], bh[j*2+1]);
                    mma_bf16(acc[i][j], ah[i], bl[j*2], bl[j*2+1]);
                    mma_bf16(acc[i][j], al[i], bh[j*2], bh[j*2+1]);
                }
            }
        }
        __syncthreads();
    }

    #pragma unroll
    for (int j = 0; j < 4; j++) {
        int col = n0 + warp_n*32 + j*8 + (lane & 3)*2;
        float b0 = bias[col], b1 = bias[col+1];
        #pragma unroll
        for (int i = 0; i < 4; i++) {
            int r0 = m0 + warp_m*64 + i*16 + (lane >> 2);
            if (r0 < BSQ) {
                float2 o = make_float2(acc[i][j][0] + b0, acc[i][j][1] + b1);
                *(float2*)(Y + (size_t)r0*DIM + col) = o;
            }
            int r1 = r0 + 8;
            if (r1 < BSQ) {
                float2 o = make_float2(acc[i][j][2] + b0, acc[i][j][3] + b1);
                *(float2*)(Y + (size_t)r1*DIM + col) = o;
            }
        }
    }
}

/* ---------------- xvmma: xv = X @ Vb^T (HMMA split), out bf16 hi/lo ------- */
/* grid (3, BB), 192 threads (6 warps), warp = 16 tokens x 32 j, K=1024      */
#define XV_ABYT 13824                 /* 96*72*2 */
#define XV_BBYT 4608                  /* 32*72*2 */
#define XV_STGB (2*XV_ABYT + 2*XV_BBYT)   /* 36864 */
#define XV_SMEM (2*XV_STGB)               /* 73728 */

__device__ __forceinline__ void xv_load_stage(uint32_t sb, int buf, int k0,
                                              int b, int mt, int tid)
{
    uint32_t base = sb + buf*XV_STGB;
    #pragma unroll
    for (int i = 0; i < 11; i++) {
        int c = tid + 192*i;
        if (c >= 2048) break;
        if (c < 1536) {
            int mat = (c >= 768);
            int cc = c - (mat ? 768 : 0);
            int row = cc >> 3, col8 = (cc & 7)*8;
            int t = mt*96 + row;
            int ok = t < SEQ;
            const __nv_bfloat16* src = (mat ? g_xl : g_xh) +
                ((size_t)b*SEQ + (ok ? t : 0))*DIM + k0 + col8;
            cp16(base + mat*XV_ABYT + (uint32_t)(row*72 + col8)*2, src, ok ? 16 : 0);
        } else {
            int c2 = c - 1536;
            int mat = c2 >> 8;
            int cc = c2 & 255;
            int row = cc >> 3, col8 = (cc & 7)*8;
            const __nv_bfloat16* src = (mat ? g_vbl : g_vbh) +
                ((size_t)b*32 + row)*DIM + k0 + col8;
            cp16(base + 2*XV_ABYT + mat*XV_BBYT + (uint32_t)(row*72 + col8)*2, src, 16);
        }
    }
}

__global__ void __launch_bounds__(192, 1) xvmma_kernel()
{
    extern __shared__ __align__(16) char xsm[];
    uint32_t sb = smem_u32(xsm);
    int tid = threadIdx.x, lane = tid & 31, w = tid >> 5;
    int mt = blockIdx.x, b = blockIdx.y;

    float acc[4][4];
    #pragma unroll
    for (int j = 0; j < 4; j++)
        #pragma unroll
        for (int q = 0; q < 4; q++) acc[j][q] = 0.f;

    uint32_t aRow = (uint32_t)(w*16 + (lane & 15));
    uint32_t aCol = (uint32_t)((lane >> 4)*8);
    uint32_t bRow = (uint32_t)((lane & 7) + ((lane >> 4) << 3));
    uint32_t bCol = (uint32_t)(((lane >> 3) & 1)*8);

    xv_load_stage(sb, 0, 0, b, mt, tid);
    CP_COMMIT();

    for (int s = 0; s < 16; s++) {
        if (s + 1 < 16) {
            xv_load_stage(sb, (s+1)&1, (s+1)*64, b, mt, tid);
            CP_COMMIT();
            CP_WAIT1();
        } else {
            CP_WAIT0();
        }
        __syncthreads();
        uint32_t stg = sb + (s&1)*XV_STGB;
        #pragma unroll
        for (int kt = 0; kt < 4; kt++) {
            uint32_t ah[4], al[4], bh2[8], bl2[8];
            uint32_t off = (aRow*72 + kt*16 + aCol)*2;
            ldsm_x4(ah[0], ah[1], ah[2], ah[3], stg + off);
            ldsm_x4(al[0], al[1], al[2], al[3], stg + XV_ABYT + off);
            #pragma unroll
            for (int g = 0; g < 2; g++) {
                uint32_t bo = ((bRow + g*16)*72 + kt*16 + bCol)*2;
                ldsm_x4(bh2[g*4+0], bh2[g*4+1], bh2[g*4+2], bh2[g*4+3],
                        stg + 2*XV_ABYT + bo);
                ldsm_x4(bl2[g*4+0], bl2[g*4+1], bl2[g*4+2], bl2[g*4+3],
                        stg + 2*XV_ABYT + XV_BBYT + bo);
            }
            #pragma unroll
            for (int j = 0; j < 4; j++) {
                mma_bf16(acc[j], ah, bh2[j*2], bh2[j*2+1]);
                mma_bf16(acc[j], ah, bl2[j*2], bl2[j*2+1]);
                mma_bf16(acc[j], al, bh2[j*2], bh2[j*2+1]);
            }
        }
        __syncthreads();
    }

    int r0 = mt*96 + w*16 + (lane >> 2);
    int r1 = r0 + 8;
    #pragma unroll
    for (int j = 0; j < 4; j++) {
        int col = j*8 + (lane & 3)*2;
        if (r0 < SEQ) {
            float p0 = acc[j][0], p1 = acc[j][1];
            float h0 = __bfloat162float(__float2bfloat16(p0));
            float h1 = __bfloat162float(__float2bfloat16(p1));
            size_t o = ((size_t)b*SEQP + r0)*32 + col;
            *(uint32_t*)(g_xvh + o) = pack_bf2(h0, h1);
            *(uint32_t*)(g_xvl + o) = pack_bf2(p0 - h0, p1 - h1);
        }
        if (r1 < SEQ) {
            float p0 = acc[j][2], p1 = acc[j][3];
            float h0 = __bfloat162float(__float2bfloat16(p0));
            float h1 = __bfloat162float(__float2bfloat16(p1));
            size_t o = ((size_t)b*SEQP + r1)*32 + col;
            *(uint32_t*)(g_xvh + o) = pack_bf2(h0, h1);
            *(uint32_t*)(g_xvl + o) = pack_bf2(p0 - h0, p1 - h1);
        }
    }
}

/* ---------------- addmma: Y = (Ymm + xv @ Ub^T)*scale (HMMA, K=32) -------- */
/* grid (3, 8, BB), 192 threads (6 warps), warp = 16 tokens x 128 n          */
#define AD_AB (96*40*2)               /* 7680 */
#define AD_BB (128*40*2)              /* 10240 */
#define AD_SMEM (2*AD_AB + 2*AD_BB)   /* 35840 < 48K static */

__global__ void __launch_bounds__(192, 1) addmma_kernel(float* __restrict__ Yext,
                                                        float scale, int code)
{
    __shared__ __align__(16) char adsm[AD_SMEM];
    uint32_t sb = smem_u32(adsm);
    const float* Yin = (code==0)?g_q:(code==1)?g_k:(code==2)?g_v:Yext;
    __nv_bfloat16* Hd = (code==0)?g_aqh:(code==1)?g_akh:g_avh;
    __nv_bfloat16* Ld = (code==0)?g_aql:(code==1)?g_akl:g_avl;
    int tid = threadIdx.x, lane = tid & 31, w = tid >> 5;
    int mt = blockIdx.x, nt = blockIdx.y, b = blockIdx.z;

    #pragma unroll
    for (int i = 0; i < 10; i++) {
        int c = tid + 192*i;
        if (c >= 1792) break;
        if (c < 768) {
            int mat = (c >= 384);
            int cc = c - (mat ? 384 : 0);
            int row = cc >> 2, col8 = (cc & 3)*8;
            uint4 v = *(const uint4*)((mat ? g_xvl : g_xvh) +
                        ((size_t)b*SEQP + mt*96 + row)*32 + col8);
            *(uint4*)(adsm + mat*AD_AB + (row*40 + col8)*2) = v;
        } else {
            int c2 = c - 768;
            int mat = (c2 >= 512);
            int cc = c2 - (mat ? 512 : 0);
            int row = cc >> 2, col8 = (cc & 3)*8;
            uint4 v = *(const uint4*)((mat ? g_ubl : g_ubh) +
                        ((size_t)b*DIM + nt*128 + row)*32 + col8);
            *(uint4*)(adsm + 2*AD_AB + mat*AD_BB + (row*40 + col8)*2) = v;
        }
    }
    __syncthreads();

    float acc[16][4];
    #pragma unroll
    for (int j = 0; j < 16; j++)
        #pragma unroll
        for (int q = 0; q < 4; q++) acc[j][q] = 0.f;

    uint32_t aRow = (uint32_t)(w*16 + (lane & 15));
    uint32_t aColb = (uint32_t)((lane >> 4)*8);
    uint32_t bRow = (uint32_t)((lane & 7) + ((lane >> 4) << 3));
    uint32_t bColb = (uint32_t)(((lane >> 3) & 1)*8);

    #pragma unroll
    for (int kt = 0; kt < 2; kt++) {
        uint32_t ah[4], al[4];
        uint32_t off = (aRow*40 + kt*16 + aColb)*2;
        ldsm_x4(ah[0], ah[1], ah[2], ah[3], sb + off);
        ldsm_x4(al[0], al[1], al[2], al[3], sb + AD_AB + off);
        #pragma unroll
        for (int g = 0; g < 8; g++) {
            uint32_t bo = ((bRow + g*16)*40 + kt*16 + bColb)*2;
            uint32_t bh[4], bl[4];
            ldsm_x4(bh[0], bh[1], bh[2], bh[3], sb + 2*AD_AB + bo);
            ldsm_x4(bl[0], bl[1], bl[2], bl[3], sb + 2*AD_AB + AD_BB + bo);
            #pragma unroll
            for (int r = 0; r < 2; r++) {
                int jj = g*2 + r;
                mma_bf16(acc[jj], ah, bh[r*2], bh[r*2+1]);
                mma_bf16(acc[jj], ah, bl[r*2], bl[r*2+1]);
                mma_bf16(acc[jj], al, bh[r*2], bh[r*2+1]);
            }
        }
    }

    int r0 = mt*96 + w*16 + (lane >> 2);
    int r1 = r0 + 8;
    #pragma unroll
    for (int j = 0; j < 16; j++) {
        int colg = nt*128 + j*8 + (lane & 3)*2;
        int hh = colg >> 6, d0 = colg & 63;
        #pragma unroll
        for (int half = 0; half < 2; half++) {
            int r = half ? r1 : r0;
            if (r >= SEQ) continue;
            float a0 = acc[j][half*2], a1 = acc[j][half*2 + 1];
            const float* yp = Yin + ((size_t)b*SEQ + r)*DIM + colg;
            float2 y = *(const float2*)yp;
            float v0 = (y.x + a0)*scale;
            float v1 = (y.y + a1)*scale;
            if (code == 3) {
                *(float2*)(Yext + ((size_t)b*SEQ + r)*DIM + colg) = make_float2(v0, v1);
            } else {
                float h0 = __bfloat162float(__float2bfloat16(v0));
                float h1 = __bfloat162float(__float2bfloat16(v1));
                size_t o = ((size_t)((b*NH + hh)*SEQP) + r)*HD + d0;
                *(uint32_t*)(Hd + o) = pack_bf2(h0, h1);
                *(uint32_t*)(Ld + o) = pack_bf2(v0 - h0, v1 - h1);
            }
        }
    }
}

/* ---------------- fused flash attention: ctx = softmax(QK^T) V ------------ */
#define FA_QBYTES  13824
#define FA_MATB    9216
#define FA_STGB    (4*FA_MATB)
#define FA_KVBASE  (2*FA_QBYTES)
#define FA_SMEM    (FA_KVBASE + 2*FA_STGB)

__device__ __forceinline__ void fa_load_kv(uint32_t sb, char* smem, int buf, int t0,
                                           int bh, int tid)
{
    uint32_t base = sb + FA_KVBASE + buf*FA_STGB;
    size_t goff = (size_t)bh*SEQP*HD + (size_t)t0*HD;
    const __nv_bfloat16* srcs[4] = {g_akh + goff, g_akl + goff, g_avh + goff, g_avl + goff};
    #pragma unroll
    for (int i = 0; i < 11; i++) {
        int c = tid + 192*i;
        if (c < 2048) {
            int mat = c >> 9, cc = c & 511;
            int row = cc >> 3, col8 = (cc & 7)*8;
            cp16(base + mat*FA_MATB + (uint32_t)(row*72 + col8)*2,
                 srcs[mat] + (size_t)row*HD + col8, 16);
        }
    }
}

__global__ void __launch_bounds__(192, 1) fa_kernel()
{
    extern __shared__ __align__(16) char fsm[];
    uint32_t sb = smem_u32(fsm);
    int tid = threadIdx.x, lane = tid & 31, w = tid >> 5;
    int mt = blockIdx.x, bh = blockIdx.y;
    int b = bh >> 4, hh = bh & 15;

    {
        const __nv_bfloat16* qs[2] = {g_aqh, g_aql};
        #pragma unroll
        for (int mat = 0; mat < 2; mat++) {
            const __nv_bfloat16* src = qs[mat] + ((size_t)bh*SEQP + mt*96)*HD;
            #pragma unroll
            for (int it = 0; it < 4; it++) {
                int c = tid + 192*it;
                int row = c >> 3, col8 = (c & 7)*8;
                uint4 v = *(const uint4*)(src + (size_t)row*HD + col8);
                *(uint4*)(fsm + mat*FA_QBYTES + (row*72 + col8)*2) = v;
            }
        }
    }
    fa_load_kv(sb, fsm, 0, 0, bh, tid);
    CP_COMMIT();
    __syncthreads();

    uint32_t qh[4][4], ql[4][4];
    {
        uint32_t aRow = (uint32_t)(w*16 + (lane & 15));
        uint32_t aCol = (uint32_t)((lane >> 4)*8);
        #pragma unroll
        for (int kt = 0; kt < 4; kt++) {
            uint32_t off = (aRow*72 + kt*16 + aCol)*2;
            ldsm_x4(qh[kt][0], qh[kt][1], qh[kt][2], qh[kt][3], sb + off);
            ldsm_x4(ql[kt][0], ql[kt][1], ql[kt][2], ql[kt][3], sb + FA_QBYTES + off);
        }
    }

    float o[8][4];
    #pragma unroll
    for (int j = 0; j < 8; j++)
        #pragma unroll
        for (int q = 0; q < 4; q++) o[j][q] = 0.f;
    float mr0 = -1e30f, mr1 = -1e30f, l0 = 0.f, l1 = 0.f;

    uint32_t kRow = (uint32_t)((lane & 7) + ((lane >> 4) << 3));
    uint32_t kCol = (uint32_t)(((lane >> 3) & 1)*8);
    uint32_t vRow = (uint32_t)(lane & 15);
    uint32_t vCol = (uint32_t)((lane >> 4) << 3);

    for (int c = 0; c < 5; c++) {
        if (c + 1 < 5) {
            fa_load_kv(sb, fsm, (c+1)&1, (c+1)*64, bh, tid);
            CP_COMMIT();
            CP_WAIT1();
        } else {
            CP_WAIT0();
        }
        __syncthreads();
        uint32_t stg = sb + FA_KVBASE + (c&1)*FA_STGB;

        float S[8][4];
        #pragma unroll
        for (int j = 0; j < 8; j++)
            #pragma unroll
            for (int q = 0; q < 4; q++) S[j][q] = 0.f;

        #pragma unroll
        for (int kt = 0; kt < 4; kt++) {
            #pragma unroll
            for (int g = 0; g < 4; g++) {
                uint32_t off = ((kRow + g*16)*72 + kt*16 + kCol)*2;
                uint32_t h0,h1,h2,h3, e0,e1,e2,e3;
                ldsm_x4(h0,h1,h2,h3, stg + 0*FA_MATB + off);
                ldsm_x4(e0,e1,e2,e3, stg + 1*FA_MATB + off);
                mma_bf16(S[2*g],   qh[kt], h0, h1);
                mma_bf16(S[2*g],   qh[kt], e0, e1);
                mma_bf16(S[2*g],   ql[kt], h0, h1);
                mma_bf16(S[2*g+1], qh[kt], h2, h3);
                mma_bf16(S[2*g+1], qh[kt], e2, e3);
                mma_bf16(S[2*g+1], ql[kt], h2, h3);
            }
        }

        if (c == 4) {
            #pragma unroll
            for (int j = 0; j < 8; j++) {
                int tb = 256 + j*8 + (lane & 3)*2;
                if (tb     >= SEQ) { S[j][0] = -1e30f; S[j][2] = -1e30f; }
                if (tb + 1 >= SEQ) { S[j][1] = -1e30f; S[j][3] = -1e30f; }
            }
        }

        float mx0 = -1e30f, mx1 = -1e30f;
        #pragma unroll
        for (int j = 0; j < 8; j++) {
            mx0 = fmaxf(mx0, fmaxf(S[j][0], S[j][1]));
            mx1 = fmaxf(mx1, fmaxf(S[j][2], S[j][3]));
        }
        mx0 = fmaxf(mx0, __shfl_xor_sync(0xffffffffu, mx0, 1));
        mx0 = fmaxf(mx0, __shfl_xor_sync(0xffffffffu, mx0, 2));
        mx1 = fmaxf(mx1, __shfl_xor_sync(0xffffffffu, mx1, 1));
        mx1 = fmaxf(mx1, __shfl_xor_sync(0xffffffffu, mx1, 2));
        float mn0 = fmaxf(mr0, mx0), mn1 = fmaxf(mr1, mx1);
        float sc0 = expf(mr0 - mn0), sc1 = expf(mr1 - mn1);
        mr0 = mn0; mr1 = mn1;

        uint32_t ph[4][4], pl[4][4];
        float rs0 = 0.f, rs1 = 0.f;
        #pragma unroll
        for (int j = 0; j < 8; j++) {
            float p0 = expf(S[j][0] - mn0), p1 = expf(S[j][1] - mn0);
            float p2 = expf(S[j][2] - mn1), p3 = expf(S[j][3] - mn1);
            rs0 += p0 + p1; rs1 += p2 + p3;
            float h0 = __bfloat162float(__float2bfloat16(p0));
            float h1 = __bfloat162float(__float2bfloat16(p1));
            float h2 = __bfloat162float(__float2bfloat16(p2));
            float h3 = __bfloat162float(__float2bfloat16(p3));
            int kt2 = j >> 1, hb = (j & 1)*2;
            ph[kt2][hb]   = pack_bf2(h0, h1);
            ph[kt2][hb+1] = pack_bf2(h2, h3);
            pl[kt2][hb]   = pack_bf2(p0 - h0, p1 - h1);
            pl[kt2][hb+1] = pack_bf2(p2 - h2, p3 - h3);
        }
        rs0 += __shfl_xor_sync(0xffffffffu, rs0, 1);
        rs0 += __shfl_xor_sync(0xffffffffu, rs0, 2);
        rs1 += __shfl_xor_sync(0xffffffffu, rs1, 1);
        rs1 += __shfl_xor_sync(0xffffffffu, rs1, 2);
        l0 = l0*sc0 + rs0;
        l1 = l1*sc1 + rs1;

        #pragma unroll
        for (int j = 0; j < 8; j++) {
            o[j][0] *= sc0; o[j][1] *= sc0;
            o[j][2] *= sc1; o[j][3] *= sc1;
        }

        #pragma unroll
        for (int kt2 = 0; kt2 < 4; kt2++) {
            #pragma unroll
            for (int g = 0; g < 4; g++) {
                uint32_t off = ((kt2*16 + vRow)*72 + g*16 + vCol)*2;
                uint32_t h0,h1,h2,h3, e0,e1,e2,e3;
                ldsm_x4_t(h0,h1,h2,h3, stg + 2*FA_MATB + off);
                ldsm_x4_t(e0,e1,e2,e3, stg + 3*FA_MATB + off);
                mma_bf16(o[2*g],   ph[kt2], h0, h1);
                mma_bf16(o[2*g],   ph[kt2], e0, e1);
                mma_bf16(o[2*g],   pl[kt2], h0, h1);
                mma_bf16(o[2*g+1], ph[kt2], h2, h3);
                mma_bf16(o[2*g+1], ph[kt2], e2, e3);
                mma_bf16(o[2*g+1], pl[kt2], h2, h3);
            }
        }
        __syncthreads();
    }

    float inv0 = 1.f/l0, inv1 = 1.f/l1;
    int r0 = mt*96 + w*16 + (lane >> 2);
    int r1 = r0 + 8;
    #pragma unroll
    for (int j = 0; j < 8; j++) {
        int d = hh*HD + j*8 + (lane & 3)*2;
        if (r0 < SEQ)
            *(float2*)(g_ctx + (size_t)(b*SEQ + r0)*DIM + d) =
                make_float2(o[j][0]*inv0, o[j][1]*inv0);
        if (r1 < SEQ)
            *(float2*)(g_ctx + (size_t)(b*SEQ + r1)*DIM + d) =
                make_float2(o[j][2]*inv1, o[j][3]*inv1);
    }
}

/* ---------------- launch ---------------- */
extern "C" void kernel_launch(void* const* d_in, const int* in_sizes, int n_in,
                              void* d_out, int out_size)
{
    const float* x   = (const float*)d_in[0];
    const float* gw1 = (const float*)d_in[1];
    const float* gb1 = (const float*)d_in[2];
    const float* gw2 = (const float*)d_in[3];
    const float* gb2 = (const float*)d_in[4];
    const float* Wm[4] = {(const float*)d_in[5],  (const float*)d_in[10],
                          (const float*)d_in[15], (const float*)d_in[20]};
    const float* Uu[4] = {(const float*)d_in[6],  (const float*)d_in[11],
                          (const float*)d_in[16], (const float*)d_in[21]};
    const float* Ss[4] = {(const float*)d_in[7],  (const float*)d_in[12],
                          (const float*)d_in[17], (const float*)d_in[22]};
    const float* Vv[4] = {(const float*)d_in[8],  (const float*)d_in[13],
                          (const float*)d_in[18], (const float*)d_in[23]};
    const float* bbv[4] = {(const float*)d_in[9],  (const float*)d_in[14],
                           (const float*)d_in[19], (const float*)d_in[24]};
    float* out = (float*)d_out;

    cudaFuncSetAttribute(mm_kernel, cudaFuncAttributeMaxDynamicSharedMemorySize, MM_SMEM);
    cudaFuncSetAttribute(fa_kernel, cudaFuncAttributeMaxDynamicSharedMemorySize, FA_SMEM);
    cudaFuncSetAttribute(xvmma_kernel, cudaFuncAttributeMaxDynamicSharedMemorySize, XV_SMEM);

    gating_kernel<<<BB, 256>>>(x, gw1, gb1, gw2, gb2);

    int nx4 = BSQ*DIM/4;
    int nw4 = DIM*DIM/4;
    conv_kernel<<<(nx4 + 255)/256, 256>>>(x, 0, nx4);
    for (int p = 0; p < 4; p++)
        conv_kernel<<<(nw4 + 255)/256, 256>>>(Wm[p], p + 1, nw4);

    dim3 gmm(8, 65);
    dim3 gxv(3, BB);
    dim3 gadd(3, 8, BB);

    for (int p = 0; p < 3; p++) {
        vconv_kernel<<<dim3(BB, 32), 256>>>(Vv[p], Ss[p]);
        uconv_kernel<<<dim3(BB, 4), 256>>>(Uu[p]);
        xvmma_kernel<<<gxv, 192, XV_SMEM>>>();
        mm_kernel<<<gmm, 256, MM_SMEM>>>(p, bbv[p], nullptr, p);
        addmma_kernel<<<gadd, 192>>>(nullptr, (p == 0) ? QSCALE : 1.0f, p);
    }

    fa_kernel<<<dim3(3, BB*NH), 192, FA_SMEM>>>();

    conv_kernel<<<(nx4 + 255)/256, 256>>>(nullptr, 5, nx4);
    vconv_kernel<<<dim3(BB, 32), 256>>>(Vv[3], Ss[3]);
    uconv_kernel<<<dim3(BB, 4), 256>>>(Uu[3]);
    xvmma_kernel<<<gxv, 192, XV_SMEM>>>();
    mm_kernel<<<gmm, 256, MM_SMEM>>>(3, bbv[3], out, 3);
    addmma_kernel<<<gadd, 192>>>(out, 1.0f, 3);
}

// round 8
// speedup vs baseline: 3.3560x; 1.1158x over previous
#include <cuda_runtime.h>
#include <cuda_bf16.h>
#include <cstdint>
#include <math.h>

#define BB   32
#define SEQ  257
#define SEQP 320
#define DIM  1024
#define NH   16
#define HD   64
#define NEXP 8
#define RNK  16
#define GHID 256
#define BSQ  (BB*SEQ)          /* 8224 tokens */
#define QSCALE 0.125f

/* ---------------- scratch (device globals; no allocations) ---------------- */
static __device__ float g_q  [(size_t)BSQ*DIM];
static __device__ float g_k  [(size_t)BSQ*DIM];
static __device__ float g_v  [(size_t)BSQ*DIM];
static __device__ float g_ctx[(size_t)BSQ*DIM];
static __device__ float g_gates[BB*2];
static __device__ int   g_idx  [BB*2];
static __device__ __align__(16) __nv_bfloat16 g_xh[(size_t)BSQ*DIM];
static __device__ __align__(16) __nv_bfloat16 g_xl[(size_t)BSQ*DIM];
static __device__ __align__(16) __nv_bfloat16 g_wh[(size_t)4*DIM*DIM];
static __device__ __align__(16) __nv_bfloat16 g_wl[(size_t)4*DIM*DIM];
/* per-projection combined expert V rows (gate*S folded), U cols */
static __device__ __align__(16) __nv_bfloat16 g_vbh[(size_t)4*BB*32*DIM];
static __device__ __align__(16) __nv_bfloat16 g_vbl[(size_t)4*BB*32*DIM];
static __device__ __align__(16) __nv_bfloat16 g_ubh[(size_t)4*BB*DIM*32];
static __device__ __align__(16) __nv_bfloat16 g_ubl[(size_t)4*BB*DIM*32];
/* xv per projection: [p][b][t<SEQP][32] hi/lo */
static __device__ __align__(16) __nv_bfloat16 g_xvh[(size_t)4*BB*SEQP*32];
static __device__ __align__(16) __nv_bfloat16 g_xvl[(size_t)4*BB*SEQP*32];
/* attention bf16 operands: [bh][s(0..SEQP)][64]; pad rows stay .bss-zero */
static __device__ __align__(16) __nv_bfloat16 g_aqh[(size_t)BB*NH*SEQP*HD];
static __device__ __align__(16) __nv_bfloat16 g_aql[(size_t)BB*NH*SEQP*HD];
static __device__ __align__(16) __nv_bfloat16 g_akh[(size_t)BB*NH*SEQP*HD];
static __device__ __align__(16) __nv_bfloat16 g_akl[(size_t)BB*NH*SEQP*HD];
static __device__ __align__(16) __nv_bfloat16 g_avh[(size_t)BB*NH*SEQP*HD];
static __device__ __align__(16) __nv_bfloat16 g_avl[(size_t)BB*NH*SEQP*HD];

/* ---------------- small PTX helpers ---------------- */
__device__ __forceinline__ uint32_t smem_u32(const void* p) {
    uint32_t a;
    asm("{ .reg .u64 t; cvta.to.shared.u64 t, %1; cvt.u32.u64 %0, t; }" : "=r"(a) : "l"(p));
    return a;
}
__device__ __forceinline__ void cp16(uint32_t dst, const void* src, int srcBytes) {
    asm volatile("cp.async.cg.shared.global [%0], [%1], 16, %2;"
                 :: "r"(dst), "l"(src), "r"(srcBytes) : "memory");
}
#define CP_COMMIT() asm volatile("cp.async.commit_group;" ::: "memory")
#define CP_WAIT0()  asm volatile("cp.async.wait_group 0;" ::: "memory")
#define CP_WAIT1()  asm volatile("cp.async.wait_group 1;" ::: "memory")

__device__ __forceinline__ void ldsm_x4(uint32_t& r0, uint32_t& r1, uint32_t& r2, uint32_t& r3,
                                        uint32_t addr) {
    asm volatile("ldmatrix.sync.aligned.m8n8.x4.shared.b16 {%0,%1,%2,%3}, [%4];"
                 : "=r"(r0), "=r"(r1), "=r"(r2), "=r"(r3) : "r"(addr));
}
__device__ __forceinline__ void ldsm_x4_t(uint32_t& r0, uint32_t& r1, uint32_t& r2, uint32_t& r3,
                                          uint32_t addr) {
    asm volatile("ldmatrix.sync.aligned.m8n8.x4.trans.shared.b16 {%0,%1,%2,%3}, [%4];"
                 : "=r"(r0), "=r"(r1), "=r"(r2), "=r"(r3) : "r"(addr));
}
__device__ __forceinline__ void mma_bf16(float* c, const uint32_t* a, uint32_t b0, uint32_t b1) {
    asm volatile("mma.sync.aligned.m16n8k16.row.col.f32.bf16.bf16.f32 "
                 "{%0,%1,%2,%3}, {%4,%5,%6,%7}, {%8,%9}, {%0,%1,%2,%3};"
                 : "+f"(c[0]), "+f"(c[1]), "+f"(c[2]), "+f"(c[3])
                 : "r"(a[0]), "r"(a[1]), "r"(a[2]), "r"(a[3]), "r"(b0), "r"(b1));
}
__device__ __forceinline__ uint32_t pack_bf2(float lo, float hi) {
    __nv_bfloat16 l = __float2bfloat16(lo), h = __float2bfloat16(hi);
    return ((uint32_t)__bfloat16_as_ushort(h) << 16) | (uint32_t)__bfloat16_as_ushort(l);
}

/* ---------------- gating ---------------- */
__global__ void gating_kernel(const float* __restrict__ x,
                              const float* __restrict__ gw1, const float* __restrict__ gb1,
                              const float* __restrict__ gw2, const float* __restrict__ gb2)
{
    int b = blockIdx.x;
    __shared__ float pooled[DIM];
    __shared__ float h[GHID];
    __shared__ float logits[NEXP];
    int tid = threadIdx.x;
    for (int d = tid; d < DIM; d += 256) {
        float s = 0.f;
        const float* xp = x + (size_t)b*SEQ*DIM + d;
        for (int t = 0; t < SEQ; t++) s += xp[(size_t)t*DIM];
        pooled[d] = s * (1.0f/SEQ);
    }
    __syncthreads();
    {
        float a = gb1[tid];
        const float* w = gw1 + (size_t)tid*DIM;
        #pragma unroll 4
        for (int d = 0; d < DIM; d++) a += pooled[d]*w[d];
        h[tid] = fmaxf(a, 0.f);
    }
    __syncthreads();
    if (tid < NEXP) {
        float a = gb2[tid];
        const float* w = gw2 + tid*GHID;
        for (int d = 0; d < GHID; d++) a += h[d]*w[d];
        logits[tid] = a;
    }
    __syncthreads();
    if (tid == 0) {
        int i0 = 0;
        for (int e = 1; e < NEXP; e++) if (logits[e] > logits[i0]) i0 = e;
        int i1 = -1;
        for (int e = 0; e < NEXP; e++) {
            if (e == i0) continue;
            if (i1 < 0 || logits[e] > logits[i1]) i1 = e;
        }
        float v0 = logits[i0], v1 = logits[i1];
        float e0 = expf(v0 - v0), e1 = expf(v1 - v0);
        float inv = 1.f/(e0 + e1);
        g_gates[b*2]   = e0*inv;
        g_gates[b*2+1] = e1*inv;
        g_idx[b*2]   = i0;
        g_idx[b*2+1] = i1;
    }
}

/* ---------------- fp32 -> (bf16 hi, bf16 lo) ---------------- */
__global__ void conv_kernel(const float* __restrict__ srcExt, int which, int n4)
{
    const float* s;
    __nv_bfloat16 *H, *L;
    if (which == 0)      { s = srcExt; H = g_xh; L = g_xl; }
    else if (which <= 4) { s = srcExt;
                           H = g_wh + (size_t)(which-1)*DIM*DIM;
                           L = g_wl + (size_t)(which-1)*DIM*DIM; }
    else                 { s = g_ctx; H = g_xh; L = g_xl; }
    int i = blockIdx.x*256 + threadIdx.x;
    if (i >= n4) return;
    float4 v = ((const float4*)s)[i];
    ushort4 hh, ll;
    __nv_bfloat16 t;
    t = __float2bfloat16(v.x); hh.x = __bfloat16_as_ushort(t);
    ll.x = __bfloat16_as_ushort(__float2bfloat16(v.x - __bfloat162float(t)));
    t = __float2bfloat16(v.y); hh.y = __bfloat16_as_ushort(t);
    ll.y = __bfloat16_as_ushort(__float2bfloat16(v.y - __bfloat162float(t)));
    t = __float2bfloat16(v.z); hh.z = __bfloat16_as_ushort(t);
    ll.z = __bfloat16_as_ushort(__float2bfloat16(v.z - __bfloat162float(t)));
    t = __float2bfloat16(v.w); hh.w = __bfloat16_as_ushort(t);
    ll.w = __bfloat16_as_ushort(__float2bfloat16(v.w - __bfloat162float(t)));
    ((ushort4*)H)[i] = hh;
    ((ushort4*)L)[i] = ll;
}

/* ---------------- vconv: gather+scale V rows, split bf16 ------------------ */
__global__ void vconv_kernel(const float* __restrict__ Vm, const float* __restrict__ Sm, int p)
{
    int b = blockIdx.x, j = blockIdx.y;
    int half = j >> 4, r = j & 15;
    int e = g_idx[b*2 + half];
    float sc = g_gates[b*2 + half] * Sm[e*RNK + r];
    float4 v = ((const float4*)(Vm + ((size_t)e*RNK + r)*DIM))[threadIdx.x];
    v.x *= sc; v.y *= sc; v.z *= sc; v.w *= sc;
    ushort4 hh, ll;
    __nv_bfloat16 t;
    t = __float2bfloat16(v.x); hh.x = __bfloat16_as_ushort(t);
    ll.x = __bfloat16_as_ushort(__float2bfloat16(v.x - __bfloat162float(t)));
    t = __float2bfloat16(v.y); hh.y = __bfloat16_as_ushort(t);
    ll.y = __bfloat16_as_ushort(__float2bfloat16(v.y - __bfloat162float(t)));
    t = __float2bfloat16(v.z); hh.z = __bfloat16_as_ushort(t);
    ll.z = __bfloat16_as_ushort(__float2bfloat16(v.z - __bfloat162float(t)));
    t = __float2bfloat16(v.w); hh.w = __bfloat16_as_ushort(t);
    ll.w = __bfloat16_as_ushort(__float2bfloat16(v.w - __bfloat162float(t)));
    size_t o = ((size_t)p*BB*32 + (size_t)b*32 + j)*DIM/4 + threadIdx.x;
    ((ushort4*)g_vbh)[o] = hh;
    ((ushort4*)g_vbl)[o] = ll;
}

/* ---------------- uconv: gather U cols per batch, split bf16 -------------- */
__global__ void uconv_kernel(const float* __restrict__ U, int p)
{
    int b = blockIdx.x;
    int n = blockIdx.y*256 + threadIdx.x;
    int i0 = g_idx[b*2], i1 = g_idx[b*2+1];
    const float* u0 = U + ((size_t)i0*DIM + n)*RNK;
    const float* u1 = U + ((size_t)i1*DIM + n)*RNK;
    __nv_bfloat16* H = g_ubh + ((size_t)p*BB*DIM + (size_t)b*DIM + n)*32;
    __nv_bfloat16* L = g_ubl + ((size_t)p*BB*DIM + (size_t)b*DIM + n)*32;
    #pragma unroll
    for (int r = 0; r < 16; r++) {
        float v0 = u0[r], v1 = u1[r];
        __nv_bfloat16 h0 = __float2bfloat16(v0);
        H[r]      = h0;
        L[r]      = __float2bfloat16(v0 - __bfloat162float(h0));
        __nv_bfloat16 h1 = __float2bfloat16(v1);
        H[16 + r] = h1;
        L[16 + r] = __float2bfloat16(v1 - __bfloat162float(h1));
    }
}

/* ---------------- HMMA split-bf16 GEMM: Y = X @ W^T + bias ---------------- */
#define MAT_BYTES (128*40*2)            /* 10240 */
#define STG_BYTES (4*MAT_BYTES)         /* 40960 */
#define MM_SMEM   (2*STG_BYTES)         /* 81920 */

__device__ __forceinline__ void mm_load_stage(uint32_t sb, int buf, int k0,
    const __nv_bfloat16* Ah, const __nv_bfloat16* Al,
    const __nv_bfloat16* Bh, const __nv_bfloat16* Bl,
    int m0, int n0, int tid)
{
    uint32_t base = sb + buf*STG_BYTES;
    const __nv_bfloat16* srcs[4] = {Ah, Al, Bh, Bl};
    #pragma unroll
    for (int i = 0; i < 8; i++) {
        int c = tid + 256*i;
        int mat = c >> 9;
        int cc  = c & 511;
        int row = cc >> 2;
        int col = (cc & 3) * 8;
        const __nv_bfloat16* p = srcs[mat];
        int grow = ((mat < 2) ? m0 : n0) + row;
        int ok = (mat >= 2) || (grow < BSQ);
        const void* src = p + ((size_t)(ok ? grow : 0))*DIM + k0 + col;
        uint32_t dst = base + mat*MAT_BYTES + (uint32_t)(row*40 + col)*2;
        cp16(dst, src, ok ? 16 : 0);
    }
}

__global__ void __launch_bounds__(256, 2) mm_kernel(int base_code,
    const float* __restrict__ bias0, const float* __restrict__ bias1,
    const float* __restrict__ bias2, float* __restrict__ Yext)
{
    extern __shared__ __align__(128) char smem[];
    int code = (base_code < 0) ? (int)blockIdx.z : base_code;
    const __nv_bfloat16* Ah = g_xh;
    const __nv_bfloat16* Al = g_xl;
    const __nv_bfloat16* Bh = g_wh + (size_t)code*DIM*DIM;
    const __nv_bfloat16* Bl = g_wl + (size_t)code*DIM*DIM;
    const float* bias = (code==0)?bias0:(code==1)?bias1:(code==2)?bias2:bias0;
    float* Y = (code==0)?g_q:(code==1)?g_k:(code==2)?g_v:Yext;

    uint32_t sb = smem_u32(smem);
    int tid = threadIdx.x;
    int lane = tid & 31;
    int wid = tid >> 5;
    int warp_m = wid >> 2;
    int warp_n = wid & 3;
    int n0 = blockIdx.x*128, m0 = blockIdx.y*128;

    float acc[4][4][4];
    #pragma unroll
    for (int i = 0; i < 4; i++)
        #pragma unroll
        for (int j = 0; j < 4; j++)
            #pragma unroll
            for (int q = 0; q < 4; q++) acc[i][j][q] = 0.f;

    uint32_t aRow = (uint32_t)(warp_m*64 + (lane & 15));
    uint32_t aCol = (uint32_t)((lane >> 4) * 8);
    uint32_t bRowBase = (uint32_t)(warp_n*32 + (lane & 7) + ((lane >> 4) << 3));
    uint32_t bCol = (uint32_t)(((lane >> 3) & 1) * 8);

    mm_load_stage(sb, 0, 0, Ah, Al, Bh, Bl, m0, n0, tid);
    CP_COMMIT();

    const int NK = DIM/32;
    for (int s = 0; s < NK; s++) {
        if (s + 1 < NK) {
            mm_load_stage(sb, (s+1)&1, (s+1)*32, Ah, Al, Bh, Bl, m0, n0, tid);
            CP_COMMIT();
            CP_WAIT1();
        } else {
            CP_WAIT0();
        }
        __syncthreads();

        uint32_t stg = sb + (s&1)*STG_BYTES;
        #pragma unroll
        for (int kk = 0; kk < 32; kk += 16) {
            uint32_t ah[4][4], al[4][4], bh[8], bl[8];
            #pragma unroll
            for (int i = 0; i < 4; i++) {
                uint32_t off = ((aRow + i*16)*40 + kk + aCol)*2;
                ldsm_x4(ah[i][0], ah[i][1], ah[i][2], ah[i][3], stg + 0*MAT_BYTES + off);
                ldsm_x4(al[i][0], al[i][1], al[i][2], al[i][3], stg + 1*MAT_BYTES + off);
            }
            #pragma unroll
            for (int g = 0; g < 2; g++) {
                uint32_t off = ((bRowBase + g*16)*40 + kk + bCol)*2;
                ldsm_x4(bh[g*4+0], bh[g*4+1], bh[g*4+2], bh[g*4+3], stg + 2*MAT_BYTES + off);
                ldsm_x4(bl[g*4+0], bl[g*4+1], bl[g*4+2], bl[g*4+3], stg + 3*MAT_BYTES + off);
            }
            #pragma unroll
            for (int i = 0; i < 4; i++) {
                #pragma unroll
                for (int j = 0; j < 4; j++) {
                    mma_bf16(acc[i][j], ah[i], bh[j*2], bh[j*2+1]);
                    mma_bf16(acc[i][j], ah[i], bl[j*2], bl[j*2+1]);
                    mma_bf16(acc[i][j], al[i], bh[j*2], bh[j*2+1]);
                }
            }
        }
        __syncthreads();
    }

    #pragma unroll
    for (int j = 0; j < 4; j++) {
        int col = n0 + warp_n*32 + j*8 + (lane & 3)*2;
        float b0 = bias[col], b1 = bias[col+1];
        #pragma unroll
        for (int i = 0; i < 4; i++) {
            int r0 = m0 + warp_m*64 + i*16 + (lane >> 2);
            if (r0 < BSQ) {
                float2 o = make_float2(acc[i][j][0] + b0, acc[i][j][1] + b1);
                *(float2*)(Y + (size_t)r0*DIM + col) = o;
            }
            int r1 = r0 + 8;
            if (r1 < BSQ) {
                float2 o = make_float2(acc[i][j][2] + b0, acc[i][j][3] + b1);
                *(float2*)(Y + (size_t)r1*DIM + col) = o;
            }
        }
    }
}

/* ---------------- xvmma: xv = X @ Vb^T (HMMA split), out bf16 hi/lo ------- */
#define XV_ABYT 13824                 /* 96*72*2 */
#define XV_BBYT 4608                  /* 32*72*2 */
#define XV_STGB (2*XV_ABYT + 2*XV_BBYT)   /* 36864 */
#define XV_SMEM (2*XV_STGB)               /* 73728 */

__device__ __forceinline__ void xv_load_stage(uint32_t sb, int buf, int k0,
                                              int b, int mt, int tid, int p)
{
    uint32_t base = sb + buf*XV_STGB;
    size_t vboff = (size_t)p*BB*32*DIM;
    #pragma unroll
    for (int i = 0; i < 11; i++) {
        int c = tid + 192*i;
        if (c >= 2048) break;
        if (c < 1536) {
            int mat = (c >= 768);
            int cc = c - (mat ? 768 : 0);
            int row = cc >> 3, col8 = (cc & 7)*8;
            int t = mt*96 + row;
            int ok = t < SEQ;
            const __nv_bfloat16* src = (mat ? g_xl : g_xh) +
                ((size_t)b*SEQ + (ok ? t : 0))*DIM + k0 + col8;
            cp16(base + mat*XV_ABYT + (uint32_t)(row*72 + col8)*2, src, ok ? 16 : 0);
        } else {
            int c2 = c - 1536;
            int mat = c2 >> 8;
            int cc = c2 & 255;
            int row = cc >> 3, col8 = (cc & 7)*8;
            const __nv_bfloat16* src = (mat ? g_vbl : g_vbh) + vboff +
                ((size_t)b*32 + row)*DIM + k0 + col8;
            cp16(base + 2*XV_ABYT + mat*XV_BBYT + (uint32_t)(row*72 + col8)*2, src, 16);
        }
    }
}

__global__ void __launch_bounds__(192, 1) xvmma_kernel(int p)
{
    extern __shared__ __align__(16) char xsm[];
    uint32_t sb = smem_u32(xsm);
    int tid = threadIdx.x, lane = tid & 31, w = tid >> 5;
    int mt = blockIdx.x, b = blockIdx.y;

    float acc[4][4];
    #pragma unroll
    for (int j = 0; j < 4; j++)
        #pragma unroll
        for (int q = 0; q < 4; q++) acc[j][q] = 0.f;

    uint32_t aRow = (uint32_t)(w*16 + (lane & 15));
    uint32_t aCol = (uint32_t)((lane >> 4)*8);
    uint32_t bRow = (uint32_t)((lane & 7) + ((lane >> 4) << 3));
    uint32_t bCol = (uint32_t)(((lane >> 3) & 1)*8);

    xv_load_stage(sb, 0, 0, b, mt, tid, p);
    CP_COMMIT();

    for (int s = 0; s < 16; s++) {
        if (s + 1 < 16) {
            xv_load_stage(sb, (s+1)&1, (s+1)*64, b, mt, tid, p);
            CP_COMMIT();
            CP_WAIT1();
        } else {
            CP_WAIT0();
        }
        __syncthreads();
        uint32_t stg = sb + (s&1)*XV_STGB;
        #pragma unroll
        for (int kt = 0; kt < 4; kt++) {
            uint32_t ah[4], al[4], bh2[8], bl2[8];
            uint32_t off = (aRow*72 + kt*16 + aCol)*2;
            ldsm_x4(ah[0], ah[1], ah[2], ah[3], stg + off);
            ldsm_x4(al[0], al[1], al[2], al[3], stg + XV_ABYT + off);
            #pragma unroll
            for (int g = 0; g < 2; g++) {
                uint32_t bo = ((bRow + g*16)*72 + kt*16 + bCol)*2;
                ldsm_x4(bh2[g*4+0], bh2[g*4+1], bh2[g*4+2], bh2[g*4+3],
                        stg + 2*XV_ABYT + bo);
                ldsm_x4(bl2[g*4+0], bl2[g*4+1], bl2[g*4+2], bl2[g*4+3],
                        stg + 2*XV_ABYT + XV_BBYT + bo);
            }
            #pragma unroll
            for (int j = 0; j < 4; j++) {
                mma_bf16(acc[j], ah, bh2[j*2], bh2[j*2+1]);
                mma_bf16(acc[j], ah, bl2[j*2], bl2[j*2+1]);
                mma_bf16(acc[j], al, bh2[j*2], bh2[j*2+1]);
            }
        }
        __syncthreads();
    }

    size_t xvoff = (size_t)p*BB*SEQP*32;
    int r0 = mt*96 + w*16 + (lane >> 2);
    int r1 = r0 + 8;
    #pragma unroll
    for (int j = 0; j < 4; j++) {
        int col = j*8 + (lane & 3)*2;
        if (r0 < SEQ) {
            float p0 = acc[j][0], p1 = acc[j][1];
            float h0 = __bfloat162float(__float2bfloat16(p0));
            float h1 = __bfloat162float(__float2bfloat16(p1));
            size_t o = xvoff + ((size_t)b*SEQP + r0)*32 + col;
            *(uint32_t*)(g_xvh + o) = pack_bf2(h0, h1);
            *(uint32_t*)(g_xvl + o) = pack_bf2(p0 - h0, p1 - h1);
        }
        if (r1 < SEQ) {
            float p0 = acc[j][2], p1 = acc[j][3];
            float h0 = __bfloat162float(__float2bfloat16(p0));
            float h1 = __bfloat162float(__float2bfloat16(p1));
            size_t o = xvoff + ((size_t)b*SEQP + r1)*32 + col;
            *(uint32_t*)(g_xvh + o) = pack_bf2(h0, h1);
            *(uint32_t*)(g_xvl + o) = pack_bf2(p0 - h0, p1 - h1);
        }
    }
}

/* ---------------- addmma: Y = (Ymm + xv @ Ub^T)*scale (HMMA, K=32) -------- */
#define AD_AB (96*40*2)               /* 7680 */
#define AD_BB (128*40*2)              /* 10240 */
#define AD_SMEM (2*AD_AB + 2*AD_BB)   /* 35840 */

__global__ void __launch_bounds__(192, 1) addmma_kernel(float* __restrict__ Yext,
                                                        float scale, int code)
{
    __shared__ __align__(16) char adsm[AD_SMEM];
    uint32_t sb = smem_u32(adsm);
    const float* Yin = (code==0)?g_q:(code==1)?g_k:(code==2)?g_v:Yext;
    __nv_bfloat16* Hd = (code==0)?g_aqh:(code==1)?g_akh:g_avh;
    __nv_bfloat16* Ld = (code==0)?g_aql:(code==1)?g_akl:g_avl;
    int tid = threadIdx.x, lane = tid & 31, w = tid >> 5;
    int mt = blockIdx.x, nt = blockIdx.y, b = blockIdx.z;
    size_t xvoff = (size_t)code*BB*SEQP*32;
    size_t uboff = (size_t)code*BB*DIM*32;

    #pragma unroll
    for (int i = 0; i < 10; i++) {
        int c = tid + 192*i;
        if (c >= 1792) break;
        if (c < 768) {
            int mat = (c >= 384);
            int cc = c - (mat ? 384 : 0);
            int row = cc >> 2, col8 = (cc & 3)*8;
            uint4 v = *(const uint4*)((mat ? g_xvl : g_xvh) + xvoff +
                        ((size_t)b*SEQP + mt*96 + row)*32 + col8);
            *(uint4*)(adsm + mat*AD_AB + (row*40 + col8)*2) = v;
        } else {
            int c2 = c - 768;
            int mat = (c2 >= 512);
            int cc = c2 - (mat ? 512 : 0);
            int row = cc >> 2, col8 = (cc & 3)*8;
            uint4 v = *(const uint4*)((mat ? g_ubl : g_ubh) + uboff +
                        ((size_t)b*DIM + nt*128 + row)*32 + col8);
            *(uint4*)(adsm + 2*AD_AB + mat*AD_BB + (row*40 + col8)*2) = v;
        }
    }
    __syncthreads();

    float acc[16][4];
    #pragma unroll
    for (int j = 0; j < 16; j++)
        #pragma unroll
        for (int q = 0; q < 4; q++) acc[j][q] = 0.f;

    uint32_t aRow = (uint32_t)(w*16 + (lane & 15));
    uint32_t aColb = (uint32_t)((lane >> 4)*8);
    uint32_t bRow = (uint32_t)((lane & 7) + ((lane >> 4) << 3));
    uint32_t bColb = (uint32_t)(((lane >> 3) & 1)*8);

    #pragma unroll
    for (int kt = 0; kt < 2; kt++) {
        uint32_t ah[4], al[4];
        uint32_t off = (aRow*40 + kt*16 + aColb)*2;
        ldsm_x4(ah[0], ah[1], ah[2], ah[3], sb + off);
        ldsm_x4(al[0], al[1], al[2], al[3], sb + AD_AB + off);
        #pragma unroll
        for (int g = 0; g < 8; g++) {
            uint32_t bo = ((bRow + g*16)*40 + kt*16 + bColb)*2;
            uint32_t bh[4], bl[4];
            ldsm_x4(bh[0], bh[1], bh[2], bh[3], sb + 2*AD_AB + bo);
            ldsm_x4(bl[0], bl[1], bl[2], bl[3], sb + 2*AD_AB + AD_BB + bo);
            #pragma unroll
            for (int r = 0; r < 2; r++) {
                int jj = g*2 + r;
                mma_bf16(acc[jj], ah, bh[r*2], bh[r*2+1]);
                mma_bf16(acc[jj], ah, bl[r*2], bl[r*2+1]);
                mma_bf16(acc[jj], al, bh[r*2], bh[r*2+1]);
            }
        }
    }

    int r0 = mt*96 + w*16 + (lane >> 2);
    int r1 = r0 + 8;
    #pragma unroll
    for (int j = 0; j < 16; j++) {
        int colg = nt*128 + j*8 + (lane & 3)*2;
        int hh = colg >> 6, d0 = colg & 63;
        #pragma unroll
        for (int half = 0; half < 2; half++) {
            int r = half ? r1 : r0;
            if (r >= SEQ) continue;
            float a0 = acc[j][half*2], a1 = acc[j][half*2 + 1];
            const float* yp = Yin + ((size_t)b*SEQ + r)*DIM + colg;
            float2 y = *(const float2*)yp;
            float v0 = (y.x + a0)*scale;
            float v1 = (y.y + a1)*scale;
            if (code == 3) {
                *(float2*)(Yext + ((size_t)b*SEQ + r)*DIM + colg) = make_float2(v0, v1);
            } else {
                float h0 = __bfloat162float(__float2bfloat16(v0));
                float h1 = __bfloat162float(__float2bfloat16(v1));
                size_t o = ((size_t)((b*NH + hh)*SEQP) + r)*HD + d0;
                *(uint32_t*)(Hd + o) = pack_bf2(h0, h1);
                *(uint32_t*)(Ld + o) = pack_bf2(v0 - h0, v1 - h1);
            }
        }
    }
}

/* ---------------- fused flash attention (KV chunk = 32, 9 chunks) --------- */
#define FA_QBYTES  13824
#define FA_MATB    4608             /* 32*72*2 */
#define FA_STGB    (4*FA_MATB)      /* 18432 */
#define FA_KVBASE  (2*FA_QBYTES)    /* 27648 */
#define FA_SMEM    (FA_KVBASE + 2*FA_STGB)   /* 64512 */
#define FA_NC      9                /* ceil(257/32) chunks */

__device__ __forceinline__ void fa_load_kv(uint32_t sb, int buf, int t0,
                                           int bh, int tid)
{
    uint32_t base = sb + FA_KVBASE + buf*FA_STGB;
    size_t goff = (size_t)bh*SEQP*HD + (size_t)t0*HD;
    const __nv_bfloat16* srcs[4] = {g_akh + goff, g_akl + goff, g_avh + goff, g_avl + goff};
    #pragma unroll
    for (int i = 0; i < 6; i++) {
        int c = tid + 192*i;
        if (c < 1024) {
            int mat = c >> 8, cc = c & 255;
            int row = cc >> 3, col8 = (cc & 7)*8;
            cp16(base + mat*FA_MATB + (uint32_t)(row*72 + col8)*2,
                 srcs[mat] + (size_t)row*HD + col8, 16);
        }
    }
}

__global__ void __launch_bounds__(192, 2) fa_kernel()
{
    extern __shared__ __align__(16) char fsm[];
    uint32_t sb = smem_u32(fsm);
    int tid = threadIdx.x, lane = tid & 31, w = tid >> 5;
    int mt = blockIdx.x, bh = blockIdx.y;
    int b = bh >> 4, hh = bh & 15;

    {
        const __nv_bfloat16* qs[2] = {g_aqh, g_aql};
        #pragma unroll
        for (int mat = 0; mat < 2; mat++) {
            const __nv_bfloat16* src = qs[mat] + ((size_t)bh*SEQP + mt*96)*HD;
            #pragma unroll
            for (int it = 0; it < 4; it++) {
                int c = tid + 192*it;
                int row = c >> 3, col8 = (c & 7)*8;
                uint4 v = *(const uint4*)(src + (size_t)row*HD + col8);
                *(uint4*)(fsm + mat*FA_QBYTES + (row*72 + col8)*2) = v;
            }
        }
    }
    fa_load_kv(sb, 0, 0, bh, tid);
    CP_COMMIT();
    __syncthreads();

    uint32_t qh[4][4], ql[4][4];
    {
        uint32_t aRow = (uint32_t)(w*16 + (lane & 15));
        uint32_t aCol = (uint32_t)((lane >> 4)*8);
        #pragma unroll
        for (int kt = 0; kt < 4; kt++) {
            uint32_t off = (aRow*72 + kt*16 + aCol)*2;
            ldsm_x4(qh[kt][0], qh[kt][1], qh[kt][2], qh[kt][3], sb + off);
            ldsm_x4(ql[kt][0], ql[kt][1], ql[kt][2], ql[kt][3], sb + FA_QBYTES + off);
        }
    }

    float o[8][4];
    #pragma unroll
    for (int j = 0; j < 8; j++)
        #pragma unroll
        for (int q = 0; q < 4; q++) o[j][q] = 0.f;
    float mr0 = -1e30f, mr1 = -1e30f, l0 = 0.f, l1 = 0.f;

    uint32_t kRow = (uint32_t)((lane & 7) + ((lane >> 4) << 3));
    uint32_t kCol = (uint32_t)(((lane >> 3) & 1)*8);
    uint32_t vRow = (uint32_t)(lane & 15);
    uint32_t vCol = (uint32_t)((lane >> 4) << 3);

    for (int c = 0; c < FA_NC; c++) {
        if (c + 1 < FA_NC) {
            fa_load_kv(sb, (c+1)&1, (c+1)*32, bh, tid);
            CP_COMMIT();
            CP_WAIT1();
        } else {
            CP_WAIT0();
        }
        __syncthreads();
        uint32_t stg = sb + FA_KVBASE + (c&1)*FA_STGB;

        float S[4][4];
        #pragma unroll
        for (int j = 0; j < 4; j++)
            #pragma unroll
            for (int q = 0; q < 4; q++) S[j][q] = 0.f;

        #pragma unroll
        for (int kt = 0; kt < 4; kt++) {
            #pragma unroll
            for (int g = 0; g < 2; g++) {
                uint32_t off = ((kRow + g*16)*72 + kt*16 + kCol)*2;
                uint32_t h0,h1,h2,h3, e0,e1,e2,e3;
                ldsm_x4(h0,h1,h2,h3, stg + 0*FA_MATB + off);
                ldsm_x4(e0,e1,e2,e3, stg + 1*FA_MATB + off);
                mma_bf16(S[2*g],   qh[kt], h0, h1);
                mma_bf16(S[2*g],   qh[kt], e0, e1);
                mma_bf16(S[2*g],   ql[kt], h0, h1);
                mma_bf16(S[2*g+1], qh[kt], h2, h3);
                mma_bf16(S[2*g+1], qh[kt], e2, e3);
                mma_bf16(S[2*g+1], ql[kt], h2, h3);
            }
        }

        if (c == FA_NC - 1) {
            #pragma unroll
            for (int j = 0; j < 4; j++) {
                int tb = (FA_NC-1)*32 + j*8 + (lane & 3)*2;
                if (tb     >= SEQ) { S[j][0] = -1e30f; S[j][2] = -1e30f; }
                if (tb + 1 >= SEQ) { S[j][1] = -1e30f; S[j][3] = -1e30f; }
            }
        }

        float mx0 = -1e30f, mx1 = -1e30f;
        #pragma unroll
        for (int j = 0; j < 4; j++) {
            mx0 = fmaxf(mx0, fmaxf(S[j][0], S[j][1]));
            mx1 = fmaxf(mx1, fmaxf(S[j][2], S[j][3]));
        }
        mx0 = fmaxf(mx0, __shfl_xor_sync(0xffffffffu, mx0, 1));
        mx0 = fmaxf(mx0, __shfl_xor_sync(0xffffffffu, mx0, 2));
        mx1 = fmaxf(mx1, __shfl_xor_sync(0xffffffffu, mx1, 1));
        mx1 = fmaxf(mx1, __shfl_xor_sync(0xffffffffu, mx1, 2));
        float mn0 = fmaxf(mr0, mx0), mn1 = fmaxf(mr1, mx1);
        float sc0 = expf(mr0 - mn0), sc1 = expf(mr1 - mn1);
        mr0 = mn0; mr1 = mn1;

        uint32_t ph[2][4], pl[2][4];
        float rs0 = 0.f, rs1 = 0.f;
        #pragma unroll
        for (int j = 0; j < 4; j++) {
            float p0 = expf(S[j][0] - mn0), p1 = expf(S[j][1] - mn0);
            float p2 = expf(S[j][2] - mn1), p3 = expf(S[j][3] - mn1);
            rs0 += p0 + p1; rs1 += p2 + p3;
            float h0 = __bfloat162float(__float2bfloat16(p0));
            float h1 = __bfloat162float(__float2bfloat16(p1));
            float h2 = __bfloat162float(__float2bfloat16(p2));
            float h3 = __bfloat162float(__float2bfloat16(p3));
            int kt2 = j >> 1, hb = (j & 1)*2;
            ph[kt2][hb]   = pack_bf2(h0, h1);
            ph[kt2][hb+1] = pack_bf2(h2, h3);
            pl[kt2][hb]   = pack_bf2(p0 - h0, p1 - h1);
            pl[kt2][hb+1] = pack_bf2(p2 - h2, p3 - h3);
        }
        rs0 += __shfl_xor_sync(0xffffffffu, rs0, 1);
        rs0 += __shfl_xor_sync(0xffffffffu, rs0, 2);
        rs1 += __shfl_xor_sync(0xffffffffu, rs1, 1);
        rs1 += __shfl_xor_sync(0xffffffffu, rs1, 2);
        l0 = l0*sc0 + rs0;
        l1 = l1*sc1 + rs1;

        #pragma unroll
        for (int j = 0; j < 8; j++) {
            o[j][0] *= sc0; o[j][1] *= sc0;
            o[j][2] *= sc1; o[j][3] *= sc1;
        }

        #pragma unroll
        for (int kt2 = 0; kt2 < 2; kt2++) {
            #pragma unroll
            for (int g = 0; g < 4; g++) {
                uint32_t off = ((kt2*16 + vRow)*72 + g*16 + vCol)*2;
                uint32_t h0,h1,h2,h3, e0,e1,e2,e3;
                ldsm_x4_t(h0,h1,h2,h3, stg + 2*FA_MATB + off);
                ldsm_x4_t(e0,e1,e2,e3, stg + 3*FA_MATB + off);
                mma_bf16(o[2*g],   ph[kt2], h0, h1);
                mma_bf16(o[2*g],   ph[kt2], e0, e1);
                mma_bf16(o[2*g],   pl[kt2], h0, h1);
                mma_bf16(o[2*g+1], ph[kt2], h2, h3);
                mma_bf16(o[2*g+1], ph[kt2], e2, e3);
                mma_bf16(o[2*g+1], pl[kt2], h2, h3);
            }
        }
        __syncthreads();
    }

    float inv0 = 1.f/l0, inv1 = 1.f/l1;
    int r0 = mt*96 + w*16 + (lane >> 2);
    int r1 = r0 + 8;
    #pragma unroll
    for (int j = 0; j < 8; j++) {
        int d = hh*HD + j*8 + (lane & 3)*2;
        if (r0 < SEQ)
            *(float2*)(g_ctx + (size_t)(b*SEQ + r0)*DIM + d) =
                make_float2(o[j][0]*inv0, o[j][1]*inv0);
        if (r1 < SEQ)
            *(float2*)(g_ctx + (size_t)(b*SEQ + r1)*DIM + d) =
                make_float2(o[j][2]*inv1, o[j][3]*inv1);
    }
}

/* ---------------- launch ---------------- */
extern "C" void kernel_launch(void* const* d_in, const int* in_sizes, int n_in,
                              void* d_out, int out_size)
{
    const float* x   = (const float*)d_in[0];
    const float* gw1 = (const float*)d_in[1];
    const float* gb1 = (const float*)d_in[2];
    const float* gw2 = (const float*)d_in[3];
    const float* gb2 = (const float*)d_in[4];
    const float* Wm[4] = {(const float*)d_in[5],  (const float*)d_in[10],
                          (const float*)d_in[15], (const float*)d_in[20]};
    const float* Uu[4] = {(const float*)d_in[6],  (const float*)d_in[11],
                          (const float*)d_in[16], (const float*)d_in[21]};
    const float* Ss[4] = {(const float*)d_in[7],  (const float*)d_in[12],
                          (const float*)d_in[17], (const float*)d_in[22]};
    const float* Vv[4] = {(const float*)d_in[8],  (const float*)d_in[13],
                          (const float*)d_in[18], (const float*)d_in[23]};
    const float* bbv[4] = {(const float*)d_in[9],  (const float*)d_in[14],
                           (const float*)d_in[19], (const float*)d_in[24]};
    float* out = (float*)d_out;

    cudaFuncSetAttribute(mm_kernel, cudaFuncAttributeMaxDynamicSharedMemorySize, MM_SMEM);
    cudaFuncSetAttribute(fa_kernel, cudaFuncAttributeMaxDynamicSharedMemorySize, FA_SMEM);
    cudaFuncSetAttribute(xvmma_kernel, cudaFuncAttributeMaxDynamicSharedMemorySize, XV_SMEM);

    gating_kernel<<<BB, 256>>>(x, gw1, gb1, gw2, gb2);

    int nx4 = BSQ*DIM/4;
    int nw4 = DIM*DIM/4;
    conv_kernel<<<(nx4 + 255)/256, 256>>>(x, 0, nx4);
    for (int p = 0; p < 4; p++)
        conv_kernel<<<(nw4 + 255)/256, 256>>>(Wm[p], p + 1, nw4);

    for (int p = 0; p < 4; p++) {
        vconv_kernel<<<dim3(BB, 32), 256>>>(Vv[p], Ss[p], p);
        uconv_kernel<<<dim3(BB, 4), 256>>>(Uu[p], p);
    }
    for (int p = 0; p < 3; p++)
        xvmma_kernel<<<dim3(3, BB), 192, XV_SMEM>>>(p);

    dim3 gmm(8, 65, 3);
    mm_kernel<<<gmm, 256, MM_SMEM>>>(-1, bbv[0], bbv[1], bbv[2], nullptr);

    dim3 gadd(3, 8, BB);
    for (int p = 0; p < 3; p++)
        addmma_kernel<<<gadd, 192>>>(nullptr, (p == 0) ? QSCALE : 1.0f, p);

    fa_kernel<<<dim3(3, BB*NH), 192, FA_SMEM>>>();

    conv_kernel<<<(nx4 + 255)/256, 256>>>(nullptr, 5, nx4);
    xvmma_kernel<<<dim3(3, BB), 192, XV_SMEM>>>(3);
    mm_kernel<<<dim3(8, 65, 1), 256, MM_SMEM>>>(3, bbv[3], bbv[3], bbv[3], out);
    addmma_kernel<<<gadd, 192>>>(out, 1.0f, 3);
}

// round 9
// speedup vs baseline: 3.8783x; 1.1556x over previous
#include <cuda_runtime.h>
#include <cuda_bf16.h>
#include <cstdint>
#include <math.h>

#define BB   32
#define SEQ  257
#define SEQP 320
#define DIM  1024
#define NH   16
#define HD   64
#define NEXP 8
#define RNK  16
#define GHID 256
#define BSQ  (BB*SEQ)          /* 8224 tokens */
#define QSCALE 0.125f

/* ---------------- scratch (device globals; no allocations) ---------------- */
static __device__ float g_ctx[(size_t)BSQ*DIM];
static __device__ float g_gates[BB*2];
static __device__ int   g_idx  [BB*2];
static __device__ __align__(16) __nv_bfloat16 g_xh[(size_t)BSQ*DIM];
static __device__ __align__(16) __nv_bfloat16 g_xl[(size_t)BSQ*DIM];
static __device__ __align__(16) __nv_bfloat16 g_wh[(size_t)4*DIM*DIM];
static __device__ __align__(16) __nv_bfloat16 g_wl[(size_t)4*DIM*DIM];
/* per-projection combined expert V rows (gate*S folded), U cols */
static __device__ __align__(16) __nv_bfloat16 g_vbh[(size_t)4*BB*32*DIM];
static __device__ __align__(16) __nv_bfloat16 g_vbl[(size_t)4*BB*32*DIM];
static __device__ __align__(16) __nv_bfloat16 g_ubh[(size_t)4*BB*DIM*32];
static __device__ __align__(16) __nv_bfloat16 g_ubl[(size_t)4*BB*DIM*32];
/* xv per projection: [p][b][t<SEQP][32] hi/lo */
static __device__ __align__(16) __nv_bfloat16 g_xvh[(size_t)4*BB*SEQP*32];
static __device__ __align__(16) __nv_bfloat16 g_xvl[(size_t)4*BB*SEQP*32];
/* attention bf16 operands: [bh][s(0..SEQP)][64]; pad rows stay .bss-zero */
static __device__ __align__(16) __nv_bfloat16 g_aqh[(size_t)BB*NH*SEQP*HD];
static __device__ __align__(16) __nv_bfloat16 g_aql[(size_t)BB*NH*SEQP*HD];
static __device__ __align__(16) __nv_bfloat16 g_akh[(size_t)BB*NH*SEQP*HD];
static __device__ __align__(16) __nv_bfloat16 g_akl[(size_t)BB*NH*SEQP*HD];
static __device__ __align__(16) __nv_bfloat16 g_avh[(size_t)BB*NH*SEQP*HD];
static __device__ __align__(16) __nv_bfloat16 g_avl[(size_t)BB*NH*SEQP*HD];

/* ---------------- small PTX helpers ---------------- */
__device__ __forceinline__ uint32_t smem_u32(const void* p) {
    uint32_t a;
    asm("{ .reg .u64 t; cvta.to.shared.u64 t, %1; cvt.u32.u64 %0, t; }" : "=r"(a) : "l"(p));
    return a;
}
__device__ __forceinline__ void cp16(uint32_t dst, const void* src, int srcBytes) {
    asm volatile("cp.async.cg.shared.global [%0], [%1], 16, %2;"
                 :: "r"(dst), "l"(src), "r"(srcBytes) : "memory");
}
#define CP_COMMIT() asm volatile("cp.async.commit_group;" ::: "memory")
#define CP_WAIT0()  asm volatile("cp.async.wait_group 0;" ::: "memory")
#define CP_WAIT1()  asm volatile("cp.async.wait_group 1;" ::: "memory")

__device__ __forceinline__ void ldsm_x4(uint32_t& r0, uint32_t& r1, uint32_t& r2, uint32_t& r3,
                                        uint32_t addr) {
    asm volatile("ldmatrix.sync.aligned.m8n8.x4.shared.b16 {%0,%1,%2,%3}, [%4];"
                 : "=r"(r0), "=r"(r1), "=r"(r2), "=r"(r3) : "r"(addr));
}
__device__ __forceinline__ void ldsm_x4_t(uint32_t& r0, uint32_t& r1, uint32_t& r2, uint32_t& r3,
                                          uint32_t addr) {
    asm volatile("ldmatrix.sync.aligned.m8n8.x4.trans.shared.b16 {%0,%1,%2,%3}, [%4];"
                 : "=r"(r0), "=r"(r1), "=r"(r2), "=r"(r3) : "r"(addr));
}
__device__ __forceinline__ void mma_bf16(float* c, const uint32_t* a, uint32_t b0, uint32_t b1) {
    asm volatile("mma.sync.aligned.m16n8k16.row.col.f32.bf16.bf16.f32 "
                 "{%0,%1,%2,%3}, {%4,%5,%6,%7}, {%8,%9}, {%0,%1,%2,%3};"
                 : "+f"(c[0]), "+f"(c[1]), "+f"(c[2]), "+f"(c[3])
                 : "r"(a[0]), "r"(a[1]), "r"(a[2]), "r"(a[3]), "r"(b0), "r"(b1));
}
__device__ __forceinline__ uint32_t pack_bf2(float lo, float hi) {
    __nv_bfloat16 l = __float2bfloat16(lo), h = __float2bfloat16(hi);
    return ((uint32_t)__bfloat16_as_ushort(h) << 16) | (uint32_t)__bfloat16_as_ushort(l);
}

/* ---------------- gating ---------------- */
__global__ void gating_kernel(const float* __restrict__ x,
                              const float* __restrict__ gw1, const float* __restrict__ gb1,
                              const float* __restrict__ gw2, const float* __restrict__ gb2)
{
    int b = blockIdx.x;
    __shared__ float pooled[DIM];
    __shared__ float h[GHID];
    __shared__ float logits[NEXP];
    int tid = threadIdx.x;
    for (int d = tid; d < DIM; d += 256) {
        float s = 0.f;
        const float* xp = x + (size_t)b*SEQ*DIM + d;
        for (int t = 0; t < SEQ; t++) s += xp[(size_t)t*DIM];
        pooled[d] = s * (1.0f/SEQ);
    }
    __syncthreads();
    {
        float a = gb1[tid];
        const float* w = gw1 + (size_t)tid*DIM;
        #pragma unroll 4
        for (int d = 0; d < DIM; d++) a += pooled[d]*w[d];
        h[tid] = fmaxf(a, 0.f);
    }
    __syncthreads();
    if (tid < NEXP) {
        float a = gb2[tid];
        const float* w = gw2 + tid*GHID;
        for (int d = 0; d < GHID; d++) a += h[d]*w[d];
        logits[tid] = a;
    }
    __syncthreads();
    if (tid == 0) {
        int i0 = 0;
        for (int e = 1; e < NEXP; e++) if (logits[e] > logits[i0]) i0 = e;
        int i1 = -1;
        for (int e = 0; e < NEXP; e++) {
            if (e == i0) continue;
            if (i1 < 0 || logits[e] > logits[i1]) i1 = e;
        }
        float v0 = logits[i0], v1 = logits[i1];
        float e0 = expf(v0 - v0), e1 = expf(v1 - v0);
        float inv = 1.f/(e0 + e1);
        g_gates[b*2]   = e0*inv;
        g_gates[b*2+1] = e1*inv;
        g_idx[b*2]   = i0;
        g_idx[b*2+1] = i1;
    }
}

/* ---------------- fp32 -> (bf16 hi, bf16 lo) ---------------- */
__global__ void conv_kernel(const float* __restrict__ srcExt, int which, int n4)
{
    const float* s;
    __nv_bfloat16 *H, *L;
    if (which == 0)      { s = srcExt; H = g_xh; L = g_xl; }
    else if (which <= 4) { s = srcExt;
                           H = g_wh + (size_t)(which-1)*DIM*DIM;
                           L = g_wl + (size_t)(which-1)*DIM*DIM; }
    else                 { s = g_ctx; H = g_xh; L = g_xl; }
    int i = blockIdx.x*256 + threadIdx.x;
    if (i >= n4) return;
    float4 v = ((const float4*)s)[i];
    ushort4 hh, ll;
    __nv_bfloat16 t;
    t = __float2bfloat16(v.x); hh.x = __bfloat16_as_ushort(t);
    ll.x = __bfloat16_as_ushort(__float2bfloat16(v.x - __bfloat162float(t)));
    t = __float2bfloat16(v.y); hh.y = __bfloat16_as_ushort(t);
    ll.y = __bfloat16_as_ushort(__float2bfloat16(v.y - __bfloat162float(t)));
    t = __float2bfloat16(v.z); hh.z = __bfloat16_as_ushort(t);
    ll.z = __bfloat16_as_ushort(__float2bfloat16(v.z - __bfloat162float(t)));
    t = __float2bfloat16(v.w); hh.w = __bfloat16_as_ushort(t);
    ll.w = __bfloat16_as_ushort(__float2bfloat16(v.w - __bfloat162float(t)));
    ((ushort4*)H)[i] = hh;
    ((ushort4*)L)[i] = ll;
}

/* ---------------- vconv: gather+scale V rows, split bf16 ------------------ */
__global__ void vconv_kernel(const float* __restrict__ Vm, const float* __restrict__ Sm, int p)
{
    int b = blockIdx.x, j = blockIdx.y;
    int half = j >> 4, r = j & 15;
    int e = g_idx[b*2 + half];
    float sc = g_gates[b*2 + half] * Sm[e*RNK + r];
    float4 v = ((const float4*)(Vm + ((size_t)e*RNK + r)*DIM))[threadIdx.x];
    v.x *= sc; v.y *= sc; v.z *= sc; v.w *= sc;
    ushort4 hh, ll;
    __nv_bfloat16 t;
    t = __float2bfloat16(v.x); hh.x = __bfloat16_as_ushort(t);
    ll.x = __bfloat16_as_ushort(__float2bfloat16(v.x - __bfloat162float(t)));
    t = __float2bfloat16(v.y); hh.y = __bfloat16_as_ushort(t);
    ll.y = __bfloat16_as_ushort(__float2bfloat16(v.y - __bfloat162float(t)));
    t = __float2bfloat16(v.z); hh.z = __bfloat16_as_ushort(t);
    ll.z = __bfloat16_as_ushort(__float2bfloat16(v.z - __bfloat162float(t)));
    t = __float2bfloat16(v.w); hh.w = __bfloat16_as_ushort(t);
    ll.w = __bfloat16_as_ushort(__float2bfloat16(v.w - __bfloat162float(t)));
    size_t o = ((size_t)p*BB*32 + (size_t)b*32 + j)*DIM/4 + threadIdx.x;
    ((ushort4*)g_vbh)[o] = hh;
    ((ushort4*)g_vbl)[o] = ll;
}

/* ---------------- uconv: gather U cols per batch, split bf16 -------------- */
__global__ void uconv_kernel(const float* __restrict__ U, int p)
{
    int b = blockIdx.x;
    int n = blockIdx.y*256 + threadIdx.x;
    int i0 = g_idx[b*2], i1 = g_idx[b*2+1];
    const float* u0 = U + ((size_t)i0*DIM + n)*RNK;
    const float* u1 = U + ((size_t)i1*DIM + n)*RNK;
    __nv_bfloat16* H = g_ubh + ((size_t)p*BB*DIM + (size_t)b*DIM + n)*32;
    __nv_bfloat16* L = g_ubl + ((size_t)p*BB*DIM + (size_t)b*DIM + n)*32;
    #pragma unroll
    for (int r = 0; r < 16; r++) {
        float v0 = u0[r], v1 = u1[r];
        __nv_bfloat16 h0 = __float2bfloat16(v0);
        H[r]      = h0;
        L[r]      = __float2bfloat16(v0 - __bfloat162float(h0));
        __nv_bfloat16 h1 = __float2bfloat16(v1);
        H[16 + r] = h1;
        L[16 + r] = __float2bfloat16(v1 - __bfloat162float(h1));
    }
}

/* ---------------- fused GEMM: Y = (X@W^T + bias + xv@Ub^T) * scale -------- */
/* 128x128 tile, BK=32, 256 threads, double-buffered; rank-32 MoE correction
   fused as extra K-stage(s) (one per batch spanned by the tile).
   code 0/1/2 -> emit bf16 hi/lo attention operands; code 3 -> fp32 out.    */
#define MAT_BYTES (128*40*2)            /* 10240 */
#define STG_BYTES (4*MAT_BYTES)         /* 40960 */
#define MM_SMEM   (2*STG_BYTES)         /* 81920 */

__device__ __forceinline__ void mm_load_stage(uint32_t sb, int buf, int k0,
    const __nv_bfloat16* Ah, const __nv_bfloat16* Al,
    const __nv_bfloat16* Bh, const __nv_bfloat16* Bl,
    int m0, int n0, int tid)
{
    uint32_t base = sb + buf*STG_BYTES;
    const __nv_bfloat16* srcs[4] = {Ah, Al, Bh, Bl};
    #pragma unroll
    for (int i = 0; i < 8; i++) {
        int c = tid + 256*i;
        int mat = c >> 9;
        int cc  = c & 511;
        int row = cc >> 2;
        int col = (cc & 3) * 8;
        const __nv_bfloat16* p = srcs[mat];
        int grow = ((mat < 2) ? m0 : n0) + row;
        int ok = (mat >= 2) || (grow < BSQ);
        const void* src = p + ((size_t)(ok ? grow : 0))*DIM + k0 + col;
        uint32_t dst = base + mat*MAT_BYTES + (uint32_t)(row*40 + col)*2;
        cp16(dst, src, ok ? 16 : 0);
    }
}

__global__ void __launch_bounds__(256, 2) mm_kernel(int base_code,
    const float* __restrict__ bias0, const float* __restrict__ bias1,
    const float* __restrict__ bias2, float* __restrict__ Yext)
{
    extern __shared__ __align__(128) char smem[];
    int code = (base_code < 0) ? (int)blockIdx.z : base_code;
    const __nv_bfloat16* Ah = g_xh;
    const __nv_bfloat16* Al = g_xl;
    const __nv_bfloat16* Bh = g_wh + (size_t)code*DIM*DIM;
    const __nv_bfloat16* Bl = g_wl + (size_t)code*DIM*DIM;
    const float* bias = (code==0)?bias0:(code==1)?bias1:(code==2)?bias2:bias0;

    uint32_t sb = smem_u32(smem);
    int tid = threadIdx.x;
    int lane = tid & 31;
    int wid = tid >> 5;
    int warp_m = wid >> 2;
    int warp_n = wid & 3;
    int n0 = blockIdx.x*128, m0 = blockIdx.y*128;

    float acc[4][4][4];
    #pragma unroll
    for (int i = 0; i < 4; i++)
        #pragma unroll
        for (int j = 0; j < 4; j++)
            #pragma unroll
            for (int q = 0; q < 4; q++) acc[i][j][q] = 0.f;

    uint32_t aRow = (uint32_t)(warp_m*64 + (lane & 15));
    uint32_t aCol = (uint32_t)((lane >> 4) * 8);
    uint32_t bRowBase = (uint32_t)(warp_n*32 + (lane & 7) + ((lane >> 4) << 3));
    uint32_t bCol = (uint32_t)(((lane >> 3) & 1) * 8);

    mm_load_stage(sb, 0, 0, Ah, Al, Bh, Bl, m0, n0, tid);
    CP_COMMIT();

    const int NK = DIM/32;
    for (int s = 0; s < NK; s++) {
        if (s + 1 < NK) {
            mm_load_stage(sb, (s+1)&1, (s+1)*32, Ah, Al, Bh, Bl, m0, n0, tid);
            CP_COMMIT();
            CP_WAIT1();
        } else {
            CP_WAIT0();
        }
        __syncthreads();

        uint32_t stg = sb + (s&1)*STG_BYTES;
        #pragma unroll
        for (int kk = 0; kk < 32; kk += 16) {
            uint32_t ah[4][4], al[4][4], bh[8], bl[8];
            #pragma unroll
            for (int i = 0; i < 4; i++) {
                uint32_t off = ((aRow + i*16)*40 + kk + aCol)*2;
                ldsm_x4(ah[i][0], ah[i][1], ah[i][2], ah[i][3], stg + 0*MAT_BYTES + off);
                ldsm_x4(al[i][0], al[i][1], al[i][2], al[i][3], stg + 1*MAT_BYTES + off);
            }
            #pragma unroll
            for (int g = 0; g < 2; g++) {
                uint32_t off = ((bRowBase + g*16)*40 + kk + bCol)*2;
                ldsm_x4(bh[g*4+0], bh[g*4+1], bh[g*4+2], bh[g*4+3], stg + 2*MAT_BYTES + off);
                ldsm_x4(bl[g*4+0], bl[g*4+1], bl[g*4+2], bl[g*4+3], stg + 3*MAT_BYTES + off);
            }
            #pragma unroll
            for (int i = 0; i < 4; i++) {
                #pragma unroll
                for (int j = 0; j < 4; j++) {
                    mma_bf16(acc[i][j], ah[i], bh[j*2], bh[j*2+1]);
                    mma_bf16(acc[i][j], ah[i], bl[j*2], bl[j*2+1]);
                    mma_bf16(acc[i][j], al[i], bh[j*2], bh[j*2+1]);
                }
            }
        }
        __syncthreads();
    }

    /* ---- fused rank-32 MoE correction: one pass per batch in this tile ---- */
    {
        int mlast = m0 + 127; if (mlast >= BSQ) mlast = BSQ - 1;
        int bb0 = m0 / SEQ, bb1 = mlast / SEQ;
        for (int bb = bb0; bb <= bb1; bb++) {
            uint32_t base = sb + ((bb - bb0) & 1)*STG_BYTES;
            #pragma unroll
            for (int i2 = 0; i2 < 4; i2++) {
                int c = tid + 256*i2;
                int mat = c >> 9, cc = c & 511;
                int row = cc >> 2, col = (cc & 3)*8;
                int m = m0 + row;
                int ok = (m < BSQ) && (m / SEQ == bb);
                int t = m - bb*SEQ;
                const __nv_bfloat16* srcA = (mat ? g_xvl : g_xvh) +
                    (size_t)code*BB*SEQP*32 + ((size_t)bb*SEQP + (ok ? t : 0))*32 + col;
                cp16(base + mat*MAT_BYTES + (uint32_t)(row*40 + col)*2, srcA, ok ? 16 : 0);
            }
            #pragma unroll
            for (int i2 = 0; i2 < 4; i2++) {
                int c = tid + 256*i2;
                int mat = c >> 9, cc = c & 511;
                int row = cc >> 2, col = (cc & 3)*8;
                const __nv_bfloat16* srcB = (mat ? g_ubl : g_ubh) +
                    (size_t)code*BB*DIM*32 + ((size_t)bb*DIM + n0 + row)*32 + col;
                cp16(base + (2 + mat)*MAT_BYTES + (uint32_t)(row*40 + col)*2, srcB, 16);
            }
            CP_COMMIT();
            CP_WAIT0();
            __syncthreads();
            #pragma unroll
            for (int kk = 0; kk < 32; kk += 16) {
                uint32_t ah[4][4], al[4][4], bh[8], bl[8];
                #pragma unroll
                for (int i = 0; i < 4; i++) {
                    uint32_t off = ((aRow + i*16)*40 + kk + aCol)*2;
                    ldsm_x4(ah[i][0], ah[i][1], ah[i][2], ah[i][3], base + 0*MAT_BYTES + off);
                    ldsm_x4(al[i][0], al[i][1], al[i][2], al[i][3], base + 1*MAT_BYTES + off);
                }
                #pragma unroll
                for (int g = 0; g < 2; g++) {
                    uint32_t off = ((bRowBase + g*16)*40 + kk + bCol)*2;
                    ldsm_x4(bh[g*4+0], bh[g*4+1], bh[g*4+2], bh[g*4+3], base + 2*MAT_BYTES + off);
                    ldsm_x4(bl[g*4+0], bl[g*4+1], bl[g*4+2], bl[g*4+3], base + 3*MAT_BYTES + off);
                }
                #pragma unroll
                for (int i = 0; i < 4; i++) {
                    #pragma unroll
                    for (int j = 0; j < 4; j++) {
                        mma_bf16(acc[i][j], ah[i], bh[j*2], bh[j*2+1]);
                        mma_bf16(acc[i][j], ah[i], bl[j*2], bl[j*2+1]);
                        mma_bf16(acc[i][j], al[i], bh[j*2], bh[j*2+1]);
                    }
                }
            }
            __syncthreads();
        }
    }

    /* ---- epilogue: bias + scale, emit bf16 hi/lo (qkv) or fp32 (o) ------- */
    float scale = (code == 0) ? QSCALE : 1.0f;
    __nv_bfloat16* Hd = (code==0)?g_aqh:(code==1)?g_akh:g_avh;
    __nv_bfloat16* Ld = (code==0)?g_aql:(code==1)?g_akl:g_avl;
    #pragma unroll
    for (int j = 0; j < 4; j++) {
        int col = n0 + warp_n*32 + j*8 + (lane & 3)*2;
        float b0v = bias[col], b1v = bias[col+1];
        int hh = col >> 6, d0 = col & 63;
        #pragma unroll
        for (int i = 0; i < 4; i++) {
            #pragma unroll
            for (int half = 0; half < 2; half++) {
                int m = m0 + warp_m*64 + i*16 + (lane >> 2) + half*8;
                if (m >= BSQ) continue;
                float v0 = (acc[i][j][half*2]   + b0v)*scale;
                float v1 = (acc[i][j][half*2+1] + b1v)*scale;
                if (code == 3) {
                    *(float2*)(Yext + (size_t)m*DIM + col) = make_float2(v0, v1);
                } else {
                    int b = m / SEQ;
                    int t = m - b*SEQ;
                    float h0 = __bfloat162float(__float2bfloat16(v0));
                    float h1 = __bfloat162float(__float2bfloat16(v1));
                    size_t o = ((size_t)((b*NH + hh)*SEQP) + t)*HD + d0;
                    *(uint32_t*)(Hd + o) = pack_bf2(h0, h1);
                    *(uint32_t*)(Ld + o) = pack_bf2(v0 - h0, v1 - h1);
                }
            }
        }
    }
}

/* ---------------- xvmma: xv = X @ Vb^T (HMMA split), out bf16 hi/lo ------- */
#define XV_ABYT 13824                 /* 96*72*2 */
#define XV_BBYT 4608                  /* 32*72*2 */
#define XV_STGB (2*XV_ABYT + 2*XV_BBYT)   /* 36864 */
#define XV_SMEM (2*XV_STGB)               /* 73728 */

__device__ __forceinline__ void xv_load_stage(uint32_t sb, int buf, int k0,
                                              int b, int mt, int tid, int p)
{
    uint32_t base = sb + buf*XV_STGB;
    size_t vboff = (size_t)p*BB*32*DIM;
    #pragma unroll
    for (int i = 0; i < 11; i++) {
        int c = tid + 192*i;
        if (c >= 2048) break;
        if (c < 1536) {
            int mat = (c >= 768);
            int cc = c - (mat ? 768 : 0);
            int row = cc >> 3, col8 = (cc & 7)*8;
            int t = mt*96 + row;
            int ok = t < SEQ;
            const __nv_bfloat16* src = (mat ? g_xl : g_xh) +
                ((size_t)b*SEQ + (ok ? t : 0))*DIM + k0 + col8;
            cp16(base + mat*XV_ABYT + (uint32_t)(row*72 + col8)*2, src, ok ? 16 : 0);
        } else {
            int c2 = c - 1536;
            int mat = c2 >> 8;
            int cc = c2 & 255;
            int row = cc >> 3, col8 = (cc & 7)*8;
            const __nv_bfloat16* src = (mat ? g_vbl : g_vbh) + vboff +
                ((size_t)b*32 + row)*DIM + k0 + col8;
            cp16(base + 2*XV_ABYT + mat*XV_BBYT + (uint32_t)(row*72 + col8)*2, src, 16);
        }
    }
}

__global__ void __launch_bounds__(192, 1) xvmma_kernel(int p)
{
    extern __shared__ __align__(16) char xsm[];
    uint32_t sb = smem_u32(xsm);
    int tid = threadIdx.x, lane = tid & 31, w = tid >> 5;
    int mt = blockIdx.x, b = blockIdx.y;

    float acc[4][4];
    #pragma unroll
    for (int j = 0; j < 4; j++)
        #pragma unroll
        for (int q = 0; q < 4; q++) acc[j][q] = 0.f;

    uint32_t aRow = (uint32_t)(w*16 + (lane & 15));
    uint32_t aCol = (uint32_t)((lane >> 4)*8);
    uint32_t bRow = (uint32_t)((lane & 7) + ((lane >> 4) << 3));
    uint32_t bCol = (uint32_t)(((lane >> 3) & 1)*8);

    xv_load_stage(sb, 0, 0, b, mt, tid, p);
    CP_COMMIT();

    for (int s = 0; s < 16; s++) {
        if (s + 1 < 16) {
            xv_load_stage(sb, (s+1)&1, (s+1)*64, b, mt, tid, p);
            CP_COMMIT();
            CP_WAIT1();
        } else {
            CP_WAIT0();
        }
        __syncthreads();
        uint32_t stg = sb + (s&1)*XV_STGB;
        #pragma unroll
        for (int kt = 0; kt < 4; kt++) {
            uint32_t ah[4], al[4], bh2[8], bl2[8];
            uint32_t off = (aRow*72 + kt*16 + aCol)*2;
            ldsm_x4(ah[0], ah[1], ah[2], ah[3], stg + off);
            ldsm_x4(al[0], al[1], al[2], al[3], stg + XV_ABYT + off);
            #pragma unroll
            for (int g = 0; g < 2; g++) {
                uint32_t bo = ((bRow + g*16)*72 + kt*16 + bCol)*2;
                ldsm_x4(bh2[g*4+0], bh2[g*4+1], bh2[g*4+2], bh2[g*4+3],
                        stg + 2*XV_ABYT + bo);
                ldsm_x4(bl2[g*4+0], bl2[g*4+1], bl2[g*4+2], bl2[g*4+3],
                        stg + 2*XV_ABYT + XV_BBYT + bo);
            }
            #pragma unroll
            for (int j = 0; j < 4; j++) {
                mma_bf16(acc[j], ah, bh2[j*2], bh2[j*2+1]);
                mma_bf16(acc[j], ah, bl2[j*2], bl2[j*2+1]);
                mma_bf16(acc[j], al, bh2[j*2], bh2[j*2+1]);
            }
        }
        __syncthreads();
    }

    size_t xvoff = (size_t)p*BB*SEQP*32;
    int r0 = mt*96 + w*16 + (lane >> 2);
    int r1 = r0 + 8;
    #pragma unroll
    for (int j = 0; j < 4; j++) {
        int col = j*8 + (lane & 3)*2;
        if (r0 < SEQ) {
            float p0 = acc[j][0], p1 = acc[j][1];
            float h0 = __bfloat162float(__float2bfloat16(p0));
            float h1 = __bfloat162float(__float2bfloat16(p1));
            size_t o = xvoff + ((size_t)b*SEQP + r0)*32 + col;
            *(uint32_t*)(g_xvh + o) = pack_bf2(h0, h1);
            *(uint32_t*)(g_xvl + o) = pack_bf2(p0 - h0, p1 - h1);
        }
        if (r1 < SEQ) {
            float p0 = acc[j][2], p1 = acc[j][3];
            float h0 = __bfloat162float(__float2bfloat16(p0));
            float h1 = __bfloat162float(__float2bfloat16(p1));
            size_t o = xvoff + ((size_t)b*SEQP + r1)*32 + col;
            *(uint32_t*)(g_xvh + o) = pack_bf2(h0, h1);
            *(uint32_t*)(g_xvl + o) = pack_bf2(p0 - h0, p1 - h1);
        }
    }
}

/* ---------------- fused flash attention (KV chunk = 32, 9 chunks) --------- */
#define FA_QBYTES  13824
#define FA_MATB    4608             /* 32*72*2 */
#define FA_STGB    (4*FA_MATB)      /* 18432 */
#define FA_KVBASE  (2*FA_QBYTES)    /* 27648 */
#define FA_SMEM    (FA_KVBASE + 2*FA_STGB)   /* 64512 */
#define FA_NC      9                /* ceil(257/32) chunks */

__device__ __forceinline__ void fa_load_kv(uint32_t sb, int buf, int t0,
                                           int bh, int tid)
{
    uint32_t base = sb + FA_KVBASE + buf*FA_STGB;
    size_t goff = (size_t)bh*SEQP*HD + (size_t)t0*HD;
    const __nv_bfloat16* srcs[4] = {g_akh + goff, g_akl + goff, g_avh + goff, g_avl + goff};
    #pragma unroll
    for (int i = 0; i < 6; i++) {
        int c = tid + 192*i;
        if (c < 1024) {
            int mat = c >> 8, cc = c & 255;
            int row = cc >> 3, col8 = (cc & 7)*8;
            cp16(base + mat*FA_MATB + (uint32_t)(row*72 + col8)*2,
                 srcs[mat] + (size_t)row*HD + col8, 16);
        }
    }
}

__global__ void __launch_bounds__(192, 2) fa_kernel()
{
    extern __shared__ __align__(16) char fsm[];
    uint32_t sb = smem_u32(fsm);
    int tid = threadIdx.x, lane = tid & 31, w = tid >> 5;
    int mt = blockIdx.x, bh = blockIdx.y;
    int b = bh >> 4, hh = bh & 15;

    {
        const __nv_bfloat16* qs[2] = {g_aqh, g_aql};
        #pragma unroll
        for (int mat = 0; mat < 2; mat++) {
            const __nv_bfloat16* src = qs[mat] + ((size_t)bh*SEQP + mt*96)*HD;
            #pragma unroll
            for (int it = 0; it < 4; it++) {
                int c = tid + 192*it;
                int row = c >> 3, col8 = (c & 7)*8;
                uint4 v = *(const uint4*)(src + (size_t)row*HD + col8);
                *(uint4*)(fsm + mat*FA_QBYTES + (row*72 + col8)*2) = v;
            }
        }
    }
    fa_load_kv(sb, 0, 0, bh, tid);
    CP_COMMIT();
    __syncthreads();

    uint32_t qh[4][4], ql[4][4];
    {
        uint32_t aRow = (uint32_t)(w*16 + (lane & 15));
        uint32_t aCol = (uint32_t)((lane >> 4)*8);
        #pragma unroll
        for (int kt = 0; kt < 4; kt++) {
            uint32_t off = (aRow*72 + kt*16 + aCol)*2;
            ldsm_x4(qh[kt][0], qh[kt][1], qh[kt][2], qh[kt][3], sb + off);
            ldsm_x4(ql[kt][0], ql[kt][1], ql[kt][2], ql[kt][3], sb + FA_QBYTES + off);
        }
    }

    float o[8][4];
    #pragma unroll
    for (int j = 0; j < 8; j++)
        #pragma unroll
        for (int q = 0; q < 4; q++) o[j][q] = 0.f;
    float mr0 = -1e30f, mr1 = -1e30f, l0 = 0.f, l1 = 0.f;

    uint32_t kRow = (uint32_t)((lane & 7) + ((lane >> 4) << 3));
    uint32_t kCol = (uint32_t)(((lane >> 3) & 1)*8);
    uint32_t vRow = (uint32_t)(lane & 15);
    uint32_t vCol = (uint32_t)((lane >> 4) << 3);

    for (int c = 0; c < FA_NC; c++) {
        if (c + 1 < FA_NC) {
            fa_load_kv(sb, (c+1)&1, (c+1)*32, bh, tid);
            CP_COMMIT();
            CP_WAIT1();
        } else {
            CP_WAIT0();
        }
        __syncthreads();
        uint32_t stg = sb + FA_KVBASE + (c&1)*FA_STGB;

        float S[4][4];
        #pragma unroll
        for (int j = 0; j < 4; j++)
            #pragma unroll
            for (int q = 0; q < 4; q++) S[j][q] = 0.f;

        #pragma unroll
        for (int kt = 0; kt < 4; kt++) {
            #pragma unroll
            for (int g = 0; g < 2; g++) {
                uint32_t off = ((kRow + g*16)*72 + kt*16 + kCol)*2;
                uint32_t h0,h1,h2,h3, e0,e1,e2,e3;
                ldsm_x4(h0,h1,h2,h3, stg + 0*FA_MATB + off);
                ldsm_x4(e0,e1,e2,e3, stg + 1*FA_MATB + off);
                mma_bf16(S[2*g],   qh[kt], h0, h1);
                mma_bf16(S[2*g],   qh[kt], e0, e1);
                mma_bf16(S[2*g],   ql[kt], h0, h1);
                mma_bf16(S[2*g+1], qh[kt], h2, h3);
                mma_bf16(S[2*g+1], qh[kt], e2, e3);
                mma_bf16(S[2*g+1], ql[kt], h2, h3);
            }
        }

        if (c == FA_NC - 1) {
            #pragma unroll
            for (int j = 0; j < 4; j++) {
                int tb = (FA_NC-1)*32 + j*8 + (lane & 3)*2;
                if (tb     >= SEQ) { S[j][0] = -1e30f; S[j][2] = -1e30f; }
                if (tb + 1 >= SEQ) { S[j][1] = -1e30f; S[j][3] = -1e30f; }
            }
        }

        float mx0 = -1e30f, mx1 = -1e30f;
        #pragma unroll
        for (int j = 0; j < 4; j++) {
            mx0 = fmaxf(mx0, fmaxf(S[j][0], S[j][1]));
            mx1 = fmaxf(mx1, fmaxf(S[j][2], S[j][3]));
        }
        mx0 = fmaxf(mx0, __shfl_xor_sync(0xffffffffu, mx0, 1));
        mx0 = fmaxf(mx0, __shfl_xor_sync(0xffffffffu, mx0, 2));
        mx1 = fmaxf(mx1, __shfl_xor_sync(0xffffffffu, mx1, 1));
        mx1 = fmaxf(mx1, __shfl_xor_sync(0xffffffffu, mx1, 2));
        float mn0 = fmaxf(mr0, mx0), mn1 = fmaxf(mr1, mx1);
        float sc0 = expf(mr0 - mn0), sc1 = expf(mr1 - mn1);
        mr0 = mn0; mr1 = mn1;

        uint32_t ph[2][4], pl[2][4];
        float rs0 = 0.f, rs1 = 0.f;
        #pragma unroll
        for (int j = 0; j < 4; j++) {
            float p0 = expf(S[j][0] - mn0), p1 = expf(S[j][1] - mn0);
            float p2 = expf(S[j][2] - mn1), p3 = expf(S[j][3] - mn1);
            rs0 += p0 + p1; rs1 += p2 + p3;
            float h0 = __bfloat162float(__float2bfloat16(p0));
            float h1 = __bfloat162float(__float2bfloat16(p1));
            float h2 = __bfloat162float(__float2bfloat16(p2));
            float h3 = __bfloat162float(__float2bfloat16(p3));
            int kt2 = j >> 1, hb = (j & 1)*2;
            ph[kt2][hb]   = pack_bf2(h0, h1);
            ph[kt2][hb+1] = pack_bf2(h2, h3);
            pl[kt2][hb]   = pack_bf2(p0 - h0, p1 - h1);
            pl[kt2][hb+1] = pack_bf2(p2 - h2, p3 - h3);
        }
        rs0 += __shfl_xor_sync(0xffffffffu, rs0, 1);
        rs0 += __shfl_xor_sync(0xffffffffu, rs0, 2);
        rs1 += __shfl_xor_sync(0xffffffffu, rs1, 1);
        rs1 += __shfl_xor_sync(0xffffffffu, rs1, 2);
        l0 = l0*sc0 + rs0;
        l1 = l1*sc1 + rs1;

        #pragma unroll
        for (int j = 0; j < 8; j++) {
            o[j][0] *= sc0; o[j][1] *= sc0;
            o[j][2] *= sc1; o[j][3] *= sc1;
        }

        #pragma unroll
        for (int kt2 = 0; kt2 < 2; kt2++) {
            #pragma unroll
            for (int g = 0; g < 4; g++) {
                uint32_t off = ((kt2*16 + vRow)*72 + g*16 + vCol)*2;
                uint32_t h0,h1,h2,h3, e0,e1,e2,e3;
                ldsm_x4_t(h0,h1,h2,h3, stg + 2*FA_MATB + off);
                ldsm_x4_t(e0,e1,e2,e3, stg + 3*FA_MATB + off);
                mma_bf16(o[2*g],   ph[kt2], h0, h1);
                mma_bf16(o[2*g],   ph[kt2], e0, e1);
                mma_bf16(o[2*g],   pl[kt2], h0, h1);
                mma_bf16(o[2*g+1], ph[kt2], h2, h3);
                mma_bf16(o[2*g+1], ph[kt2], e2, e3);
                mma_bf16(o[2*g+1], pl[kt2], h2, h3);
            }
        }
        __syncthreads();
    }

    float inv0 = 1.f/l0, inv1 = 1.f/l1;
    int r0 = mt*96 + w*16 + (lane >> 2);
    int r1 = r0 + 8;
    #pragma unroll
    for (int j = 0; j < 8; j++) {
        int d = hh*HD + j*8 + (lane & 3)*2;
        if (r0 < SEQ)
            *(float2*)(g_ctx + (size_t)(b*SEQ + r0)*DIM + d) =
                make_float2(o[j][0]*inv0, o[j][1]*inv0);
        if (r1 < SEQ)
            *(float2*)(g_ctx + (size_t)(b*SEQ + r1)*DIM + d) =
                make_float2(o[j][2]*inv1, o[j][3]*inv1);
    }
}

/* ---------------- launch ---------------- */
extern "C" void kernel_launch(void* const* d_in, const int* in_sizes, int n_in,
                              void* d_out, int out_size)
{
    const float* x   = (const float*)d_in[0];
    const float* gw1 = (const float*)d_in[1];
    const float* gb1 = (const float*)d_in[2];
    const float* gw2 = (const float*)d_in[3];
    const float* gb2 = (const float*)d_in[4];
    const float* Wm[4] = {(const float*)d_in[5],  (const float*)d_in[10],
                          (const float*)d_in[15], (const float*)d_in[20]};
    const float* Uu[4] = {(const float*)d_in[6],  (const float*)d_in[11],
                          (const float*)d_in[16], (const float*)d_in[21]};
    const float* Ss[4] = {(const float*)d_in[7],  (const float*)d_in[12],
                          (const float*)d_in[17], (const float*)d_in[22]};
    const float* Vv[4] = {(const float*)d_in[8],  (const float*)d_in[13],
                          (const float*)d_in[18], (const float*)d_in[23]};
    const float* bbv[4] = {(const float*)d_in[9],  (const float*)d_in[14],
                           (const float*)d_in[19], (const float*)d_in[24]};
    float* out = (float*)d_out;

    cudaFuncSetAttribute(mm_kernel, cudaFuncAttributeMaxDynamicSharedMemorySize, MM_SMEM);
    cudaFuncSetAttribute(fa_kernel, cudaFuncAttributeMaxDynamicSharedMemorySize, FA_SMEM);
    cudaFuncSetAttribute(xvmma_kernel, cudaFuncAttributeMaxDynamicSharedMemorySize, XV_SMEM);

    gating_kernel<<<BB, 256>>>(x, gw1, gb1, gw2, gb2);

    int nx4 = BSQ*DIM/4;
    int nw4 = DIM*DIM/4;
    conv_kernel<<<(nx4 + 255)/256, 256>>>(x, 0, nx4);
    for (int p = 0; p < 4; p++)
        conv_kernel<<<(nw4 + 255)/256, 256>>>(Wm[p], p + 1, nw4);

    for (int p = 0; p < 4; p++) {
        vconv_kernel<<<dim3(BB, 32), 256>>>(Vv[p], Ss[p], p);
        uconv_kernel<<<dim3(BB, 4), 256>>>(Uu[p], p);
    }
    for (int p = 0; p < 3; p++)
        xvmma_kernel<<<dim3(3, BB), 192, XV_SMEM>>>(p);

    dim3 gmm(8, 65, 3);
    mm_kernel<<<gmm, 256, MM_SMEM>>>(-1, bbv[0], bbv[1], bbv[2], nullptr);

    fa_kernel<<<dim3(3, BB*NH), 192, FA_SMEM>>>();

    conv_kernel<<<(nx4 + 255)/256, 256>>>(nullptr, 5, nx4);
    xvmma_kernel<<<dim3(3, BB), 192, XV_SMEM>>>(3);
    mm_kernel<<<dim3(8, 65, 1), 256, MM_SMEM>>>(3, bbv[3], bbv[3], bbv[3], out);
}